// round 1
// baseline (speedup 1.0000x reference)
#include <cuda_runtime.h>
#include <math.h>

// ---- fixed problem shape (HBlock_18597208391748) ----
#define BB   2
#define TT   4160
#define DD   1024
#define HH   16
#define KVH  4
#define HD   64
#define CS   2048
#define NU   (TT - CS)        // 2112
#define KVD  (KVH * HD)       // 256
#define DFF  (4 * DD)         // 4096
#define MQ   (BB * NU)        // 4224
#define MX   (BB * TT)        // 8320

// ---- scratch (device globals; no allocation allowed) ----
__device__ float g_xn  [(size_t)MX * DD];   // rms_norm(x), later rms_norm(x_new)
__device__ float g_q   [(size_t)MQ * DD];
__device__ float g_k   [(size_t)MX * KVD];
__device__ float g_v   [(size_t)MX * KVD];
__device__ float g_attn[(size_t)MQ * DD];   // attention out, later reused as final x_new
__device__ float g_xnew[(size_t)MQ * DD];
__device__ float g_h   [(size_t)MQ * DFF];

// ============================================================
// RMSNorm: one block per row of 1024 floats
// ============================================================
__global__ __launch_bounds__(256) void rmsnorm_k(const float* __restrict__ x,
                                                 float* __restrict__ y)
{
    const int row = blockIdx.x;
    const float4* xr = (const float4*)x + (size_t)row * (DD / 4);
    float4 v = xr[threadIdx.x];
    float ss = v.x * v.x + v.y * v.y + v.z * v.z + v.w * v.w;
    #pragma unroll
    for (int o = 16; o; o >>= 1) ss += __shfl_xor_sync(0xffffffffu, ss, o);
    __shared__ float red[8];
    if ((threadIdx.x & 31) == 0) red[threadIdx.x >> 5] = ss;
    __syncthreads();
    float tot = red[0] + red[1] + red[2] + red[3] + red[4] + red[5] + red[6] + red[7];
    float s = rsqrtf(tot * (1.0f / DD) + 1e-6f);
    v.x *= s; v.y *= s; v.z *= s; v.w *= s;
    float4* yr = (float4*)y + (size_t)row * (DD / 4);
    yr[threadIdx.x] = v;
}

// ============================================================
// L2-normalize contiguous 64-float vectors (optionally * sc)
// one warp per vector, 8 vectors per block
// ============================================================
__global__ __launch_bounds__(256) void l2norm_k(float* __restrict__ v, int nvec, float sc)
{
    int vec = blockIdx.x * 8 + (threadIdx.x >> 5);
    if (vec >= nvec) return;
    int lane = threadIdx.x & 31;
    float2* p = (float2*)(v + (size_t)vec * 64) + lane;
    float2 d = *p;
    float ss = d.x * d.x + d.y * d.y;
    #pragma unroll
    for (int o = 16; o; o >>= 1) ss += __shfl_xor_sync(0xffffffffu, ss, o);
    float n = fmaxf(sqrtf(ss), 1e-12f);
    float s = sc / n;
    d.x *= s; d.y *= s;
    *p = d;
}

// ============================================================
// SGEMM: C[M,N] = A[M,K] * W[N,K]^T, 128x128x8 tile, 8x8 micro
// A rows can be remapped (segment gather): arow = (r/asl)*ast + aso + r%asl
// epilogues: 0 none; 1 softcap+resid(R remapped); 2 relu^2; 3 +R (identity)
// ============================================================
__global__ __launch_bounds__(256) void sgemm_k(
    const float* __restrict__ A, const float* __restrict__ W,
    float* __restrict__ C, const float* __restrict__ R,
    int N, int K,
    int asl, int ast, int aso,
    int rsl, int rst, int rso,
    int epi)
{
    __shared__ float As[8][132];
    __shared__ float Ws[8][132];
    const int tid = threadIdx.x;
    const int bm = blockIdx.x * 128;
    const int bn = blockIdx.y * 128;
    const int lr = tid >> 1;            // 0..127
    const int lk = (tid & 1) << 2;      // 0 or 4
    const int row = bm + lr;
    const size_t arow = (size_t)(row / asl) * ast + aso + (row % asl);
    const float* Ap = A + arow * K + lk;
    const float* Wp = W + (size_t)(bn + lr) * K + lk;
    const int ty = tid >> 4, tx = tid & 15;

    float acc[8][8];
    #pragma unroll
    for (int i = 0; i < 8; i++)
        #pragma unroll
        for (int j = 0; j < 8; j++) acc[i][j] = 0.f;

    float4 a4 = *(const float4*)Ap;
    float4 w4 = *(const float4*)Wp;

    for (int kt = 0; kt < K; kt += 8) {
        __syncthreads();
        As[lk + 0][lr] = a4.x; As[lk + 1][lr] = a4.y;
        As[lk + 2][lr] = a4.z; As[lk + 3][lr] = a4.w;
        Ws[lk + 0][lr] = w4.x; Ws[lk + 1][lr] = w4.y;
        Ws[lk + 2][lr] = w4.z; Ws[lk + 3][lr] = w4.w;
        __syncthreads();
        if (kt + 8 < K) {
            a4 = *(const float4*)(Ap + kt + 8);
            w4 = *(const float4*)(Wp + kt + 8);
        }
        #pragma unroll
        for (int kk = 0; kk < 8; kk++) {
            float af[8], wf[8];
            *(float4*)(af)     = *(const float4*)(&As[kk][ty * 8]);
            *(float4*)(af + 4) = *(const float4*)(&As[kk][ty * 8 + 4]);
            *(float4*)(wf)     = *(const float4*)(&Ws[kk][tx * 8]);
            *(float4*)(wf + 4) = *(const float4*)(&Ws[kk][tx * 8 + 4]);
            #pragma unroll
            for (int i = 0; i < 8; i++)
                #pragma unroll
                for (int j = 0; j < 8; j++)
                    acc[i][j] = fmaf(af[i], wf[j], acc[i][j]);
        }
    }

    const int r0 = bm + ty * 8, c0 = bn + tx * 8;
    #pragma unroll
    for (int i = 0; i < 8; i++) {
        const int ri = r0 + i;
        float out[8];
        if (epi == 0) {
            #pragma unroll
            for (int j = 0; j < 8; j++) out[j] = acc[i][j];
        } else if (epi == 1) {
            const size_t rr = (size_t)(ri / rsl) * rst + rso + (ri % rsl);
            const float* rp = R + rr * N + c0;
            #pragma unroll
            for (int j = 0; j < 8; j++)
                out[j] = rp[j] + 15.0f * tanhf(acc[i][j] * (1.0f / 15.0f));
        } else if (epi == 2) {
            #pragma unroll
            for (int j = 0; j < 8; j++) {
                float t = fmaxf(acc[i][j], 0.f);
                out[j] = t * t;
            }
        } else {
            const float* rp = R + (size_t)ri * N + c0;
            #pragma unroll
            for (int j = 0; j < 8; j++) out[j] = rp[j] + acc[i][j];
        }
        *(float4*)(C + (size_t)ri * N + c0)     = make_float4(out[0], out[1], out[2], out[3]);
        *(float4*)(C + (size_t)ri * N + c0 + 4) = make_float4(out[4], out[5], out[6], out[7]);
    }
}

// ============================================================
// Flash attention (causal, GQA rep=4), 64q x 64k tiles, HD=64.
// grid: (NU/64, B*H); block 256 threads; 4x4 micro for S and O.
// q is pre-scaled by 1/sqrt(HD) (folded into l2norm).
// ============================================================
__global__ __launch_bounds__(256) void attn_k(
    const float* __restrict__ q, const float* __restrict__ k,
    const float* __restrict__ v, float* __restrict__ o)
{
    extern __shared__ float sm[];
    float* q_s = sm;                 // [64][68] (r, d) row-major
    float* k_s = sm + 64 * 68;       // [64][68] (d, kk) d-major
    float* v_s = k_s + 64 * 68;      // [64][68] (kk, c)
    float* p_s = v_s + 64 * 68;      // [64][68] (kk, r)

    const int tid = threadIdx.x;
    const int ty = tid >> 4, tx = tid & 15;
    const int qt = blockIdx.x;
    const int bh = blockIdx.y;
    const int b = bh >> 4, h = bh & 15;
    const int kvh = h >> 2;
    const int q0 = qt * 64;

    // load Q tile (row-major)
    for (int i = tid; i < 1024; i += 256) {
        int r = i >> 4, dq = (i & 15) << 2;
        float4 t4 = *(const float4*)(q + ((size_t)(b * NU + q0 + r)) * DD + h * HD + dq);
        *(float4*)(q_s + r * 68 + dq) = t4;
    }

    float acc[4][4];
    float m_i[4], l_i[4];
    #pragma unroll
    for (int i = 0; i < 4; i++) {
        m_i[i] = -INFINITY; l_i[i] = 0.f;
        #pragma unroll
        for (int j = 0; j < 4; j++) acc[i][j] = 0.f;
    }

    const int n_kt = (CS / 64) + qt + 1;
    for (int kt = 0; kt < n_kt; kt++) {
        __syncthreads();   // protect k_s/v_s/p_s from previous iteration readers
        const int k0 = kt * 64;
        for (int i = tid; i < 1024; i += 256) {
            int r = i >> 4, dq = (i & 15) << 2;
            size_t base = ((size_t)(b * TT + k0 + r)) * KVD + kvh * HD + dq;
            float4 k4 = *(const float4*)(k + base);
            k_s[(dq + 0) * 68 + r] = k4.x;
            k_s[(dq + 1) * 68 + r] = k4.y;
            k_s[(dq + 2) * 68 + r] = k4.z;
            k_s[(dq + 3) * 68 + r] = k4.w;
            float4 v4 = *(const float4*)(v + base);
            *(float4*)(v_s + r * 68 + dq) = v4;
        }
        __syncthreads();

        // S = Q * K^T  (4x4 micro)
        float s[4][4];
        #pragma unroll
        for (int i = 0; i < 4; i++)
            #pragma unroll
            for (int j = 0; j < 4; j++) s[i][j] = 0.f;
        #pragma unroll 8
        for (int d = 0; d < 64; d++) {
            float qv[4];
            #pragma unroll
            for (int i = 0; i < 4; i++) qv[i] = q_s[(4 * ty + i) * 68 + d];
            float4 kv = *(const float4*)(k_s + d * 68 + 4 * tx);
            #pragma unroll
            for (int i = 0; i < 4; i++) {
                s[i][0] = fmaf(qv[i], kv.x, s[i][0]);
                s[i][1] = fmaf(qv[i], kv.y, s[i][1]);
                s[i][2] = fmaf(qv[i], kv.z, s[i][2]);
                s[i][3] = fmaf(qv[i], kv.w, s[i][3]);
            }
        }

        // causal mask on the (single, aligned) diagonal tile
        if (kt == n_kt - 1) {
            #pragma unroll
            for (int i = 0; i < 4; i++)
                #pragma unroll
                for (int j = 0; j < 4; j++)
                    if (4 * tx + j > 4 * ty + i) s[i][j] = -INFINITY;
        }

        // online softmax (row reductions over 16 tx lanes)
        #pragma unroll
        for (int i = 0; i < 4; i++) {
            float mt = fmaxf(fmaxf(s[i][0], s[i][1]), fmaxf(s[i][2], s[i][3]));
            #pragma unroll
            for (int off = 8; off; off >>= 1)
                mt = fmaxf(mt, __shfl_xor_sync(0xffffffffu, mt, off));
            float m_new = fmaxf(m_i[i], mt);
            float corr = __expf(m_i[i] - m_new);
            float rs = 0.f;
            #pragma unroll
            for (int j = 0; j < 4; j++) {
                float p = __expf(s[i][j] - m_new);
                rs += p;
                p_s[(4 * tx + j) * 68 + 4 * ty + i] = p;
            }
            #pragma unroll
            for (int off = 8; off; off >>= 1)
                rs += __shfl_xor_sync(0xffffffffu, rs, off);
            l_i[i] = l_i[i] * corr + rs;
            m_i[i] = m_new;
            #pragma unroll
            for (int j = 0; j < 4; j++) acc[i][j] *= corr;
        }
        __syncthreads();

        // O += P^T-stored * V
        #pragma unroll 8
        for (int kk = 0; kk < 64; kk++) {
            float4 p4 = *(const float4*)(p_s + kk * 68 + 4 * ty);
            float4 v4 = *(const float4*)(v_s + kk * 68 + 4 * tx);
            acc[0][0] = fmaf(p4.x, v4.x, acc[0][0]);
            acc[0][1] = fmaf(p4.x, v4.y, acc[0][1]);
            acc[0][2] = fmaf(p4.x, v4.z, acc[0][2]);
            acc[0][3] = fmaf(p4.x, v4.w, acc[0][3]);
            acc[1][0] = fmaf(p4.y, v4.x, acc[1][0]);
            acc[1][1] = fmaf(p4.y, v4.y, acc[1][1]);
            acc[1][2] = fmaf(p4.y, v4.z, acc[1][2]);
            acc[1][3] = fmaf(p4.y, v4.w, acc[1][3]);
            acc[2][0] = fmaf(p4.z, v4.x, acc[2][0]);
            acc[2][1] = fmaf(p4.z, v4.y, acc[2][1]);
            acc[2][2] = fmaf(p4.z, v4.z, acc[2][2]);
            acc[2][3] = fmaf(p4.z, v4.w, acc[2][3]);
            acc[3][0] = fmaf(p4.w, v4.x, acc[3][0]);
            acc[3][1] = fmaf(p4.w, v4.y, acc[3][1]);
            acc[3][2] = fmaf(p4.w, v4.z, acc[3][2]);
            acc[3][3] = fmaf(p4.w, v4.w, acc[3][3]);
        }
    }

    // write O / l
    #pragma unroll
    for (int i = 0; i < 4; i++) {
        float inv = 1.0f / l_i[i];
        float4 r4 = make_float4(acc[i][0] * inv, acc[i][1] * inv,
                                acc[i][2] * inv, acc[i][3] * inv);
        *(float4*)(o + ((size_t)(b * NU + q0 + 4 * ty + i)) * DD + h * HD + 4 * tx) = r4;
    }
}

// ============================================================
// final: out[b,t,:] = t<CS ? x : fin
// ============================================================
__global__ __launch_bounds__(256) void finalize_k(const float* __restrict__ x,
                                                  const float* __restrict__ fin,
                                                  float* __restrict__ out)
{
    size_t i = (size_t)blockIdx.x * 256 + threadIdx.x;  // float4 index
    int rowd = (int)(i >> 8);     // b*T + t
    int c4 = (int)(i & 255);
    int t = rowd % TT;
    float4 val;
    if (t < CS) {
        val = ((const float4*)x)[i];
    } else {
        int b = rowd / TT;
        val = ((const float4*)fin)[(size_t)(b * NU + (t - CS)) * 256 + c4];
    }
    ((float4*)out)[i] = val;
}

// ============================================================
extern "C" void kernel_launch(void* const* d_in, const int* in_sizes, int n_in,
                              void* d_out, int out_size)
{
    const float* x     = (const float*)d_in[0];
    const float* Wq    = (const float*)d_in[1];
    const float* Wk    = (const float*)d_in[2];
    const float* Wv    = (const float*)d_in[3];
    const float* Wo    = (const float*)d_in[4];
    const float* Wfc   = (const float*)d_in[5];
    const float* Wproj = (const float*)d_in[6];
    float* out = (float*)d_out;

    float *xn, *qb, *kb, *vb, *ab, *xnb, *hb;
    cudaGetSymbolAddress((void**)&xn,  g_xn);
    cudaGetSymbolAddress((void**)&qb,  g_q);
    cudaGetSymbolAddress((void**)&kb,  g_k);
    cudaGetSymbolAddress((void**)&vb,  g_v);
    cudaGetSymbolAddress((void**)&ab,  g_attn);
    cudaGetSymbolAddress((void**)&xnb, g_xnew);
    cudaGetSymbolAddress((void**)&hb,  g_h);

    // 1. x_norm = rms_norm(x)
    rmsnorm_k<<<MX, 256>>>(x, xn);

    // 2. K, V, Q projections
    sgemm_k<<<dim3(MX / 128, KVD / 128), 256>>>(xn, Wk, kb, nullptr, KVD, DD,
                                                MX, MX, 0, 1, 1, 0, 0);
    sgemm_k<<<dim3(MX / 128, KVD / 128), 256>>>(xn, Wv, vb, nullptr, KVD, DD,
                                                MX, MX, 0, 1, 1, 0, 0);
    sgemm_k<<<dim3(MQ / 128, DD / 128), 256>>>(xn, Wq, qb, nullptr, DD, DD,
                                               NU, TT, CS, 1, 1, 0, 0);

    // 3. L2 normalize (q also picks up the 1/sqrt(HD) score scale)
    l2norm_k<<<(MQ * HH) / 8, 256>>>(qb, MQ * HH, 0.125f);
    l2norm_k<<<(MX * KVH) / 8, 256>>>(kb, MX * KVH, 1.0f);

    // 4. flash attention
    cudaFuncSetAttribute(attn_k, cudaFuncAttributeMaxDynamicSharedMemorySize,
                         4 * 64 * 68 * (int)sizeof(float));
    attn_k<<<dim3(NU / 64, BB * HH), 256, 4 * 64 * 68 * sizeof(float)>>>(qb, kb, vb, ab);

    // 5. x_new = x_upd + softcap(attn @ Wo^T)
    sgemm_k<<<dim3(MQ / 128, DD / 128), 256>>>(ab, Wo, xnb, x, DD, DD,
                                               MQ, MQ, 0, NU, TT, CS, 1);

    // 6. FFN: h = relu(rms_norm(x_new) @ Wfc^T)^2 ; final = x_new + h @ Wproj^T
    rmsnorm_k<<<MQ, 256>>>(xnb, xn);
    sgemm_k<<<dim3(MQ / 128, DFF / 128), 256>>>(xn, Wfc, hb, nullptr, DFF, DD,
                                                MQ, MQ, 0, 1, 1, 0, 2);
    sgemm_k<<<dim3(MQ / 128, DD / 128), 256>>>(hb, Wproj, ab, xnb, DD, DFF,
                                               MQ, MQ, 0, MQ, MQ, 0, 3);

    // 7. scatter output
    finalize_k<<<MX, 256>>>(x, ab, out);
}

// round 4
// speedup vs baseline: 1.8478x; 1.8478x over previous
#include <cuda_runtime.h>
#include <cuda_bf16.h>
#include <stdint.h>
#include <math.h>

// ---- fixed problem shape (HBlock_18597208391748) ----
#define BB   2
#define TT   4160
#define DD   1024
#define HH   16
#define KVH  4
#define HD   64
#define CS   2048
#define NU   (TT - CS)        // 2112
#define KVD  (KVH * HD)       // 256
#define DFF  (4 * DD)         // 4096
#define MQ   (BB * NU)        // 4224
#define MX   (BB * TT)        // 8320

// tcgen05 only exists in arch-specific ('a') compilation passes.
#if defined(__CUDA_ARCH_FEAT_SM103_ALL) || defined(__CUDA_ARCH_FEAT_SM100_ALL)
#define USE_TCGEN05 1
#else
#define USE_TCGEN05 0
#endif

// ---- scratch (device globals; no allocation allowed) ----
__device__ __nv_bfloat16 g_xnh[(size_t)MX * DD], g_xnl[(size_t)MX * DD];
__device__ float g_q [(size_t)MQ * DD];
__device__ float g_k [(size_t)MX * KVD];
__device__ float g_v [(size_t)MX * KVD];
__device__ __nv_bfloat16 g_ah[(size_t)MQ * DD], g_al[(size_t)MQ * DD];
__device__ float g_xnew[(size_t)MQ * DD];
__device__ __nv_bfloat16 g_x2h[(size_t)MQ * DD], g_x2l[(size_t)MQ * DD];
__device__ __nv_bfloat16 g_hh[(size_t)MQ * DFF], g_hl[(size_t)MQ * DFF];
__device__ float g_fin[(size_t)MQ * DD];
// weight hi/lo
__device__ __nv_bfloat16 g_wqh[DD * DD],  g_wql[DD * DD];
__device__ __nv_bfloat16 g_wkh[KVD * DD], g_wkl[KVD * DD];
__device__ __nv_bfloat16 g_wvh[KVD * DD], g_wvl[KVD * DD];
__device__ __nv_bfloat16 g_woh[DD * DD],  g_wol[DD * DD];
__device__ __nv_bfloat16 g_wfh[DFF * DD], g_wfl[DFF * DD];
__device__ __nv_bfloat16 g_wph[DD * DFF], g_wpl[DD * DFF];

// ============================================================
// PTX helpers
// ============================================================
__device__ __forceinline__ uint32_t smem_u32(const void* p) {
    uint32_t a;
    asm("{ .reg .u64 t; cvta.to.shared.u64 t, %1; cvt.u32.u64 %0, t; }" : "=r"(a) : "l"(p));
    return a;
}
// cp.async (sm_80+, legal on plain compute_103)
#define CP_ASYNC16(dst, src) \
    asm volatile("cp.async.cg.shared.global [%0], [%1], 16;" :: "r"(dst), "l"(src))
#define CP_COMMIT() asm volatile("cp.async.commit_group;" ::: "memory")
#define CP_WAIT(n)  asm volatile("cp.async.wait_group %0;" :: "n"(n) : "memory")

// ldmatrix / mma (sm_75/80+, legal on plain compute_103)
__device__ __forceinline__ void ldsm4(uint32_t& r0, uint32_t& r1, uint32_t& r2, uint32_t& r3,
                                      uint32_t a) {
    asm volatile("ldmatrix.sync.aligned.m8n8.x4.shared.b16 {%0,%1,%2,%3}, [%4];"
                 : "=r"(r0), "=r"(r1), "=r"(r2), "=r"(r3) : "r"(a));
}
__device__ __forceinline__ void mma16816(float* d, const uint32_t* a, const uint32_t* b) {
    asm volatile("mma.sync.aligned.m16n8k16.row.col.f32.bf16.bf16.f32 "
                 "{%0,%1,%2,%3}, {%4,%5,%6,%7}, {%8,%9}, {%0,%1,%2,%3};"
                 : "+f"(d[0]), "+f"(d[1]), "+f"(d[2]), "+f"(d[3])
                 : "r"(a[0]), "r"(a[1]), "r"(a[2]), "r"(a[3]), "r"(b[0]), "r"(b[1]));
}

#if USE_TCGEN05
#define MBARRIER_INIT(addr, cnt) \
    asm volatile("mbarrier.init.shared.b64 [%0], %1;" :: "r"((uint32_t)(addr)), "r"((uint32_t)(cnt)) : "memory")
#define MBARRIER_WAIT_PARITY(addr, par) do {                                              \
    uint32_t _m = (uint32_t)(addr); uint32_t _p = (uint32_t)(par); uint32_t _d;           \
    asm volatile("{\n\t.reg .pred p;\n\t"                                                 \
        "mbarrier.try_wait.parity.acquire.cta.shared::cta.b64 p, [%1], %2;\n\t"           \
        "selp.b32 %0, 1, 0, p;\n\t}" : "=r"(_d) : "r"(_m), "r"(_p) : "memory");           \
    if (!_d) {                                                                            \
        asm volatile("{\n\t.reg .pred P1;\n\t"                                            \
            "WL_%=:\n\t"                                                                  \
            "mbarrier.try_wait.parity.acquire.cta.shared::cta.b64 P1, [%0], %1, 0x989680;\n\t" \
            "@P1 bra.uni WD_%=;\n\t bra.uni WL_%=;\n\t WD_%=:\n\t}"                       \
            :: "r"(_m), "r"(_p) : "memory");                                              \
    }                                                                                     \
} while (0)
#define TCGEN05_ALLOC(saddr, ncols) \
    asm volatile("tcgen05.alloc.cta_group::1.sync.aligned.shared::cta.b32 [%0], %1;" \
                 :: "r"((uint32_t)(saddr)), "r"((uint32_t)(ncols)) : "memory")
#define TCGEN05_DEALLOC(tmem, ncols) \
    asm volatile("tcgen05.dealloc.cta_group::1.sync.aligned.b32 %0, %1;" :: "r"(tmem), "r"((uint32_t)(ncols)))
#define TCGEN05_COMMIT(mbar) \
    asm volatile("tcgen05.commit.cta_group::1.mbarrier::arrive::one.shared::cluster.b64 [%0];" \
                 :: "r"((uint32_t)(mbar)) : "memory")
#define TCGEN05_WAIT_LD() asm volatile("tcgen05.wait::ld.sync.aligned;" ::: "memory")
#define TCGEN05_FENCE_AFTER()  asm volatile("tcgen05.fence::after_thread_sync;" ::: "memory")
#define TCGEN05_FENCE_BEFORE() asm volatile("tcgen05.fence::before_thread_sync;" ::: "memory")
#define FENCE_PROXY_ASYNC() asm volatile("fence.proxy.async.shared::cta;" ::: "memory")
#define TCGEN05_LD_X32(r, addr)                                                           \
    asm volatile("tcgen05.ld.sync.aligned.32x32b.x32.b32 "                                \
        "{%0, %1, %2, %3, %4, %5, %6, %7, %8, %9, %10, %11, %12, %13, %14, %15, "         \
        " %16, %17, %18, %19, %20, %21, %22, %23, %24, %25, %26, %27, %28, %29, %30, %31}, [%32];" \
        : "=r"((r)[0]),  "=r"((r)[1]),  "=r"((r)[2]),  "=r"((r)[3]),                      \
          "=r"((r)[4]),  "=r"((r)[5]),  "=r"((r)[6]),  "=r"((r)[7]),                      \
          "=r"((r)[8]),  "=r"((r)[9]),  "=r"((r)[10]), "=r"((r)[11]),                     \
          "=r"((r)[12]), "=r"((r)[13]), "=r"((r)[14]), "=r"((r)[15]),                     \
          "=r"((r)[16]), "=r"((r)[17]), "=r"((r)[18]), "=r"((r)[19]),                     \
          "=r"((r)[20]), "=r"((r)[21]), "=r"((r)[22]), "=r"((r)[23]),                     \
          "=r"((r)[24]), "=r"((r)[25]), "=r"((r)[26]), "=r"((r)[27]),                     \
          "=r"((r)[28]), "=r"((r)[29]), "=r"((r)[30]), "=r"((r)[31])                      \
        : "r"(addr))

__device__ __forceinline__ uint64_t make_desc_sw128(uint32_t addr) {
    return (2ull << 61) | (1ull << 46) | (64ull << 32) | (1ull << 16)
         | ((uint64_t)(addr >> 4) & 0x3FFF);
}
__device__ __forceinline__ void mma_bf16_ss(uint32_t d, uint64_t a, uint64_t b,
                                            uint32_t idesc, uint32_t en) {
    asm volatile(
        "{\n\t.reg .pred p;\n\t"
        "setp.ne.u32 p, %5, 0;\n\t"
        "tcgen05.mma.cta_group::1.kind::f16 [%0], %1, %2, %3, {%4, %4, %4, %4}, p;\n\t}"
        :: "r"(d), "l"(a), "l"(b), "r"(idesc), "r"(0u), "r"(en) : "memory");
}
#define IDESC 0x8200490u
#endif // USE_TCGEN05

// ============================================================
// weight fp32 -> bf16 hi/lo split
// ============================================================
__global__ __launch_bounds__(256) void cvt_hl_k(const float* __restrict__ x,
                                                __nv_bfloat16* __restrict__ hi,
                                                __nv_bfloat16* __restrict__ lo, int n4)
{
    int i = blockIdx.x * 256 + threadIdx.x;
    if (i >= n4) return;
    float4 v = ((const float4*)x)[i];
    float vv[4] = {v.x, v.y, v.z, v.w};
    __nv_bfloat162 h2[2], l2[2];
    #pragma unroll
    for (int j = 0; j < 4; j++) {
        __nv_bfloat16 h = __float2bfloat16_rn(vv[j]);
        __nv_bfloat16 l = __float2bfloat16_rn(vv[j] - __bfloat162float(h));
        if (j & 1) { h2[j >> 1].y = h; l2[j >> 1].y = l; }
        else       { h2[j >> 1].x = h; l2[j >> 1].x = l; }
    }
    ((__nv_bfloat162*)hi)[2 * i]     = h2[0];
    ((__nv_bfloat162*)hi)[2 * i + 1] = h2[1];
    ((__nv_bfloat162*)lo)[2 * i]     = l2[0];
    ((__nv_bfloat162*)lo)[2 * i + 1] = l2[1];
}

// ============================================================
// RMSNorm -> bf16 hi/lo
// ============================================================
__global__ __launch_bounds__(256) void rmsnorm_hl_k(const float* __restrict__ x,
                                                    __nv_bfloat16* __restrict__ yh,
                                                    __nv_bfloat16* __restrict__ yl)
{
    const int row = blockIdx.x;
    const float4* xr = (const float4*)x + (size_t)row * (DD / 4);
    float4 v = xr[threadIdx.x];
    float ss = v.x * v.x + v.y * v.y + v.z * v.z + v.w * v.w;
    #pragma unroll
    for (int o = 16; o; o >>= 1) ss += __shfl_xor_sync(0xffffffffu, ss, o);
    __shared__ float red[8];
    if ((threadIdx.x & 31) == 0) red[threadIdx.x >> 5] = ss;
    __syncthreads();
    float tot = red[0] + red[1] + red[2] + red[3] + red[4] + red[5] + red[6] + red[7];
    float s = rsqrtf(tot * (1.0f / DD) + 1e-6f);
    float vv[4] = {v.x * s, v.y * s, v.z * s, v.w * s};
    __nv_bfloat162 h2[2], l2[2];
    #pragma unroll
    for (int j = 0; j < 4; j++) {
        __nv_bfloat16 h = __float2bfloat16_rn(vv[j]);
        __nv_bfloat16 l = __float2bfloat16_rn(vv[j] - __bfloat162float(h));
        if (j & 1) { h2[j >> 1].y = h; l2[j >> 1].y = l; }
        else       { h2[j >> 1].x = h; l2[j >> 1].x = l; }
    }
    size_t base = (size_t)row * (DD / 2) + 2 * threadIdx.x;
    ((__nv_bfloat162*)yh)[base]     = h2[0];
    ((__nv_bfloat162*)yh)[base + 1] = h2[1];
    ((__nv_bfloat162*)yl)[base]     = l2[0];
    ((__nv_bfloat162*)yl)[base + 1] = l2[1];
}

// ============================================================
// L2-normalize contiguous 64-float vectors
// ============================================================
__global__ __launch_bounds__(256) void l2norm_k(float* __restrict__ v, int nvec, float sc)
{
    int vec = blockIdx.x * 8 + (threadIdx.x >> 5);
    if (vec >= nvec) return;
    int lane = threadIdx.x & 31;
    float2* p = (float2*)(v + (size_t)vec * 64) + lane;
    float2 d = *p;
    float ss = d.x * d.x + d.y * d.y;
    #pragma unroll
    for (int o = 16; o; o >>= 1) ss += __shfl_xor_sync(0xffffffffu, ss, o);
    float n = fmaxf(sqrtf(ss), 1e-12f);
    float s = sc / n;
    d.x *= s; d.y *= s;
    *p = d;
}

// ============================================================
// tensor-core bf16 split GEMM: C[M,N] = A[M,K] * W[N,K]^T
// 3-pass hi/lo split. Tile 128x128, Kchunk 64, SW128-swizzled smem,
// cp.async double buffering. Compute core: tcgen05 if the 'a'
// feature pass exists, else HMMA mma.sync (plain compute_103).
// A rows remapped: arow = (r/asl)*ast + aso + r%asl
// epi: 0 none(fp32); 1 softcap+R(gathered); 2 relu^2 -> bf16 hi/lo; 3 +R
// ============================================================
__global__ __launch_bounds__(256, 1)
void gemm_tc(const __nv_bfloat16* __restrict__ Ah, const __nv_bfloat16* __restrict__ Al,
             const __nv_bfloat16* __restrict__ Wh, const __nv_bfloat16* __restrict__ Wl,
             float* __restrict__ C,
             __nv_bfloat16* __restrict__ Chh, __nv_bfloat16* __restrict__ Chl,
             const float* __restrict__ R,
             int Nglob, int K,
             int asl, int ast, int aso,
             int rsl, int rst, int rso,
             int epi)
{
    extern __shared__ char smem[];
    const uint32_t sb = smem_u32(smem);
    const int tid = threadIdx.x;
    const int wid = tid >> 5;
    const int bm = blockIdx.x * 128;
    const int bn = blockIdx.y * 128;
    const int nchunks = K >> 6;

    // cp.async loader into stage p (4 sub-buffers of 16KB: Ah, Al, Wh, Wl)
    auto load_chunk = [&](int p, int c) {
        const int kc = c << 6;
        uint32_t bufb = sb + 1024 + p * 65536;
        #pragma unroll
        for (int i = tid; i < 1024; i += 256) {
            int r = i >> 3, seg = i & 7;
            int row = bm + r;
            size_t ar = (size_t)(row / asl) * ast + aso + (row % asl);
            const __nv_bfloat16* sh = Ah + ar * K + kc + seg * 8;
            const __nv_bfloat16* sl = Al + ar * K + kc + seg * 8;
            uint32_t off = (r << 7) + (seg << 4);
            uint32_t sw = off ^ ((off >> 3) & 0x70);
            CP_ASYNC16(bufb + sw, sh);
            CP_ASYNC16(bufb + 16384 + sw, sl);
        }
        #pragma unroll
        for (int i = tid; i < 1024; i += 256) {
            int r = i >> 3, seg = i & 7;
            const __nv_bfloat16* sh = Wh + (size_t)(bn + r) * K + kc + seg * 8;
            const __nv_bfloat16* sl = Wl + (size_t)(bn + r) * K + kc + seg * 8;
            uint32_t off = (r << 7) + (seg << 4);
            uint32_t sw = off ^ ((off >> 3) & 0x70);
            CP_ASYNC16(bufb + 32768 + sw, sh);
            CP_ASYNC16(bufb + 49152 + sw, sl);
        }
        CP_COMMIT();
    };

#if USE_TCGEN05
    if (wid == 0) TCGEN05_ALLOC(sb + 0, 128);
    if (tid == 0) { MBARRIER_INIT(sb + 8, 1); MBARRIER_INIT(sb + 16, 1); }
    __syncthreads();
    uint32_t tmem;
    asm volatile("ld.shared.b32 %0, [%1];" : "=r"(tmem) : "r"(sb + 0));

    load_chunk(0, 0);
    int ph0 = 0, ph1 = 0;
    for (int c = 0; c < nchunks; c++) {
        const int p = c & 1;
        if (c + 1 < nchunks) {
            if (c >= 1) {
                if (p == 0) { MBARRIER_WAIT_PARITY(sb + 16, ph1); ph1 ^= 1; }
                else        { MBARRIER_WAIT_PARITY(sb + 8,  ph0); ph0 ^= 1; }
            }
            load_chunk(1 - p, c + 1);
            CP_WAIT(1);
        } else {
            CP_WAIT(0);
        }
        __syncthreads();
        if (tid == 0) {
            FENCE_PROXY_ASYNC();
            uint32_t ba = sb + 1024 + p * 65536;
            uint64_t dah = make_desc_sw128(ba);
            uint64_t dal = make_desc_sw128(ba + 16384);
            uint64_t dwh = make_desc_sw128(ba + 32768);
            uint64_t dwl = make_desc_sw128(ba + 49152);
            #pragma unroll
            for (int ks = 0; ks < 4; ks++)
                mma_bf16_ss(tmem, dah + ks * 2, dwh + ks * 2, IDESC, (c | ks) != 0);
            #pragma unroll
            for (int ks = 0; ks < 4; ks++)
                mma_bf16_ss(tmem, dah + ks * 2, dwl + ks * 2, IDESC, 1);
            #pragma unroll
            for (int ks = 0; ks < 4; ks++)
                mma_bf16_ss(tmem, dal + ks * 2, dwh + ks * 2, IDESC, 1);
            TCGEN05_COMMIT(sb + 8 + 8 * p);
        }
        __syncthreads();
    }
    if (((nchunks - 1) & 1) == 0) { MBARRIER_WAIT_PARITY(sb + 8,  ph0); }
    else                          { MBARRIER_WAIT_PARITY(sb + 16, ph1); }
    TCGEN05_FENCE_AFTER();

    if (wid < 4) {
        const int lid = tid & 31;
        const int rowg = bm + wid * 32 + lid;
        #pragma unroll
        for (int cb = 0; cb < 128; cb += 32) {
            uint32_t rg[32];
            TCGEN05_LD_X32(rg, tmem + cb);
            TCGEN05_WAIT_LD();
            const int col0 = bn + cb;
            if (epi == 0) {
                float4* dst = (float4*)(C + (size_t)rowg * Nglob + col0);
                #pragma unroll
                for (int j = 0; j < 8; j++)
                    dst[j] = make_float4(__uint_as_float(rg[4*j]),   __uint_as_float(rg[4*j+1]),
                                         __uint_as_float(rg[4*j+2]), __uint_as_float(rg[4*j+3]));
            } else if (epi == 1) {
                size_t rr = (size_t)(rowg / rsl) * rst + rso + (rowg % rsl);
                const float* rp = R + rr * Nglob + col0;
                float4* dst = (float4*)(C + (size_t)rowg * Nglob + col0);
                #pragma unroll
                for (int j = 0; j < 8; j++) {
                    float4 o;
                    o.x = rp[4*j]   + 15.0f * tanhf(__uint_as_float(rg[4*j])   * (1.0f/15.0f));
                    o.y = rp[4*j+1] + 15.0f * tanhf(__uint_as_float(rg[4*j+1]) * (1.0f/15.0f));
                    o.z = rp[4*j+2] + 15.0f * tanhf(__uint_as_float(rg[4*j+2]) * (1.0f/15.0f));
                    o.w = rp[4*j+3] + 15.0f * tanhf(__uint_as_float(rg[4*j+3]) * (1.0f/15.0f));
                    dst[j] = o;
                }
            } else if (epi == 2) {
                __nv_bfloat162* dh = (__nv_bfloat162*)(Chh + (size_t)rowg * Nglob + col0);
                __nv_bfloat162* dl = (__nv_bfloat162*)(Chl + (size_t)rowg * Nglob + col0);
                #pragma unroll
                for (int j = 0; j < 16; j++) {
                    float a = fmaxf(__uint_as_float(rg[2*j]),   0.f); a *= a;
                    float b = fmaxf(__uint_as_float(rg[2*j+1]), 0.f); b *= b;
                    __nv_bfloat162 h2, l2;
                    h2.x = __float2bfloat16_rn(a);
                    h2.y = __float2bfloat16_rn(b);
                    l2.x = __float2bfloat16_rn(a - __bfloat162float(h2.x));
                    l2.y = __float2bfloat16_rn(b - __bfloat162float(h2.y));
                    dh[j] = h2; dl[j] = l2;
                }
            } else {
                const float* rp = R + (size_t)rowg * Nglob + col0;
                float4* dst = (float4*)(C + (size_t)rowg * Nglob + col0);
                #pragma unroll
                for (int j = 0; j < 8; j++) {
                    float4 o;
                    o.x = rp[4*j]   + __uint_as_float(rg[4*j]);
                    o.y = rp[4*j+1] + __uint_as_float(rg[4*j+1]);
                    o.z = rp[4*j+2] + __uint_as_float(rg[4*j+2]);
                    o.w = rp[4*j+3] + __uint_as_float(rg[4*j+3]);
                    dst[j] = o;
                }
            }
        }
        TCGEN05_FENCE_BEFORE();
    }
    __syncthreads();
    if (wid == 0) TCGEN05_DEALLOC(tmem, 128);

#else  // ===================== HMMA path (plain compute_103) =====================
    const int lane = tid & 31;
    const int warp_m = wid >> 1;      // 0..3 -> 32-row slabs
    const int warp_n = wid & 1;       // 0..1 -> 64-col slabs

    float acc[2][8][4];
    #pragma unroll
    for (int mf = 0; mf < 2; mf++)
        #pragma unroll
        for (int nf = 0; nf < 8; nf++)
            #pragma unroll
            for (int j = 0; j < 4; j++) acc[mf][nf][j] = 0.f;

    load_chunk(0, 0);

    // ldmatrix lane addressing (constant across chunks)
    const int a_row = warp_m * 32 + (lane & 15);
    const uint32_t a_koff = (lane >> 4) << 4;                 // 0 / 16 bytes
    const int b_row = warp_n * 64 + ((lane >> 4) << 3) + (lane & 7);
    const uint32_t b_koff = ((lane >> 3) & 1) << 4;

    for (int c = 0; c < nchunks; c++) {
        const int p = c & 1;
        if (c + 1 < nchunks) { load_chunk(1 - p, c + 1); CP_WAIT(1); }
        else                 { CP_WAIT(0); }
        __syncthreads();

        const uint32_t bA  = sb + 1024 + p * 65536;
        const uint32_t bAl = bA + 16384;
        const uint32_t bW  = bA + 32768;
        const uint32_t bWl = bA + 49152;

        #pragma unroll
        for (int ks = 0; ks < 4; ks++) {
            const uint32_t kb = ks * 32;
            uint32_t ah[2][4], al[2][4], wh[8][2], wl[8][2];
            #pragma unroll
            for (int mf = 0; mf < 2; mf++) {
                uint32_t off = ((uint32_t)(a_row + mf * 16) << 7) + kb + a_koff;
                off ^= (off >> 3) & 0x70;
                ldsm4(ah[mf][0], ah[mf][1], ah[mf][2], ah[mf][3], bA + off);
                ldsm4(al[mf][0], al[mf][1], al[mf][2], al[mf][3], bAl + off);
            }
            #pragma unroll
            for (int nf2 = 0; nf2 < 4; nf2++) {
                uint32_t off = ((uint32_t)(b_row + nf2 * 16) << 7) + kb + b_koff;
                off ^= (off >> 3) & 0x70;
                uint32_t t0, t1, t2, t3;
                ldsm4(t0, t1, t2, t3, bW + off);
                wh[2*nf2][0] = t0; wh[2*nf2][1] = t1;
                wh[2*nf2+1][0] = t2; wh[2*nf2+1][1] = t3;
                ldsm4(t0, t1, t2, t3, bWl + off);
                wl[2*nf2][0] = t0; wl[2*nf2][1] = t1;
                wl[2*nf2+1][0] = t2; wl[2*nf2+1][1] = t3;
            }
            #pragma unroll
            for (int mf = 0; mf < 2; mf++)
                #pragma unroll
                for (int nf = 0; nf < 8; nf++) {
                    mma16816(acc[mf][nf], ah[mf], wh[nf]);
                    mma16816(acc[mf][nf], ah[mf], wl[nf]);
                    mma16816(acc[mf][nf], al[mf], wh[nf]);
                }
        }
        __syncthreads();
    }

    // epilogue: thread owns rows (base+rq, base+rq+8), col pairs
    const int rq = lane >> 2, cq = (lane & 3) << 1;
    #pragma unroll
    for (int mf = 0; mf < 2; mf++) {
        #pragma unroll
        for (int h = 0; h < 2; h++) {
            const int rowg = bm + warp_m * 32 + mf * 16 + rq + h * 8;
            size_t rr = 0;
            if (epi == 1) rr = (size_t)(rowg / rsl) * rst + rso + (rowg % rsl);
            #pragma unroll
            for (int nf = 0; nf < 8; nf++) {
                float x0 = acc[mf][nf][2*h], x1 = acc[mf][nf][2*h+1];
                const int colg = bn + warp_n * 64 + nf * 8 + cq;
                if (epi == 0) {
                    *(float2*)(C + (size_t)rowg * Nglob + colg) = make_float2(x0, x1);
                } else if (epi == 1) {
                    const float* rp = R + rr * Nglob + colg;
                    float2 o;
                    o.x = rp[0] + 15.0f * tanhf(x0 * (1.0f/15.0f));
                    o.y = rp[1] + 15.0f * tanhf(x1 * (1.0f/15.0f));
                    *(float2*)(C + (size_t)rowg * Nglob + colg) = o;
                } else if (epi == 2) {
                    float a = fmaxf(x0, 0.f); a *= a;
                    float b = fmaxf(x1, 0.f); b *= b;
                    __nv_bfloat162 h2, l2;
                    h2.x = __float2bfloat16_rn(a);
                    h2.y = __float2bfloat16_rn(b);
                    l2.x = __float2bfloat16_rn(a - __bfloat162float(h2.x));
                    l2.y = __float2bfloat16_rn(b - __bfloat162float(h2.y));
                    *(__nv_bfloat162*)(Chh + (size_t)rowg * Nglob + colg) = h2;
                    *(__nv_bfloat162*)(Chl + (size_t)rowg * Nglob + colg) = l2;
                } else {
                    const float* rp = R + (size_t)rowg * Nglob + colg;
                    *(float2*)(C + (size_t)rowg * Nglob + colg) =
                        make_float2(rp[0] + x0, rp[1] + x1);
                }
            }
        }
    }
#endif
}

// ============================================================
// Flash attention (causal, GQA rep=4), 64q x 64k tiles, HD=64.
// writes bf16 hi/lo output (feeds Wo gemm).
// ============================================================
__global__ __launch_bounds__(256) void attn_k(
    const float* __restrict__ q, const float* __restrict__ k,
    const float* __restrict__ v,
    __nv_bfloat16* __restrict__ oh, __nv_bfloat16* __restrict__ ol)
{
    extern __shared__ float sm[];
    float* q_s = sm;
    float* k_s = sm + 64 * 68;
    float* v_s = k_s + 64 * 68;
    float* p_s = v_s + 64 * 68;

    const int tid = threadIdx.x;
    const int ty = tid >> 4, tx = tid & 15;
    const int qt = blockIdx.x;
    const int bh = blockIdx.y;
    const int b = bh >> 4, h = bh & 15;
    const int kvh = h >> 2;
    const int q0 = qt * 64;

    for (int i = tid; i < 1024; i += 256) {
        int r = i >> 4, dq = (i & 15) << 2;
        float4 t4 = *(const float4*)(q + ((size_t)(b * NU + q0 + r)) * DD + h * HD + dq);
        *(float4*)(q_s + r * 68 + dq) = t4;
    }

    float acc[4][4];
    float m_i[4], l_i[4];
    #pragma unroll
    for (int i = 0; i < 4; i++) {
        m_i[i] = -INFINITY; l_i[i] = 0.f;
        #pragma unroll
        for (int j = 0; j < 4; j++) acc[i][j] = 0.f;
    }

    const int n_kt = (CS / 64) + qt + 1;
    for (int kt = 0; kt < n_kt; kt++) {
        __syncthreads();
        const int k0 = kt * 64;
        for (int i = tid; i < 1024; i += 256) {
            int r = i >> 4, dq = (i & 15) << 2;
            size_t base = ((size_t)(b * TT + k0 + r)) * KVD + kvh * HD + dq;
            float4 k4 = *(const float4*)(k + base);
            k_s[(dq + 0) * 68 + r] = k4.x;
            k_s[(dq + 1) * 68 + r] = k4.y;
            k_s[(dq + 2) * 68 + r] = k4.z;
            k_s[(dq + 3) * 68 + r] = k4.w;
            float4 v4 = *(const float4*)(v + base);
            *(float4*)(v_s + r * 68 + dq) = v4;
        }
        __syncthreads();

        float s[4][4];
        #pragma unroll
        for (int i = 0; i < 4; i++)
            #pragma unroll
            for (int j = 0; j < 4; j++) s[i][j] = 0.f;
        #pragma unroll 8
        for (int d = 0; d < 64; d++) {
            float qv[4];
            #pragma unroll
            for (int i = 0; i < 4; i++) qv[i] = q_s[(4 * ty + i) * 68 + d];
            float4 kv = *(const float4*)(k_s + d * 68 + 4 * tx);
            #pragma unroll
            for (int i = 0; i < 4; i++) {
                s[i][0] = fmaf(qv[i], kv.x, s[i][0]);
                s[i][1] = fmaf(qv[i], kv.y, s[i][1]);
                s[i][2] = fmaf(qv[i], kv.z, s[i][2]);
                s[i][3] = fmaf(qv[i], kv.w, s[i][3]);
            }
        }

        if (kt == n_kt - 1) {
            #pragma unroll
            for (int i = 0; i < 4; i++)
                #pragma unroll
                for (int j = 0; j < 4; j++)
                    if (4 * tx + j > 4 * ty + i) s[i][j] = -INFINITY;
        }

        #pragma unroll
        for (int i = 0; i < 4; i++) {
            float mt = fmaxf(fmaxf(s[i][0], s[i][1]), fmaxf(s[i][2], s[i][3]));
            #pragma unroll
            for (int off = 8; off; off >>= 1)
                mt = fmaxf(mt, __shfl_xor_sync(0xffffffffu, mt, off));
            float m_new = fmaxf(m_i[i], mt);
            float corr = __expf(m_i[i] - m_new);
            float rs = 0.f;
            #pragma unroll
            for (int j = 0; j < 4; j++) {
                float p = __expf(s[i][j] - m_new);
                rs += p;
                p_s[(4 * tx + j) * 68 + 4 * ty + i] = p;
            }
            #pragma unroll
            for (int off = 8; off; off >>= 1)
                rs += __shfl_xor_sync(0xffffffffu, rs, off);
            l_i[i] = l_i[i] * corr + rs;
            m_i[i] = m_new;
            #pragma unroll
            for (int j = 0; j < 4; j++) acc[i][j] *= corr;
        }
        __syncthreads();

        #pragma unroll 8
        for (int kk = 0; kk < 64; kk++) {
            float4 p4 = *(const float4*)(p_s + kk * 68 + 4 * ty);
            float4 v4 = *(const float4*)(v_s + kk * 68 + 4 * tx);
            acc[0][0] = fmaf(p4.x, v4.x, acc[0][0]);
            acc[0][1] = fmaf(p4.x, v4.y, acc[0][1]);
            acc[0][2] = fmaf(p4.x, v4.z, acc[0][2]);
            acc[0][3] = fmaf(p4.x, v4.w, acc[0][3]);
            acc[1][0] = fmaf(p4.y, v4.x, acc[1][0]);
            acc[1][1] = fmaf(p4.y, v4.y, acc[1][1]);
            acc[1][2] = fmaf(p4.y, v4.z, acc[1][2]);
            acc[1][3] = fmaf(p4.y, v4.w, acc[1][3]);
            acc[2][0] = fmaf(p4.z, v4.x, acc[2][0]);
            acc[2][1] = fmaf(p4.z, v4.y, acc[2][1]);
            acc[2][2] = fmaf(p4.z, v4.z, acc[2][2]);
            acc[2][3] = fmaf(p4.z, v4.w, acc[2][3]);
            acc[3][0] = fmaf(p4.w, v4.x, acc[3][0]);
            acc[3][1] = fmaf(p4.w, v4.y, acc[3][1]);
            acc[3][2] = fmaf(p4.w, v4.z, acc[3][2]);
            acc[3][3] = fmaf(p4.w, v4.w, acc[3][3]);
        }
    }

    #pragma unroll
    for (int i = 0; i < 4; i++) {
        float inv = 1.0f / l_i[i];
        float o[4] = {acc[i][0] * inv, acc[i][1] * inv, acc[i][2] * inv, acc[i][3] * inv};
        __nv_bfloat162 h2[2], l2[2];
        #pragma unroll
        for (int j = 0; j < 4; j++) {
            __nv_bfloat16 hh = __float2bfloat16_rn(o[j]);
            __nv_bfloat16 ll = __float2bfloat16_rn(o[j] - __bfloat162float(hh));
            if (j & 1) { h2[j >> 1].y = hh; l2[j >> 1].y = ll; }
            else       { h2[j >> 1].x = hh; l2[j >> 1].x = ll; }
        }
        size_t idx = ((size_t)(b * NU + q0 + 4 * ty + i)) * DD + h * HD + 4 * tx;
        ((__nv_bfloat162*)(oh + idx))[0] = h2[0];
        ((__nv_bfloat162*)(oh + idx))[1] = h2[1];
        ((__nv_bfloat162*)(ol + idx))[0] = l2[0];
        ((__nv_bfloat162*)(ol + idx))[1] = l2[1];
    }
}

// ============================================================
// final: out[b,t,:] = t<CS ? x : fin
// ============================================================
__global__ __launch_bounds__(256) void finalize_k(const float* __restrict__ x,
                                                  const float* __restrict__ fin,
                                                  float* __restrict__ out)
{
    size_t i = (size_t)blockIdx.x * 256 + threadIdx.x;
    int rowd = (int)(i >> 8);
    int c4 = (int)(i & 255);
    int t = rowd % TT;
    float4 val;
    if (t < CS) {
        val = ((const float4*)x)[i];
    } else {
        int b = rowd / TT;
        val = ((const float4*)fin)[(size_t)(b * NU + (t - CS)) * 256 + c4];
    }
    ((float4*)out)[i] = val;
}

// ============================================================
extern "C" void kernel_launch(void* const* d_in, const int* in_sizes, int n_in,
                              void* d_out, int out_size)
{
    const float* x     = (const float*)d_in[0];
    const float* Wq    = (const float*)d_in[1];
    const float* Wk    = (const float*)d_in[2];
    const float* Wv    = (const float*)d_in[3];
    const float* Wo    = (const float*)d_in[4];
    const float* Wfc   = (const float*)d_in[5];
    const float* Wproj = (const float*)d_in[6];
    float* out = (float*)d_out;

    __nv_bfloat16 *xnh, *xnl, *ah, *al, *x2h, *x2l, *hh, *hl;
    __nv_bfloat16 *wqh, *wql, *wkh, *wkl, *wvh, *wvl, *woh, *wol, *wfh, *wfl, *wph, *wpl;
    float *qb, *kb, *vb, *xnb, *fin;
    cudaGetSymbolAddress((void**)&xnh, g_xnh); cudaGetSymbolAddress((void**)&xnl, g_xnl);
    cudaGetSymbolAddress((void**)&qb,  g_q);
    cudaGetSymbolAddress((void**)&kb,  g_k);
    cudaGetSymbolAddress((void**)&vb,  g_v);
    cudaGetSymbolAddress((void**)&ah,  g_ah);  cudaGetSymbolAddress((void**)&al,  g_al);
    cudaGetSymbolAddress((void**)&xnb, g_xnew);
    cudaGetSymbolAddress((void**)&x2h, g_x2h); cudaGetSymbolAddress((void**)&x2l, g_x2l);
    cudaGetSymbolAddress((void**)&hh,  g_hh);  cudaGetSymbolAddress((void**)&hl,  g_hl);
    cudaGetSymbolAddress((void**)&fin, g_fin);
    cudaGetSymbolAddress((void**)&wqh, g_wqh); cudaGetSymbolAddress((void**)&wql, g_wql);
    cudaGetSymbolAddress((void**)&wkh, g_wkh); cudaGetSymbolAddress((void**)&wkl, g_wkl);
    cudaGetSymbolAddress((void**)&wvh, g_wvh); cudaGetSymbolAddress((void**)&wvl, g_wvl);
    cudaGetSymbolAddress((void**)&woh, g_woh); cudaGetSymbolAddress((void**)&wol, g_wol);
    cudaGetSymbolAddress((void**)&wfh, g_wfh); cudaGetSymbolAddress((void**)&wfl, g_wfl);
    cudaGetSymbolAddress((void**)&wph, g_wph); cudaGetSymbolAddress((void**)&wpl, g_wpl);

    cudaFuncSetAttribute(gemm_tc, cudaFuncAttributeMaxDynamicSharedMemorySize, 132096);
    cudaFuncSetAttribute(attn_k, cudaFuncAttributeMaxDynamicSharedMemorySize,
                         4 * 64 * 68 * (int)sizeof(float));

    // 0. weight hi/lo split
    cvt_hl_k<<<(DD * DD / 4 + 255) / 256, 256>>>(Wq, wqh, wql, DD * DD / 4);
    cvt_hl_k<<<(KVD * DD / 4 + 255) / 256, 256>>>(Wk, wkh, wkl, KVD * DD / 4);
    cvt_hl_k<<<(KVD * DD / 4 + 255) / 256, 256>>>(Wv, wvh, wvl, KVD * DD / 4);
    cvt_hl_k<<<(DD * DD / 4 + 255) / 256, 256>>>(Wo, woh, wol, DD * DD / 4);
    cvt_hl_k<<<(DFF * DD / 4 + 255) / 256, 256>>>(Wfc, wfh, wfl, DFF * DD / 4);
    cvt_hl_k<<<(DD * DFF / 4 + 255) / 256, 256>>>(Wproj, wph, wpl, DD * DFF / 4);

    // 1. x_norm = rms_norm(x) -> bf16 hi/lo
    rmsnorm_hl_k<<<MX, 256>>>(x, xnh, xnl);

    const int SMEM = 132096;
    // 2. K, V, Q projections (tensor core)
    gemm_tc<<<dim3(MX / 128, KVD / 128), 256, SMEM>>>(xnh, xnl, wkh, wkl, kb, nullptr, nullptr,
        nullptr, KVD, DD, MX, MX, 0, 1, 1, 0, 0);
    gemm_tc<<<dim3(MX / 128, KVD / 128), 256, SMEM>>>(xnh, xnl, wvh, wvl, vb, nullptr, nullptr,
        nullptr, KVD, DD, MX, MX, 0, 1, 1, 0, 0);
    gemm_tc<<<dim3(MQ / 128, DD / 128), 256, SMEM>>>(xnh, xnl, wqh, wql, qb, nullptr, nullptr,
        nullptr, DD, DD, NU, TT, CS, 1, 1, 0, 0);

    // 3. L2 normalize (q also picks up 1/sqrt(HD))
    l2norm_k<<<(MQ * HH) / 8, 256>>>(qb, MQ * HH, 0.125f);
    l2norm_k<<<(MX * KVH) / 8, 256>>>(kb, MX * KVH, 1.0f);

    // 4. flash attention -> bf16 hi/lo
    attn_k<<<dim3(NU / 64, BB * HH), 256, 4 * 64 * 68 * sizeof(float)>>>(qb, kb, vb, ah, al);

    // 5. x_new = x_upd + softcap(attn @ Wo^T)
    gemm_tc<<<dim3(MQ / 128, DD / 128), 256, SMEM>>>(ah, al, woh, wol, xnb, nullptr, nullptr,
        x, DD, DD, MQ, MQ, 0, NU, TT, CS, 1);

    // 6. FFN
    rmsnorm_hl_k<<<MQ, 256>>>(xnb, x2h, x2l);
    gemm_tc<<<dim3(MQ / 128, DFF / 128), 256, SMEM>>>(x2h, x2l, wfh, wfl, nullptr, hh, hl,
        nullptr, DFF, DD, MQ, MQ, 0, 1, 1, 0, 2);
    gemm_tc<<<dim3(MQ / 128, DD / 128), 256, SMEM>>>(hh, hl, wph, wpl, fin, nullptr, nullptr,
        xnb, DD, DFF, MQ, MQ, 0, MQ, MQ, 0, 3);

    // 7. scatter output
    finalize_k<<<MX, 256>>>(x, fin, out);
}

// round 5
// speedup vs baseline: 4.5245x; 2.4487x over previous
#include <cuda_runtime.h>
#include <cuda_bf16.h>
#include <stdint.h>
#include <math.h>

// ---- fixed problem shape (HBlock_18597208391748) ----
#define BB   2
#define TT   4160
#define DD   1024
#define HH   16
#define KVH  4
#define HD   64
#define CS   2048
#define NU   (TT - CS)        // 2112
#define KVD  (KVH * HD)       // 256
#define DFF  (4 * DD)         // 4096
#define MQ   (BB * NU)        // 4224
#define MX   (BB * TT)        // 8320

// ---- scratch (device globals; no allocation allowed) ----
__device__ __nv_bfloat16 g_xnh[(size_t)MX * DD], g_xnl[(size_t)MX * DD];
__device__ float g_q [(size_t)MQ * DD];
__device__ float g_k [(size_t)MX * KVD];
__device__ float g_v [(size_t)MX * KVD];
__device__ __nv_bfloat16 g_qbf[(size_t)MQ * DD];      // [b*H+h][NU][64]
__device__ __nv_bfloat16 g_kbf[(size_t)MX * KVD];     // [b*KVH+kvh][TT][64]
__device__ __nv_bfloat16 g_vbf[(size_t)MX * KVD];
__device__ __nv_bfloat16 g_ah[(size_t)MQ * DD], g_al[(size_t)MQ * DD];
__device__ float g_xnew[(size_t)MQ * DD];
__device__ __nv_bfloat16 g_x2h[(size_t)MQ * DD], g_x2l[(size_t)MQ * DD];
__device__ __nv_bfloat16 g_hh[(size_t)MQ * DFF], g_hl[(size_t)MQ * DFF];
__device__ float g_fin[(size_t)MQ * DD];
// weight hi/lo
__device__ __nv_bfloat16 g_wqh[DD * DD],  g_wql[DD * DD];
__device__ __nv_bfloat16 g_wkh[KVD * DD], g_wkl[KVD * DD];
__device__ __nv_bfloat16 g_wvh[KVD * DD], g_wvl[KVD * DD];
__device__ __nv_bfloat16 g_woh[DD * DD],  g_wol[DD * DD];
__device__ __nv_bfloat16 g_wfh[DFF * DD], g_wfl[DFF * DD];
__device__ __nv_bfloat16 g_wph[DD * DFF], g_wpl[DD * DFF];

// ============================================================
// PTX helpers
// ============================================================
__device__ __forceinline__ uint32_t smem_u32(const void* p) {
    uint32_t a;
    asm("{ .reg .u64 t; cvta.to.shared.u64 t, %1; cvt.u32.u64 %0, t; }" : "=r"(a) : "l"(p));
    return a;
}
#define CP_ASYNC16(dst, src) \
    asm volatile("cp.async.cg.shared.global [%0], [%1], 16;" :: "r"(dst), "l"(src))
#define CP_COMMIT() asm volatile("cp.async.commit_group;" ::: "memory")
#define CP_WAIT(n)  asm volatile("cp.async.wait_group %0;" :: "n"(n) : "memory")

__device__ __forceinline__ void ldsm4(uint32_t& r0, uint32_t& r1, uint32_t& r2, uint32_t& r3,
                                      uint32_t a) {
    asm volatile("ldmatrix.sync.aligned.m8n8.x4.shared.b16 {%0,%1,%2,%3}, [%4];"
                 : "=r"(r0), "=r"(r1), "=r"(r2), "=r"(r3) : "r"(a));
}
__device__ __forceinline__ void ldsm4t(uint32_t& r0, uint32_t& r1, uint32_t& r2, uint32_t& r3,
                                       uint32_t a) {
    asm volatile("ldmatrix.sync.aligned.m8n8.x4.trans.shared.b16 {%0,%1,%2,%3}, [%4];"
                 : "=r"(r0), "=r"(r1), "=r"(r2), "=r"(r3) : "r"(a));
}
__device__ __forceinline__ void mma16816(float* d, const uint32_t* a, const uint32_t* b) {
    asm volatile("mma.sync.aligned.m16n8k16.row.col.f32.bf16.bf16.f32 "
                 "{%0,%1,%2,%3}, {%4,%5,%6,%7}, {%8,%9}, {%0,%1,%2,%3};"
                 : "+f"(d[0]), "+f"(d[1]), "+f"(d[2]), "+f"(d[3])
                 : "r"(a[0]), "r"(a[1]), "r"(a[2]), "r"(a[3]), "r"(b[0]), "r"(b[1]));
}
__device__ __forceinline__ uint32_t packbf(float lo, float hi) {
    uint32_t r;
    asm("cvt.rn.bf16x2.f32 %0, %1, %2;" : "=r"(r) : "f"(hi), "f"(lo));
    return r;
}

// ============================================================
// weight fp32 -> bf16 hi/lo split
// ============================================================
__global__ __launch_bounds__(256) void cvt_hl_k(const float* __restrict__ x,
                                                __nv_bfloat16* __restrict__ hi,
                                                __nv_bfloat16* __restrict__ lo, int n4)
{
    int i = blockIdx.x * 256 + threadIdx.x;
    if (i >= n4) return;
    float4 v = ((const float4*)x)[i];
    float vv[4] = {v.x, v.y, v.z, v.w};
    __nv_bfloat162 h2[2], l2[2];
    #pragma unroll
    for (int j = 0; j < 4; j++) {
        __nv_bfloat16 h = __float2bfloat16_rn(vv[j]);
        __nv_bfloat16 l = __float2bfloat16_rn(vv[j] - __bfloat162float(h));
        if (j & 1) { h2[j >> 1].y = h; l2[j >> 1].y = l; }
        else       { h2[j >> 1].x = h; l2[j >> 1].x = l; }
    }
    ((__nv_bfloat162*)hi)[2 * i]     = h2[0];
    ((__nv_bfloat162*)hi)[2 * i + 1] = h2[1];
    ((__nv_bfloat162*)lo)[2 * i]     = l2[0];
    ((__nv_bfloat162*)lo)[2 * i + 1] = l2[1];
}

// ============================================================
// RMSNorm -> bf16 hi/lo
// ============================================================
__global__ __launch_bounds__(256) void rmsnorm_hl_k(const float* __restrict__ x,
                                                    __nv_bfloat16* __restrict__ yh,
                                                    __nv_bfloat16* __restrict__ yl)
{
    const int row = blockIdx.x;
    const float4* xr = (const float4*)x + (size_t)row * (DD / 4);
    float4 v = xr[threadIdx.x];
    float ss = v.x * v.x + v.y * v.y + v.z * v.z + v.w * v.w;
    #pragma unroll
    for (int o = 16; o; o >>= 1) ss += __shfl_xor_sync(0xffffffffu, ss, o);
    __shared__ float red[8];
    if ((threadIdx.x & 31) == 0) red[threadIdx.x >> 5] = ss;
    __syncthreads();
    float tot = red[0] + red[1] + red[2] + red[3] + red[4] + red[5] + red[6] + red[7];
    float s = rsqrtf(tot * (1.0f / DD) + 1e-6f);
    float vv[4] = {v.x * s, v.y * s, v.z * s, v.w * s};
    __nv_bfloat162 h2[2], l2[2];
    #pragma unroll
    for (int j = 0; j < 4; j++) {
        __nv_bfloat16 h = __float2bfloat16_rn(vv[j]);
        __nv_bfloat16 l = __float2bfloat16_rn(vv[j] - __bfloat162float(h));
        if (j & 1) { h2[j >> 1].y = h; l2[j >> 1].y = l; }
        else       { h2[j >> 1].x = h; l2[j >> 1].x = l; }
    }
    size_t base = (size_t)row * (DD / 2) + 2 * threadIdx.x;
    ((__nv_bfloat162*)yh)[base]     = h2[0];
    ((__nv_bfloat162*)yh)[base + 1] = h2[1];
    ((__nv_bfloat162*)yl)[base]     = l2[0];
    ((__nv_bfloat162*)yl)[base + 1] = l2[1];
}

// ============================================================
// L2-normalize 64-float vectors -> bf16, head-major layout.
// in rows: [row][Hh*64] with vec = row*Hh + h; out [(b*Hh+h)*SEQ+t][64]
// ============================================================
__global__ __launch_bounds__(256) void l2n_bf_k(const float* __restrict__ in,
                                                __nv_bfloat16* __restrict__ out,
                                                int nvec, int hshift, int SEQ, float sc)
{
    int vec = blockIdx.x * 8 + (threadIdx.x >> 5);
    if (vec >= nvec) return;
    int lane = threadIdx.x & 31;
    const float2* p = (const float2*)(in + (size_t)vec * 64) + lane;
    float2 d = *p;
    float ss = d.x * d.x + d.y * d.y;
    #pragma unroll
    for (int o = 16; o; o >>= 1) ss += __shfl_xor_sync(0xffffffffu, ss, o);
    float n = fmaxf(sqrtf(ss), 1e-12f);
    float s = sc / n;
    __nv_bfloat162 o2;
    o2.x = __float2bfloat16_rn(d.x * s);
    o2.y = __float2bfloat16_rn(d.y * s);
    int Hm = (1 << hshift) - 1;
    int h = vec & Hm;
    int row = vec >> hshift;
    int b = row / SEQ, t = row - b * SEQ;
    size_t ob = ((size_t)((b << hshift) + h) * SEQ + t) * 64;
    *(__nv_bfloat162*)(out + ob + lane * 2) = o2;
}

// ============================================================
// V fp32 [b*TT+t][256] -> bf16 head-major [(b*4+kvh)*TT+t][64]
// ============================================================
__global__ __launch_bounds__(256) void cvt_v_k(const float* __restrict__ v,
                                               __nv_bfloat16* __restrict__ out)
{
    int i = blockIdx.x * 256 + threadIdx.x;   // one float4 each
    if (i >= MX * KVD / 4) return;
    int flat = i * 4;
    int row = flat >> 8;
    int cidx = flat & 255;
    int kvh = cidx >> 6, dd = cidx & 63;
    int b = row / TT, t = row - b * TT;
    float4 x = ((const float4*)v)[i];
    __nv_bfloat162 a, c;
    a.x = __float2bfloat16_rn(x.x); a.y = __float2bfloat16_rn(x.y);
    c.x = __float2bfloat16_rn(x.z); c.y = __float2bfloat16_rn(x.w);
    size_t ob = ((size_t)(b * KVH + kvh) * TT + t) * 64 + dd;
    *(__nv_bfloat162*)(out + ob)     = a;
    *(__nv_bfloat162*)(out + ob + 2) = c;
}

// ============================================================
// tensor-core bf16 split GEMM (HMMA mma.sync): C = A * W^T
// 3-pass hi/lo split. Tile 128x128, Kchunk 64, SW128 smem, cp.async x2 buf.
// A rows remapped: arow = (r/asl)*ast + aso + r%asl
// epi: 0 none(fp32); 1 softcap+R(gathered); 2 relu^2 -> bf16 hi/lo; 3 +R
// ============================================================
__global__ __launch_bounds__(256, 1)
void gemm_tc(const __nv_bfloat16* __restrict__ Ah, const __nv_bfloat16* __restrict__ Al,
             const __nv_bfloat16* __restrict__ Wh, const __nv_bfloat16* __restrict__ Wl,
             float* __restrict__ C,
             __nv_bfloat16* __restrict__ Chh, __nv_bfloat16* __restrict__ Chl,
             const float* __restrict__ R,
             int Nglob, int K,
             int asl, int ast, int aso,
             int rsl, int rst, int rso,
             int epi)
{
    extern __shared__ char smem[];
    const uint32_t sb = smem_u32(smem);
    const int tid = threadIdx.x;
    const int wid = tid >> 5;
    const int bm = blockIdx.x * 128;
    const int bn = blockIdx.y * 128;
    const int nchunks = K >> 6;

    auto load_chunk = [&](int p, int c) {
        const int kc = c << 6;
        uint32_t bufb = sb + 1024 + p * 65536;
        #pragma unroll
        for (int i = tid; i < 1024; i += 256) {
            int r = i >> 3, seg = i & 7;
            int row = bm + r;
            size_t ar = (size_t)(row / asl) * ast + aso + (row % asl);
            const __nv_bfloat16* sh = Ah + ar * K + kc + seg * 8;
            const __nv_bfloat16* sl = Al + ar * K + kc + seg * 8;
            uint32_t off = (r << 7) + (seg << 4);
            uint32_t sw = off ^ ((off >> 3) & 0x70);
            CP_ASYNC16(bufb + sw, sh);
            CP_ASYNC16(bufb + 16384 + sw, sl);
        }
        #pragma unroll
        for (int i = tid; i < 1024; i += 256) {
            int r = i >> 3, seg = i & 7;
            const __nv_bfloat16* sh = Wh + (size_t)(bn + r) * K + kc + seg * 8;
            const __nv_bfloat16* sl = Wl + (size_t)(bn + r) * K + kc + seg * 8;
            uint32_t off = (r << 7) + (seg << 4);
            uint32_t sw = off ^ ((off >> 3) & 0x70);
            CP_ASYNC16(bufb + 32768 + sw, sh);
            CP_ASYNC16(bufb + 49152 + sw, sl);
        }
        CP_COMMIT();
    };

    const int lane = tid & 31;
    const int warp_m = wid >> 1;
    const int warp_n = wid & 1;

    float acc[2][8][4];
    #pragma unroll
    for (int mf = 0; mf < 2; mf++)
        #pragma unroll
        for (int nf = 0; nf < 8; nf++)
            #pragma unroll
            for (int j = 0; j < 4; j++) acc[mf][nf][j] = 0.f;

    load_chunk(0, 0);

    const int a_row = warp_m * 32 + (lane & 15);
    const uint32_t a_koff = (lane >> 4) << 4;
    const int b_row = warp_n * 64 + ((lane >> 4) << 3) + (lane & 7);
    const uint32_t b_koff = ((lane >> 3) & 1) << 4;

    for (int c = 0; c < nchunks; c++) {
        const int p = c & 1;
        if (c + 1 < nchunks) { load_chunk(1 - p, c + 1); CP_WAIT(1); }
        else                 { CP_WAIT(0); }
        __syncthreads();

        const uint32_t bA  = sb + 1024 + p * 65536;
        const uint32_t bAl = bA + 16384;
        const uint32_t bW  = bA + 32768;
        const uint32_t bWl = bA + 49152;

        #pragma unroll
        for (int ks = 0; ks < 4; ks++) {
            const uint32_t kb = ks * 32;
            uint32_t ah[2][4], al[2][4], wh[8][2], wl[8][2];
            #pragma unroll
            for (int mf = 0; mf < 2; mf++) {
                uint32_t off = ((uint32_t)(a_row + mf * 16) << 7) + kb + a_koff;
                off ^= (off >> 3) & 0x70;
                ldsm4(ah[mf][0], ah[mf][1], ah[mf][2], ah[mf][3], bA + off);
                ldsm4(al[mf][0], al[mf][1], al[mf][2], al[mf][3], bAl + off);
            }
            #pragma unroll
            for (int nf2 = 0; nf2 < 4; nf2++) {
                uint32_t off = ((uint32_t)(b_row + nf2 * 16) << 7) + kb + b_koff;
                off ^= (off >> 3) & 0x70;
                uint32_t t0, t1, t2, t3;
                ldsm4(t0, t1, t2, t3, bW + off);
                wh[2*nf2][0] = t0; wh[2*nf2][1] = t1;
                wh[2*nf2+1][0] = t2; wh[2*nf2+1][1] = t3;
                ldsm4(t0, t1, t2, t3, bWl + off);
                wl[2*nf2][0] = t0; wl[2*nf2][1] = t1;
                wl[2*nf2+1][0] = t2; wl[2*nf2+1][1] = t3;
            }
            #pragma unroll
            for (int mf = 0; mf < 2; mf++)
                #pragma unroll
                for (int nf = 0; nf < 8; nf++) {
                    mma16816(acc[mf][nf], ah[mf], wh[nf]);
                    mma16816(acc[mf][nf], ah[mf], wl[nf]);
                    mma16816(acc[mf][nf], al[mf], wh[nf]);
                }
        }
        __syncthreads();
    }

    const int rq = lane >> 2, cq = (lane & 3) << 1;
    #pragma unroll
    for (int mf = 0; mf < 2; mf++) {
        #pragma unroll
        for (int h = 0; h < 2; h++) {
            const int rowg = bm + warp_m * 32 + mf * 16 + rq + h * 8;
            size_t rr = 0;
            if (epi == 1) rr = (size_t)(rowg / rsl) * rst + rso + (rowg % rsl);
            #pragma unroll
            for (int nf = 0; nf < 8; nf++) {
                float x0 = acc[mf][nf][2*h], x1 = acc[mf][nf][2*h+1];
                const int colg = bn + warp_n * 64 + nf * 8 + cq;
                if (epi == 0) {
                    *(float2*)(C + (size_t)rowg * Nglob + colg) = make_float2(x0, x1);
                } else if (epi == 1) {
                    const float* rp = R + rr * Nglob + colg;
                    float2 o;
                    o.x = rp[0] + 15.0f * tanhf(x0 * (1.0f/15.0f));
                    o.y = rp[1] + 15.0f * tanhf(x1 * (1.0f/15.0f));
                    *(float2*)(C + (size_t)rowg * Nglob + colg) = o;
                } else if (epi == 2) {
                    float a = fmaxf(x0, 0.f); a *= a;
                    float b = fmaxf(x1, 0.f); b *= b;
                    __nv_bfloat162 h2, l2;
                    h2.x = __float2bfloat16_rn(a);
                    h2.y = __float2bfloat16_rn(b);
                    l2.x = __float2bfloat16_rn(a - __bfloat162float(h2.x));
                    l2.y = __float2bfloat16_rn(b - __bfloat162float(h2.y));
                    *(__nv_bfloat162*)(Chh + (size_t)rowg * Nglob + colg) = h2;
                    *(__nv_bfloat162*)(Chl + (size_t)rowg * Nglob + colg) = l2;
                } else {
                    const float* rp = R + (size_t)rowg * Nglob + colg;
                    *(float2*)(C + (size_t)rowg * Nglob + colg) =
                        make_float2(rp[0] + x0, rp[1] + x1);
                }
            }
        }
    }
}

// ============================================================
// Flash attention via mma.sync bf16 (causal, GQA rep=4).
// 64 q-rows per block, 4 warps x 16 rows. No-max softmax (|s|<=0.125).
// smem: Q 8KB @0; stage p: K @8192+p*16384, V @+8192. Total 40960.
// ============================================================
__global__ __launch_bounds__(128) void attn_mma(
    const __nv_bfloat16* __restrict__ qbf,
    const __nv_bfloat16* __restrict__ kbf,
    const __nv_bfloat16* __restrict__ vbf,
    __nv_bfloat16* __restrict__ oh, __nv_bfloat16* __restrict__ ol)
{
    extern __shared__ char sm[];
    const uint32_t sb = smem_u32(sm);
    const int tid = threadIdx.x;
    const int w = tid >> 5, l = tid & 31;
    const int qt = blockIdx.x;
    const int bh = blockIdx.y;
    const int b = bh >> 4, h = bh & 15;
    const int q0 = qt * 64;

    const __nv_bfloat16* qg = qbf + ((size_t)bh * NU + q0) * 64;
    const __nv_bfloat16* kg = kbf + ((size_t)(b * KVH + (h >> 2)) * TT) * 64;
    const __nv_bfloat16* vg = vbf + ((size_t)(b * KVH + (h >> 2)) * TT) * 64;

    // Q load (one-time)
    for (int i = tid; i < 512; i += 128) {
        int r = i >> 3, seg = i & 7;
        uint32_t off = (r << 7) + (seg << 4);
        uint32_t swo = off ^ ((off >> 3) & 0x70);
        CP_ASYNC16(sb + swo, qg + r * 64 + seg * 8);
    }
    const int n_kt = (CS >> 6) + qt + 1;
    auto load_kv = [&](int p, int c) {
        uint32_t base = sb + 8192 + p * 16384;
        const __nv_bfloat16* ks = kg + (size_t)(c << 6) * 64;
        const __nv_bfloat16* vs = vg + (size_t)(c << 6) * 64;
        for (int i = tid; i < 512; i += 128) {
            int r = i >> 3, seg = i & 7;
            uint32_t off = (r << 7) + (seg << 4);
            uint32_t swo = off ^ ((off >> 3) & 0x70);
            CP_ASYNC16(base + swo, ks + r * 64 + seg * 8);
            CP_ASYNC16(base + 8192 + swo, vs + r * 64 + seg * 8);
        }
        CP_COMMIT();
    };
    load_kv(0, 0);

    float o_acc[8][4];
    #pragma unroll
    for (int j = 0; j < 8; j++)
        #pragma unroll
        for (int i = 0; i < 4; i++) o_acc[j][i] = 0.f;
    float rsum0 = 0.f, rsum1 = 0.f;

    const int lrow = l & 15;
    const int lhi = l >> 4;
    const int qpos = CS + q0 + w * 16 + (l >> 2);   // global q pos of row0 frag

    for (int c = 0; c < n_kt; c++) {
        const int p = c & 1;
        if (c + 1 < n_kt) { load_kv(1 - p, c + 1); CP_WAIT(1); }
        else              { CP_WAIT(0); }
        __syncthreads();
        const uint32_t kbase = sb + 8192 + p * 16384;
        const uint32_t vbase = kbase + 8192;

        // ---- S = Q K^T ----
        float s[8][4];
        #pragma unroll
        for (int j = 0; j < 8; j++)
            #pragma unroll
            for (int i = 0; i < 4; i++) s[j][i] = 0.f;
        #pragma unroll
        for (int ks = 0; ks < 4; ks++) {
            uint32_t a[4];
            {
                uint32_t off = ((uint32_t)(w * 16 + lrow) << 7) + ks * 32 + (lhi << 4);
                off ^= (off >> 3) & 0x70;
                ldsm4(a[0], a[1], a[2], a[3], sb + off);
            }
            #pragma unroll
            for (int j = 0; j < 8; j += 2) {
                uint32_t off = ((uint32_t)((j + lhi) * 8 + (l & 7)) << 7)
                             + ks * 32 + (((l >> 3) & 1) << 4);
                off ^= (off >> 3) & 0x70;
                uint32_t b0, b1, b2, b3;
                ldsm4(b0, b1, b2, b3, kbase + off);
                uint32_t bb0[2] = {b0, b1}, bb1[2] = {b2, b3};
                mma16816(s[j],     a, bb0);
                mma16816(s[j + 1], a, bb1);
            }
        }

        // ---- causal mask on diagonal tile ----
        if (c == n_kt - 1) {
            const int k0 = c * 64;
            #pragma unroll
            for (int j = 0; j < 8; j++) {
                int kc = k0 + j * 8 + ((l & 3) << 1);
                if (kc     > qpos)     s[j][0] = -1e30f;
                if (kc + 1 > qpos)     s[j][1] = -1e30f;
                if (kc     > qpos + 8) s[j][2] = -1e30f;
                if (kc + 1 > qpos + 8) s[j][3] = -1e30f;
            }
        }

        // ---- P = exp(S) (no max needed: |s| <= 0.125), row sums ----
        #pragma unroll
        for (int j = 0; j < 8; j++) {
            s[j][0] = __expf(s[j][0]);
            s[j][1] = __expf(s[j][1]);
            s[j][2] = __expf(s[j][2]);
            s[j][3] = __expf(s[j][3]);
            rsum0 += s[j][0] + s[j][1];
            rsum1 += s[j][2] + s[j][3];
        }

        // ---- O += P V ----
        #pragma unroll
        for (int ks = 0; ks < 4; ks++) {
            uint32_t a[4];
            a[0] = packbf(s[2*ks][0],   s[2*ks][1]);
            a[1] = packbf(s[2*ks][2],   s[2*ks][3]);
            a[2] = packbf(s[2*ks+1][0], s[2*ks+1][1]);
            a[3] = packbf(s[2*ks+1][2], s[2*ks+1][3]);
            #pragma unroll
            for (int j = 0; j < 8; j += 2) {
                uint32_t off = ((uint32_t)(ks * 16 + lrow) << 7) + ((j + lhi) << 4);
                off ^= (off >> 3) & 0x70;
                uint32_t b0, b1, b2, b3;
                ldsm4t(b0, b1, b2, b3, vbase + off);
                uint32_t bb0[2] = {b0, b1}, bb1[2] = {b2, b3};
                mma16816(o_acc[j],     a, bb0);
                mma16816(o_acc[j + 1], a, bb1);
            }
        }
        __syncthreads();
    }

    // final row-sum reduce across the quad owning each row
    rsum0 += __shfl_xor_sync(0xffffffffu, rsum0, 1);
    rsum0 += __shfl_xor_sync(0xffffffffu, rsum0, 2);
    rsum1 += __shfl_xor_sync(0xffffffffu, rsum1, 1);
    rsum1 += __shfl_xor_sync(0xffffffffu, rsum1, 2);
    const float inv0 = 1.0f / rsum0, inv1 = 1.0f / rsum1;

    const size_t gr0 = (size_t)(b * NU + q0 + w * 16 + (l >> 2));
    const size_t gr1 = gr0 + 8;
    const int colb = h * 64 + ((l & 3) << 1);
    #pragma unroll
    for (int j = 0; j < 8; j++) {
        const int col = colb + j * 8;
        float v0 = o_acc[j][0] * inv0, v1 = o_acc[j][1] * inv0;
        float v2 = o_acc[j][2] * inv1, v3 = o_acc[j][3] * inv1;
        __nv_bfloat162 h2, l2;
        h2.x = __float2bfloat16_rn(v0); h2.y = __float2bfloat16_rn(v1);
        l2.x = __float2bfloat16_rn(v0 - __bfloat162float(h2.x));
        l2.y = __float2bfloat16_rn(v1 - __bfloat162float(h2.y));
        *(__nv_bfloat162*)(oh + gr0 * DD + col) = h2;
        *(__nv_bfloat162*)(ol + gr0 * DD + col) = l2;
        h2.x = __float2bfloat16_rn(v2); h2.y = __float2bfloat16_rn(v3);
        l2.x = __float2bfloat16_rn(v2 - __bfloat162float(h2.x));
        l2.y = __float2bfloat16_rn(v3 - __bfloat162float(h2.y));
        *(__nv_bfloat162*)(oh + gr1 * DD + col) = h2;
        *(__nv_bfloat162*)(ol + gr1 * DD + col) = l2;
    }
}

// ============================================================
// final: out[b,t,:] = t<CS ? x : fin
// ============================================================
__global__ __launch_bounds__(256) void finalize_k(const float* __restrict__ x,
                                                  const float* __restrict__ fin,
                                                  float* __restrict__ out)
{
    size_t i = (size_t)blockIdx.x * 256 + threadIdx.x;
    int rowd = (int)(i >> 8);
    int c4 = (int)(i & 255);
    int t = rowd % TT;
    float4 val;
    if (t < CS) {
        val = ((const float4*)x)[i];
    } else {
        int b = rowd / TT;
        val = ((const float4*)fin)[(size_t)(b * NU + (t - CS)) * 256 + c4];
    }
    ((float4*)out)[i] = val;
}

// ============================================================
extern "C" void kernel_launch(void* const* d_in, const int* in_sizes, int n_in,
                              void* d_out, int out_size)
{
    const float* x     = (const float*)d_in[0];
    const float* Wq    = (const float*)d_in[1];
    const float* Wk    = (const float*)d_in[2];
    const float* Wv    = (const float*)d_in[3];
    const float* Wo    = (const float*)d_in[4];
    const float* Wfc   = (const float*)d_in[5];
    const float* Wproj = (const float*)d_in[6];
    float* out = (float*)d_out;

    __nv_bfloat16 *xnh, *xnl, *ah, *al, *x2h, *x2l, *hh, *hl, *qbf, *kbf, *vbf;
    __nv_bfloat16 *wqh, *wql, *wkh, *wkl, *wvh, *wvl, *woh, *wol, *wfh, *wfl, *wph, *wpl;
    float *qb, *kb, *vb, *xnb, *fin;
    cudaGetSymbolAddress((void**)&xnh, g_xnh); cudaGetSymbolAddress((void**)&xnl, g_xnl);
    cudaGetSymbolAddress((void**)&qb,  g_q);
    cudaGetSymbolAddress((void**)&kb,  g_k);
    cudaGetSymbolAddress((void**)&vb,  g_v);
    cudaGetSymbolAddress((void**)&qbf, g_qbf);
    cudaGetSymbolAddress((void**)&kbf, g_kbf);
    cudaGetSymbolAddress((void**)&vbf, g_vbf);
    cudaGetSymbolAddress((void**)&ah,  g_ah);  cudaGetSymbolAddress((void**)&al,  g_al);
    cudaGetSymbolAddress((void**)&xnb, g_xnew);
    cudaGetSymbolAddress((void**)&x2h, g_x2h); cudaGetSymbolAddress((void**)&x2l, g_x2l);
    cudaGetSymbolAddress((void**)&hh,  g_hh);  cudaGetSymbolAddress((void**)&hl,  g_hl);
    cudaGetSymbolAddress((void**)&fin, g_fin);
    cudaGetSymbolAddress((void**)&wqh, g_wqh); cudaGetSymbolAddress((void**)&wql, g_wql);
    cudaGetSymbolAddress((void**)&wkh, g_wkh); cudaGetSymbolAddress((void**)&wkl, g_wkl);
    cudaGetSymbolAddress((void**)&wvh, g_wvh); cudaGetSymbolAddress((void**)&wvl, g_wvl);
    cudaGetSymbolAddress((void**)&woh, g_woh); cudaGetSymbolAddress((void**)&wol, g_wol);
    cudaGetSymbolAddress((void**)&wfh, g_wfh); cudaGetSymbolAddress((void**)&wfl, g_wfl);
    cudaGetSymbolAddress((void**)&wph, g_wph); cudaGetSymbolAddress((void**)&wpl, g_wpl);

    cudaFuncSetAttribute(gemm_tc, cudaFuncAttributeMaxDynamicSharedMemorySize, 132096);
    cudaFuncSetAttribute(attn_mma, cudaFuncAttributeMaxDynamicSharedMemorySize, 40960);

    // 0. weight hi/lo split
    cvt_hl_k<<<(DD * DD / 4 + 255) / 256, 256>>>(Wq, wqh, wql, DD * DD / 4);
    cvt_hl_k<<<(KVD * DD / 4 + 255) / 256, 256>>>(Wk, wkh, wkl, KVD * DD / 4);
    cvt_hl_k<<<(KVD * DD / 4 + 255) / 256, 256>>>(Wv, wvh, wvl, KVD * DD / 4);
    cvt_hl_k<<<(DD * DD / 4 + 255) / 256, 256>>>(Wo, woh, wol, DD * DD / 4);
    cvt_hl_k<<<(DFF * DD / 4 + 255) / 256, 256>>>(Wfc, wfh, wfl, DFF * DD / 4);
    cvt_hl_k<<<(DD * DFF / 4 + 255) / 256, 256>>>(Wproj, wph, wpl, DD * DFF / 4);

    // 1. x_norm = rms_norm(x) -> bf16 hi/lo
    rmsnorm_hl_k<<<MX, 256>>>(x, xnh, xnl);

    const int SMEM = 132096;
    // 2. K, V, Q projections
    gemm_tc<<<dim3(MX / 128, KVD / 128), 256, SMEM>>>(xnh, xnl, wkh, wkl, kb, nullptr, nullptr,
        nullptr, KVD, DD, MX, MX, 0, 1, 1, 0, 0);
    gemm_tc<<<dim3(MX / 128, KVD / 128), 256, SMEM>>>(xnh, xnl, wvh, wvl, vb, nullptr, nullptr,
        nullptr, KVD, DD, MX, MX, 0, 1, 1, 0, 0);
    gemm_tc<<<dim3(MQ / 128, DD / 128), 256, SMEM>>>(xnh, xnl, wqh, wql, qb, nullptr, nullptr,
        nullptr, DD, DD, NU, TT, CS, 1, 1, 0, 0);

    // 3. L2 normalize -> bf16 head-major (q gets 1/sqrt(HD) folded in)
    l2n_bf_k<<<(MQ * HH + 7) / 8, 256>>>(qb, qbf, MQ * HH, 4, NU, 0.125f);
    l2n_bf_k<<<(MX * KVH + 7) / 8, 256>>>(kb, kbf, MX * KVH, 2, TT, 1.0f);
    cvt_v_k<<<(MX * KVD / 4 + 255) / 256, 256>>>(vb, vbf);

    // 4. flash attention (tensor cores) -> bf16 hi/lo
    attn_mma<<<dim3(NU / 64, BB * HH), 128, 40960>>>(qbf, kbf, vbf, ah, al);

    // 5. x_new = x_upd + softcap(attn @ Wo^T)
    gemm_tc<<<dim3(MQ / 128, DD / 128), 256, SMEM>>>(ah, al, woh, wol, xnb, nullptr, nullptr,
        x, DD, DD, MQ, MQ, 0, NU, TT, CS, 1);

    // 6. FFN
    rmsnorm_hl_k<<<MQ, 256>>>(xnb, x2h, x2l);
    gemm_tc<<<dim3(MQ / 128, DFF / 128), 256, SMEM>>>(x2h, x2l, wfh, wfl, nullptr, hh, hl,
        nullptr, DFF, DD, MQ, MQ, 0, 1, 1, 0, 2);
    gemm_tc<<<dim3(MQ / 128, DD / 128), 256, SMEM>>>(hh, hl, wph, wpl, fin, nullptr, nullptr,
        xnb, DD, DFF, MQ, MQ, 0, MQ, MQ, 0, 3);

    // 7. scatter output
    finalize_k<<<MX, 256>>>(x, fin, out);
}

// round 6
// speedup vs baseline: 5.6118x; 1.2403x over previous
#include <cuda_runtime.h>
#include <cuda_fp16.h>
#include <stdint.h>
#include <math.h>

// ---- fixed problem shape (HBlock_18597208391748) ----
#define BB   2
#define TT   4160
#define DD   1024
#define HH   16
#define KVH  4
#define HD   64
#define CS   2048
#define NU   (TT - CS)        // 2112
#define KVD  (KVH * HD)       // 256
#define DFF  (4 * DD)         // 4096
#define MQ   (BB * NU)        // 4224
#define MX   (BB * TT)        // 8320

// ---- scratch (device globals; no allocation allowed) ----
__device__ __half g_xnf[(size_t)MX * DD];          // rms_norm(x) fp16
__device__ __half g_qbf[(size_t)MQ * DD];          // [b*16+h][NU][64]
__device__ __half g_kbf[(size_t)MX * KVD];         // [b*4+kvh][TT][64]
__device__ __half g_vbf[(size_t)MX * KVD];
__device__ __half g_af [(size_t)MQ * DD];          // attention out fp16
__device__ float  g_xnew[(size_t)MQ * DD];         // x_new fp32
__device__ __half g_x2h[(size_t)MQ * DD], g_x2l[(size_t)MQ * DD];
__device__ __half g_hf [(size_t)MQ * DFF];         // relu^2 out fp16
// weights fp16 (QKV/Wo single; Wfc/Wproj hi/lo)
__device__ __half g_wq[DD * DD];
__device__ __half g_wk[KVD * DD];
__device__ __half g_wv[KVD * DD];
__device__ __half g_wo[DD * DD];
__device__ __half g_wfh[DFF * DD], g_wfl[DFF * DD];
__device__ __half g_wph[DD * DFF], g_wpl[DD * DFF];

// ============================================================
// PTX helpers
// ============================================================
__device__ __forceinline__ uint32_t smem_u32(const void* p) {
    uint32_t a;
    asm("{ .reg .u64 t; cvta.to.shared.u64 t, %1; cvt.u32.u64 %0, t; }" : "=r"(a) : "l"(p));
    return a;
}
#define CP_ASYNC16(dst, src) \
    asm volatile("cp.async.cg.shared.global [%0], [%1], 16;" :: "r"(dst), "l"(src))
#define CP_COMMIT() asm volatile("cp.async.commit_group;" ::: "memory")
#define CP_WAIT(n)  asm volatile("cp.async.wait_group %0;" :: "n"(n) : "memory")

__device__ __forceinline__ void ldsm4(uint32_t& r0, uint32_t& r1, uint32_t& r2, uint32_t& r3,
                                      uint32_t a) {
    asm volatile("ldmatrix.sync.aligned.m8n8.x4.shared.b16 {%0,%1,%2,%3}, [%4];"
                 : "=r"(r0), "=r"(r1), "=r"(r2), "=r"(r3) : "r"(a));
}
__device__ __forceinline__ void ldsm4t(uint32_t& r0, uint32_t& r1, uint32_t& r2, uint32_t& r3,
                                       uint32_t a) {
    asm volatile("ldmatrix.sync.aligned.m8n8.x4.trans.shared.b16 {%0,%1,%2,%3}, [%4];"
                 : "=r"(r0), "=r"(r1), "=r"(r2), "=r"(r3) : "r"(a));
}
__device__ __forceinline__ void mma_f16(float* d, const uint32_t* a, const uint32_t* b) {
    asm volatile("mma.sync.aligned.m16n8k16.row.col.f32.f16.f16.f32 "
                 "{%0,%1,%2,%3}, {%4,%5,%6,%7}, {%8,%9}, {%0,%1,%2,%3};"
                 : "+f"(d[0]), "+f"(d[1]), "+f"(d[2]), "+f"(d[3])
                 : "r"(a[0]), "r"(a[1]), "r"(a[2]), "r"(a[3]), "r"(b[0]), "r"(b[1]));
}
__device__ __forceinline__ uint32_t packh2(float lo, float hi) {
    __half2 h = __floats2half2_rn(lo, hi);
    return *reinterpret_cast<uint32_t*>(&h);
}
__device__ __forceinline__ float tanhfast(float x) {
    float e = __expf(2.0f * x);
    return (e - 1.0f) / (e + 1.0f);
}

// ============================================================
// weight fp32 -> fp16 single (2 float4 per thread)
// ============================================================
__global__ __launch_bounds__(256) void cvt_h_k(const float* __restrict__ x,
                                               __half* __restrict__ y, int n4)
{
    int i0 = (blockIdx.x * 256 + threadIdx.x) * 2;
    #pragma unroll
    for (int j = 0; j < 2; j++) {
        int i = i0 + j;
        if (i < n4) {
            float4 v = ((const float4*)x)[i];
            ((__half2*)y)[2*i]     = __floats2half2_rn(v.x, v.y);
            ((__half2*)y)[2*i + 1] = __floats2half2_rn(v.z, v.w);
        }
    }
}

// ============================================================
// weight fp32 -> fp16 hi/lo split (2 float4 per thread)
// ============================================================
__global__ __launch_bounds__(256) void cvt_hl_k(const float* __restrict__ x,
                                                __half* __restrict__ hi,
                                                __half* __restrict__ lo, int n4)
{
    int i0 = (blockIdx.x * 256 + threadIdx.x) * 2;
    #pragma unroll
    for (int j = 0; j < 2; j++) {
        int i = i0 + j;
        if (i < n4) {
            float4 v = ((const float4*)x)[i];
            float vv[4] = {v.x, v.y, v.z, v.w};
            __half h[4], l[4];
            #pragma unroll
            for (int t = 0; t < 4; t++) {
                h[t] = __float2half_rn(vv[t]);
                l[t] = __float2half_rn(vv[t] - __half2float(h[t]));
            }
            ((__half2*)hi)[2*i]     = __halves2half2(h[0], h[1]);
            ((__half2*)hi)[2*i + 1] = __halves2half2(h[2], h[3]);
            ((__half2*)lo)[2*i]     = __halves2half2(l[0], l[1]);
            ((__half2*)lo)[2*i + 1] = __halves2half2(l[2], l[3]);
        }
    }
}

// ============================================================
// RMSNorm fp32 -> fp16 (optionally hi/lo if yl != null)
// ============================================================
__global__ __launch_bounds__(256) void rms_k(const float* __restrict__ x,
                                             __half* __restrict__ yh,
                                             __half* __restrict__ yl)
{
    const int row = blockIdx.x;
    const float4* xr = (const float4*)x + (size_t)row * (DD / 4);
    float4 v = xr[threadIdx.x];
    float ss = v.x * v.x + v.y * v.y + v.z * v.z + v.w * v.w;
    #pragma unroll
    for (int o = 16; o; o >>= 1) ss += __shfl_xor_sync(0xffffffffu, ss, o);
    __shared__ float red[8];
    if ((threadIdx.x & 31) == 0) red[threadIdx.x >> 5] = ss;
    __syncthreads();
    float tot = red[0] + red[1] + red[2] + red[3] + red[4] + red[5] + red[6] + red[7];
    float s = rsqrtf(tot * (1.0f / DD) + 1e-6f);
    float vv[4] = {v.x * s, v.y * s, v.z * s, v.w * s};
    size_t base = (size_t)row * (DD / 2) + 2 * threadIdx.x;
    __half h[4];
    #pragma unroll
    for (int t = 0; t < 4; t++) h[t] = __float2half_rn(vv[t]);
    ((__half2*)yh)[base]     = __halves2half2(h[0], h[1]);
    ((__half2*)yh)[base + 1] = __halves2half2(h[2], h[3]);
    if (yl) {
        __half l[4];
        #pragma unroll
        for (int t = 0; t < 4; t++) l[t] = __float2half_rn(vv[t] - __half2float(h[t]));
        ((__half2*)yl)[base]     = __halves2half2(l[0], l[1]);
        ((__half2*)yl)[base + 1] = __halves2half2(l[2], l[3]);
    }
}

// ============================================================
// fp16 HMMA GEMM: C[M,N] = A[M,K] * W[N,K]^T, tile 128x128, Kchunk 64.
// PASSES: 1 = A*Wh; 2 = A*(Wh+Wl); 3 = Ah*(Wh+Wl) + Al*Wh.
// A rows remapped: arow = (r/asl)*ast + aso + r%asl
// epi: 1 softcap + R(gathered) -> fp32 C dense     (Wo)
//      2 relu^2 -> fp16 Ch dense                   (Wfc)
//      3 +R dense -> fp32 C rows gathered          (Wproj -> out)
//      4 l2norm*sc -> fp16 HM head-major           (Q, K)
//      5 fp16 HM head-major                        (V)
// ============================================================
template<int PASSES>
__global__ __launch_bounds__(256)
void gemm_tc(const __half* __restrict__ Ah, const __half* __restrict__ Al,
             const __half* __restrict__ Wh, const __half* __restrict__ Wl,
             float* __restrict__ C, __half* __restrict__ Ch, __half* __restrict__ HM,
             const float* __restrict__ R,
             int Nglob, int K,
             int asl, int ast, int aso,
             int rsl, int rst, int rso,
             int SEQ, float sc, int epi)
{
    extern __shared__ char smem[];
    const uint32_t sb = smem_u32(smem);
    const int tid = threadIdx.x;
    const int wid = tid >> 5;
    const int lane = tid & 31;
    const int bm = blockIdx.x * 128;
    const int bn = blockIdx.y * 128;
    const int nchunks = K >> 6;
    constexpr uint32_t SS = (PASSES == 1) ? 32768u : (PASSES == 2) ? 49152u : 65536u;

    auto load_chunk = [&](int p, int c) {
        const int kc = c << 6;
        uint32_t bufb = sb + 1024 + p * SS;
        #pragma unroll
        for (int i = tid; i < 1024; i += 256) {
            int r = i >> 3, seg = i & 7;
            int row = bm + r;
            size_t ar = (size_t)(row / asl) * ast + aso + (row % asl);
            uint32_t off = (r << 7) + (seg << 4);
            uint32_t sw = off ^ ((off >> 3) & 0x70);
            CP_ASYNC16(bufb + sw, Ah + ar * K + kc + seg * 8);
            if (PASSES == 3) CP_ASYNC16(bufb + 49152 + sw, Al + ar * K + kc + seg * 8);
        }
        #pragma unroll
        for (int i = tid; i < 1024; i += 256) {
            int r = i >> 3, seg = i & 7;
            uint32_t off = (r << 7) + (seg << 4);
            uint32_t sw = off ^ ((off >> 3) & 0x70);
            CP_ASYNC16(bufb + 16384 + sw, Wh + (size_t)(bn + r) * K + kc + seg * 8);
            if (PASSES >= 2) CP_ASYNC16(bufb + 32768 + sw, Wl + (size_t)(bn + r) * K + kc + seg * 8);
        }
        CP_COMMIT();
    };

    const int warp_m = wid >> 1;
    const int warp_n = wid & 1;

    float acc[2][8][4];
    #pragma unroll
    for (int mf = 0; mf < 2; mf++)
        #pragma unroll
        for (int nf = 0; nf < 8; nf++)
            #pragma unroll
            for (int j = 0; j < 4; j++) acc[mf][nf][j] = 0.f;

    load_chunk(0, 0);

    const int a_row = warp_m * 32 + (lane & 15);
    const uint32_t a_koff = (lane >> 4) << 4;
    const int b_row = warp_n * 64 + ((lane >> 4) << 3) + (lane & 7);
    const uint32_t b_koff = ((lane >> 3) & 1) << 4;

    for (int c = 0; c < nchunks; c++) {
        const int p = c & 1;
        if (c + 1 < nchunks) { load_chunk(1 - p, c + 1); CP_WAIT(1); }
        else                 { CP_WAIT(0); }
        __syncthreads();

        const uint32_t bA  = sb + 1024 + p * SS;
        const uint32_t bWh = bA + 16384;
        const uint32_t bWl = bA + 32768;
        const uint32_t bAl = bA + 49152;

        #pragma unroll
        for (int ks = 0; ks < 4; ks++) {
            const uint32_t kb = ks * 32;
            uint32_t ah[2][4], al[2][4], wh[8][2], wl[8][2];
            #pragma unroll
            for (int mf = 0; mf < 2; mf++) {
                uint32_t off = ((uint32_t)(a_row + mf * 16) << 7) + kb + a_koff;
                off ^= (off >> 3) & 0x70;
                ldsm4(ah[mf][0], ah[mf][1], ah[mf][2], ah[mf][3], bA + off);
                if (PASSES == 3)
                    ldsm4(al[mf][0], al[mf][1], al[mf][2], al[mf][3], bAl + off);
            }
            #pragma unroll
            for (int nf2 = 0; nf2 < 4; nf2++) {
                uint32_t off = ((uint32_t)(b_row + nf2 * 16) << 7) + kb + b_koff;
                off ^= (off >> 3) & 0x70;
                uint32_t t0, t1, t2, t3;
                ldsm4(t0, t1, t2, t3, bWh + off);
                wh[2*nf2][0] = t0; wh[2*nf2][1] = t1;
                wh[2*nf2+1][0] = t2; wh[2*nf2+1][1] = t3;
                if (PASSES >= 2) {
                    ldsm4(t0, t1, t2, t3, bWl + off);
                    wl[2*nf2][0] = t0; wl[2*nf2][1] = t1;
                    wl[2*nf2+1][0] = t2; wl[2*nf2+1][1] = t3;
                }
            }
            #pragma unroll
            for (int mf = 0; mf < 2; mf++)
                #pragma unroll
                for (int nf = 0; nf < 8; nf++) {
                    mma_f16(acc[mf][nf], ah[mf], wh[nf]);
                    if (PASSES >= 2) mma_f16(acc[mf][nf], ah[mf], wl[nf]);
                    if (PASSES == 3) mma_f16(acc[mf][nf], al[mf], wh[nf]);
                }
        }
        __syncthreads();
    }

    // ---- epilogue ----
    const int rq = lane >> 2, cq = (lane & 3) << 1;
    if (epi >= 4) {
        // head-major fp16 out, optional l2 normalize (epi 4)
        const int headw = (bn + warp_n * 64) >> 6;
        const int heads = Nglob >> 6;
        #pragma unroll
        for (int mf = 0; mf < 2; mf++) {
            #pragma unroll
            for (int h2 = 0; h2 < 2; h2++) {
                const int rowg = bm + warp_m * 32 + mf * 16 + rq + h2 * 8;
                float s = 1.0f;
                if (epi == 4) {
                    float ss = 0.f;
                    #pragma unroll
                    for (int nf = 0; nf < 8; nf++) {
                        float x0 = acc[mf][nf][2*h2], x1 = acc[mf][nf][2*h2+1];
                        ss += x0 * x0 + x1 * x1;
                    }
                    ss += __shfl_xor_sync(0xffffffffu, ss, 1);
                    ss += __shfl_xor_sync(0xffffffffu, ss, 2);
                    s = sc / fmaxf(sqrtf(ss), 1e-12f);
                }
                int b = rowg / SEQ, t = rowg - b * SEQ;
                __half* dst = HM + (((size_t)(b * heads + headw)) * SEQ + t) * 64;
                #pragma unroll
                for (int nf = 0; nf < 8; nf++) {
                    float x0 = acc[mf][nf][2*h2] * s, x1 = acc[mf][nf][2*h2+1] * s;
                    *(__half2*)(dst + nf * 8 + cq) = __floats2half2_rn(x0, x1);
                }
            }
        }
    } else {
        #pragma unroll
        for (int mf = 0; mf < 2; mf++) {
            #pragma unroll
            for (int h2 = 0; h2 < 2; h2++) {
                const int rowg = bm + warp_m * 32 + mf * 16 + rq + h2 * 8;
                #pragma unroll
                for (int nf = 0; nf < 8; nf++) {
                    float x0 = acc[mf][nf][2*h2], x1 = acc[mf][nf][2*h2+1];
                    const int colg = bn + warp_n * 64 + nf * 8 + cq;
                    if (epi == 1) {
                        size_t rr = (size_t)(rowg / rsl) * rst + rso + (rowg % rsl);
                        const float* rp = R + rr * Nglob + colg;
                        float2 o;
                        o.x = rp[0] + 15.0f * tanhfast(x0 * (1.0f/15.0f));
                        o.y = rp[1] + 15.0f * tanhfast(x1 * (1.0f/15.0f));
                        *(float2*)(C + (size_t)rowg * Nglob + colg) = o;
                    } else if (epi == 2) {
                        float a = fmaxf(x0, 0.f); a *= a;
                        float b = fmaxf(x1, 0.f); b *= b;
                        *(__half2*)(Ch + (size_t)rowg * Nglob + colg) = __floats2half2_rn(a, b);
                    } else { // epi == 3: +R dense, C rows gathered
                        const float* rp = R + (size_t)rowg * Nglob + colg;
                        size_t cr = (size_t)(rowg / rsl) * rst + rso + (rowg % rsl);
                        *(float2*)(C + cr * Nglob + colg) =
                            make_float2(rp[0] + x0, rp[1] + x1);
                    }
                }
            }
        }
    }
}

// ============================================================
// Flash attention via mma.sync fp16 (causal, GQA rep=4).
// 64 q-rows per block, 4 warps x 16 rows. No-max softmax (|s|<=0.125).
// smem: Q 8KB @0; stage p: K @8192+p*16384, V @+8192. Total 40960.
// ============================================================
__global__ __launch_bounds__(128) void attn_mma(
    const __half* __restrict__ qbf,
    const __half* __restrict__ kbf,
    const __half* __restrict__ vbf,
    __half* __restrict__ o)
{
    extern __shared__ char sm[];
    const uint32_t sb = smem_u32(sm);
    const int tid = threadIdx.x;
    const int w = tid >> 5, l = tid & 31;
    const int qt = blockIdx.x;
    const int bh = blockIdx.y;
    const int b = bh >> 4, h = bh & 15;
    const int q0 = qt * 64;

    const __half* qg = qbf + ((size_t)bh * NU + q0) * 64;
    const __half* kg = kbf + ((size_t)(b * KVH + (h >> 2)) * TT) * 64;
    const __half* vg = vbf + ((size_t)(b * KVH + (h >> 2)) * TT) * 64;

    for (int i = tid; i < 512; i += 128) {
        int r = i >> 3, seg = i & 7;
        uint32_t off = (r << 7) + (seg << 4);
        uint32_t swo = off ^ ((off >> 3) & 0x70);
        CP_ASYNC16(sb + swo, qg + r * 64 + seg * 8);
    }
    const int n_kt = (CS >> 6) + qt + 1;
    auto load_kv = [&](int p, int c) {
        uint32_t base = sb + 8192 + p * 16384;
        const __half* ks = kg + (size_t)(c << 6) * 64;
        const __half* vs = vg + (size_t)(c << 6) * 64;
        for (int i = tid; i < 512; i += 128) {
            int r = i >> 3, seg = i & 7;
            uint32_t off = (r << 7) + (seg << 4);
            uint32_t swo = off ^ ((off >> 3) & 0x70);
            CP_ASYNC16(base + swo, ks + r * 64 + seg * 8);
            CP_ASYNC16(base + 8192 + swo, vs + r * 64 + seg * 8);
        }
        CP_COMMIT();
    };
    load_kv(0, 0);

    float o_acc[8][4];
    #pragma unroll
    for (int j = 0; j < 8; j++)
        #pragma unroll
        for (int i = 0; i < 4; i++) o_acc[j][i] = 0.f;
    float rsum0 = 0.f, rsum1 = 0.f;

    const int lrow = l & 15;
    const int lhi = l >> 4;
    const int qpos = CS + q0 + w * 16 + (l >> 2);

    for (int c = 0; c < n_kt; c++) {
        const int p = c & 1;
        if (c + 1 < n_kt) { load_kv(1 - p, c + 1); CP_WAIT(1); }
        else              { CP_WAIT(0); }
        __syncthreads();
        const uint32_t kbase = sb + 8192 + p * 16384;
        const uint32_t vbase = kbase + 8192;

        float s[8][4];
        #pragma unroll
        for (int j = 0; j < 8; j++)
            #pragma unroll
            for (int i = 0; i < 4; i++) s[j][i] = 0.f;
        #pragma unroll
        for (int ks = 0; ks < 4; ks++) {
            uint32_t a[4];
            {
                uint32_t off = ((uint32_t)(w * 16 + lrow) << 7) + ks * 32 + (lhi << 4);
                off ^= (off >> 3) & 0x70;
                ldsm4(a[0], a[1], a[2], a[3], sb + off);
            }
            #pragma unroll
            for (int j = 0; j < 8; j += 2) {
                uint32_t off = ((uint32_t)((j + lhi) * 8 + (l & 7)) << 7)
                             + ks * 32 + (((l >> 3) & 1) << 4);
                off ^= (off >> 3) & 0x70;
                uint32_t b0, b1, b2, b3;
                ldsm4(b0, b1, b2, b3, kbase + off);
                uint32_t bb0[2] = {b0, b1}, bb1[2] = {b2, b3};
                mma_f16(s[j],     a, bb0);
                mma_f16(s[j + 1], a, bb1);
            }
        }

        if (c == n_kt - 1) {
            const int k0 = c * 64;
            #pragma unroll
            for (int j = 0; j < 8; j++) {
                int kc = k0 + j * 8 + ((l & 3) << 1);
                if (kc     > qpos)     s[j][0] = -1e30f;
                if (kc + 1 > qpos)     s[j][1] = -1e30f;
                if (kc     > qpos + 8) s[j][2] = -1e30f;
                if (kc + 1 > qpos + 8) s[j][3] = -1e30f;
            }
        }

        #pragma unroll
        for (int j = 0; j < 8; j++) {
            s[j][0] = __expf(s[j][0]);
            s[j][1] = __expf(s[j][1]);
            s[j][2] = __expf(s[j][2]);
            s[j][3] = __expf(s[j][3]);
            rsum0 += s[j][0] + s[j][1];
            rsum1 += s[j][2] + s[j][3];
        }

        #pragma unroll
        for (int ks = 0; ks < 4; ks++) {
            uint32_t a[4];
            a[0] = packh2(s[2*ks][0],   s[2*ks][1]);
            a[1] = packh2(s[2*ks][2],   s[2*ks][3]);
            a[2] = packh2(s[2*ks+1][0], s[2*ks+1][1]);
            a[3] = packh2(s[2*ks+1][2], s[2*ks+1][3]);
            #pragma unroll
            for (int j = 0; j < 8; j += 2) {
                uint32_t off = ((uint32_t)(ks * 16 + lrow) << 7) + ((j + lhi) << 4);
                off ^= (off >> 3) & 0x70;
                uint32_t b0, b1, b2, b3;
                ldsm4t(b0, b1, b2, b3, vbase + off);
                uint32_t bb0[2] = {b0, b1}, bb1[2] = {b2, b3};
                mma_f16(o_acc[j],     a, bb0);
                mma_f16(o_acc[j + 1], a, bb1);
            }
        }
        __syncthreads();
    }

    rsum0 += __shfl_xor_sync(0xffffffffu, rsum0, 1);
    rsum0 += __shfl_xor_sync(0xffffffffu, rsum0, 2);
    rsum1 += __shfl_xor_sync(0xffffffffu, rsum1, 1);
    rsum1 += __shfl_xor_sync(0xffffffffu, rsum1, 2);
    const float inv0 = 1.0f / rsum0, inv1 = 1.0f / rsum1;

    const size_t gr0 = (size_t)(b * NU + q0 + w * 16 + (l >> 2));
    const size_t gr1 = gr0 + 8;
    const int colb = h * 64 + ((l & 3) << 1);
    #pragma unroll
    for (int j = 0; j < 8; j++) {
        const int col = colb + j * 8;
        *(__half2*)(o + gr0 * DD + col) =
            __floats2half2_rn(o_acc[j][0] * inv0, o_acc[j][1] * inv0);
        *(__half2*)(o + gr1 * DD + col) =
            __floats2half2_rn(o_acc[j][2] * inv1, o_acc[j][3] * inv1);
    }
}

// ============================================================
// copy prefix rows: out[b, t<CS, :] = x
// ============================================================
__global__ __launch_bounds__(256) void copy_pre_k(const float* __restrict__ x,
                                                  float* __restrict__ out)
{
    int i4 = blockIdx.x * 256 + threadIdx.x;      // float4 idx over (BB*CS*256)
    int row = i4 >> 8;                             // b*CS + t
    int col = i4 & 255;
    int b = row >> 11;                             // CS = 2048
    int t = row & 2047;
    size_t g = ((size_t)(b * TT + t) << 8) + col;
    ((float4*)out)[g] = ((const float4*)x)[g];
}

// ============================================================
extern "C" void kernel_launch(void* const* d_in, const int* in_sizes, int n_in,
                              void* d_out, int out_size)
{
    const float* x     = (const float*)d_in[0];
    const float* Wq    = (const float*)d_in[1];
    const float* Wk    = (const float*)d_in[2];
    const float* Wv    = (const float*)d_in[3];
    const float* Wo    = (const float*)d_in[4];
    const float* Wfc   = (const float*)d_in[5];
    const float* Wproj = (const float*)d_in[6];
    float* out = (float*)d_out;

    __half *xnf, *qbf, *kbf, *vbf, *af, *x2h, *x2l, *hf;
    __half *wq, *wk, *wv, *wo, *wfh, *wfl, *wph, *wpl;
    float *xnew;
    cudaGetSymbolAddress((void**)&xnf, g_xnf);
    cudaGetSymbolAddress((void**)&qbf, g_qbf);
    cudaGetSymbolAddress((void**)&kbf, g_kbf);
    cudaGetSymbolAddress((void**)&vbf, g_vbf);
    cudaGetSymbolAddress((void**)&af,  g_af);
    cudaGetSymbolAddress((void**)&xnew, g_xnew);
    cudaGetSymbolAddress((void**)&x2h, g_x2h);
    cudaGetSymbolAddress((void**)&x2l, g_x2l);
    cudaGetSymbolAddress((void**)&hf,  g_hf);
    cudaGetSymbolAddress((void**)&wq,  g_wq);
    cudaGetSymbolAddress((void**)&wk,  g_wk);
    cudaGetSymbolAddress((void**)&wv,  g_wv);
    cudaGetSymbolAddress((void**)&wo,  g_wo);
    cudaGetSymbolAddress((void**)&wfh, g_wfh); cudaGetSymbolAddress((void**)&wfl, g_wfl);
    cudaGetSymbolAddress((void**)&wph, g_wph); cudaGetSymbolAddress((void**)&wpl, g_wpl);

    const int SM1 = 1024 + 2 * 32768;   // 66560
    const int SM2 = 1024 + 2 * 49152;   // 99328
    const int SM3 = 1024 + 2 * 65536;   // 132096
    cudaFuncSetAttribute(gemm_tc<1>, cudaFuncAttributeMaxDynamicSharedMemorySize, SM1);
    cudaFuncSetAttribute(gemm_tc<2>, cudaFuncAttributeMaxDynamicSharedMemorySize, SM2);
    cudaFuncSetAttribute(gemm_tc<3>, cudaFuncAttributeMaxDynamicSharedMemorySize, SM3);
    cudaFuncSetAttribute(attn_mma, cudaFuncAttributeMaxDynamicSharedMemorySize, 40960);

    // 0. weight conversion
    cvt_h_k<<<DD * DD / 4 / 512, 256>>>(Wq, wq, DD * DD / 4);
    cvt_h_k<<<KVD * DD / 4 / 512, 256>>>(Wk, wk, KVD * DD / 4);
    cvt_h_k<<<KVD * DD / 4 / 512, 256>>>(Wv, wv, KVD * DD / 4);
    cvt_h_k<<<DD * DD / 4 / 512, 256>>>(Wo, wo, DD * DD / 4);
    cvt_hl_k<<<DFF * DD / 4 / 512, 256>>>(Wfc, wfh, wfl, DFF * DD / 4);
    cvt_hl_k<<<DD * DFF / 4 / 512, 256>>>(Wproj, wph, wpl, DD * DFF / 4);

    // 1. x_norm = rms_norm(x) -> fp16
    rms_k<<<MX, 256>>>(x, xnf, nullptr);

    // 2. K, V, Q projections, fused l2norm + head-major fp16 out
    gemm_tc<1><<<dim3(MX / 128, KVD / 128), 256, SM1>>>(xnf, nullptr, wk, nullptr,
        nullptr, nullptr, kbf, nullptr, KVD, DD, MX, MX, 0, 0, 0, 0, TT, 1.0f, 4);
    gemm_tc<1><<<dim3(MX / 128, KVD / 128), 256, SM1>>>(xnf, nullptr, wv, nullptr,
        nullptr, nullptr, vbf, nullptr, KVD, DD, MX, MX, 0, 0, 0, 0, TT, 1.0f, 5);
    gemm_tc<1><<<dim3(MQ / 128, DD / 128), 256, SM1>>>(xnf, nullptr, wq, nullptr,
        nullptr, nullptr, qbf, nullptr, DD, DD, NU, TT, CS, 0, 0, 0, NU, 0.125f, 4);

    // 3. flash attention (fp16 tensor cores)
    attn_mma<<<dim3(NU / 64, BB * HH), 128, 40960>>>(qbf, kbf, vbf, af);

    // 4. x_new = x_upd + softcap(attn @ Wo^T)
    gemm_tc<1><<<dim3(MQ / 128, DD / 128), 256, SM1>>>(af, nullptr, wo, nullptr,
        xnew, nullptr, nullptr, x, DD, DD, MQ, MQ, 0, NU, TT, CS, 0, 0.f, 1);

    // 5. FFN
    rms_k<<<MQ, 256>>>(xnew, x2h, x2l);
    gemm_tc<3><<<dim3(MQ / 128, DFF / 128), 256, SM3>>>(x2h, x2l, wfh, wfl,
        nullptr, hf, nullptr, nullptr, DFF, DD, MQ, MQ, 0, 0, 0, 0, 0, 0.f, 2);
    gemm_tc<2><<<dim3(MQ / 128, DD / 128), 256, SM2>>>(hf, nullptr, wph, wpl,
        out, nullptr, nullptr, xnew, DD, DFF, MQ, MQ, 0, NU, TT, CS, 0, 0.f, 3);

    // 6. prefix copy
    copy_pre_k<<<BB * CS * 256 / 256, 256>>>(x, out);
}

// round 7
// speedup vs baseline: 7.6930x; 1.3709x over previous
#include <cuda_runtime.h>
#include <cuda_fp16.h>
#include <stdint.h>
#include <math.h>

// ---- fixed problem shape (HBlock_18597208391748) ----
#define BB   2
#define TT   4160
#define DD   1024
#define HH   16
#define KVH  4
#define HD   64
#define CS   2048
#define NU   (TT - CS)        // 2112
#define KVD  (KVH * HD)       // 256
#define DFF  (4 * DD)         // 4096
#define MQ   (BB * NU)        // 4224
#define MX   (BB * TT)        // 8320

// ---- scratch (device globals; no allocation allowed) ----
__device__ __half g_xnf[(size_t)MX * DD];          // rms_norm(x) fp16
__device__ __half g_qbf[(size_t)MQ * DD];          // [b*16+h][NU][64]
__device__ __half g_kbf[(size_t)MX * KVD];         // [b*4+kvh][TT][64]
__device__ __half g_vbf[(size_t)MX * KVD];
__device__ __half g_af [(size_t)MQ * DD];          // attention out fp16
__device__ float  g_xnew[(size_t)MQ * DD];         // x_new fp32
__device__ __half g_x2f[(size_t)MQ * DD];          // rms(x_new) fp16
__device__ __half g_hf [(size_t)MQ * DFF];         // relu^2 out fp16
// weights fp16 (QKV/Wo/Wproj single; Wfc hi/lo)
__device__ __half g_wq[DD * DD];
__device__ __half g_wk[KVD * DD];
__device__ __half g_wv[KVD * DD];
__device__ __half g_wo[DD * DD];
__device__ __half g_wfh[DFF * DD], g_wfl[DFF * DD];
__device__ __half g_wp[DD * DFF];

// ============================================================
// PTX helpers
// ============================================================
__device__ __forceinline__ uint32_t smem_u32(const void* p) {
    uint32_t a;
    asm("{ .reg .u64 t; cvta.to.shared.u64 t, %1; cvt.u32.u64 %0, t; }" : "=r"(a) : "l"(p));
    return a;
}
#define CP_ASYNC16(dst, src) \
    asm volatile("cp.async.cg.shared.global [%0], [%1], 16;" :: "r"(dst), "l"(src))
#define CP_COMMIT() asm volatile("cp.async.commit_group;" ::: "memory")
#define CP_WAIT(n)  asm volatile("cp.async.wait_group %0;" :: "n"(n) : "memory")

__device__ __forceinline__ void ldsm4(uint32_t& r0, uint32_t& r1, uint32_t& r2, uint32_t& r3,
                                      uint32_t a) {
    asm volatile("ldmatrix.sync.aligned.m8n8.x4.shared.b16 {%0,%1,%2,%3}, [%4];"
                 : "=r"(r0), "=r"(r1), "=r"(r2), "=r"(r3) : "r"(a));
}
__device__ __forceinline__ void ldsm4t(uint32_t& r0, uint32_t& r1, uint32_t& r2, uint32_t& r3,
                                       uint32_t a) {
    asm volatile("ldmatrix.sync.aligned.m8n8.x4.trans.shared.b16 {%0,%1,%2,%3}, [%4];"
                 : "=r"(r0), "=r"(r1), "=r"(r2), "=r"(r3) : "r"(a));
}
__device__ __forceinline__ void mma_f16(float* d, const uint32_t* a, const uint32_t* b) {
    asm volatile("mma.sync.aligned.m16n8k16.row.col.f32.f16.f16.f32 "
                 "{%0,%1,%2,%3}, {%4,%5,%6,%7}, {%8,%9}, {%0,%1,%2,%3};"
                 : "+f"(d[0]), "+f"(d[1]), "+f"(d[2]), "+f"(d[3])
                 : "r"(a[0]), "r"(a[1]), "r"(a[2]), "r"(a[3]), "r"(b[0]), "r"(b[1]));
}
__device__ __forceinline__ uint32_t packh2(float lo, float hi) {
    __half2 h = __floats2half2_rn(lo, hi);
    return *reinterpret_cast<uint32_t*>(&h);
}
__device__ __forceinline__ float tanhfast(float x) {
    float e = __expf(2.0f * x);
    return (e - 1.0f) / (e + 1.0f);
}

// ============================================================
// fused prologue: weight cvts + rms_norm(x) + output prefix copy
// block ranges:
//  [0,512) Wq  [512,640) Wk  [640,768) Wv  [768,1280) Wo
//  [1280,3328) Wfc hi/lo  [3328,5376) Wproj  [5376,9472) prefix copy
//  [9472,17792) rms rows
// ============================================================
__global__ __launch_bounds__(256) void prep_k(
    const float* __restrict__ x,
    const float* __restrict__ Wq, const float* __restrict__ Wk,
    const float* __restrict__ Wv, const float* __restrict__ Wo,
    const float* __restrict__ Wfc, const float* __restrict__ Wproj,
    float* __restrict__ out, __half* __restrict__ xnf,
    __half* __restrict__ wq, __half* __restrict__ wk,
    __half* __restrict__ wv, __half* __restrict__ wo,
    __half* __restrict__ wfh, __half* __restrict__ wfl,
    __half* __restrict__ wp)
{
    const int bx = blockIdx.x;
    const int tid = threadIdx.x;
    __shared__ float red[8];

    if (bx < 1280) {                       // single fp16 cvt (Wq/Wk/Wv/Wo)
        const float* src; __half* dst; int base, n4;
        if (bx < 512)      { src = Wq; dst = wq; base = 0;   n4 = 262144; }
        else if (bx < 640) { src = Wk; dst = wk; base = 512; n4 = 65536; }
        else if (bx < 768) { src = Wv; dst = wv; base = 640; n4 = 65536; }
        else               { src = Wo; dst = wo; base = 768; n4 = 262144; }
        int i0 = ((bx - base) * 256 + tid) * 2;
        #pragma unroll
        for (int j = 0; j < 2; j++) {
            int i = i0 + j;
            if (i < n4) {
                float4 v = ((const float4*)src)[i];
                ((__half2*)dst)[2*i]     = __floats2half2_rn(v.x, v.y);
                ((__half2*)dst)[2*i + 1] = __floats2half2_rn(v.z, v.w);
            }
        }
    } else if (bx < 3328) {                // Wfc hi/lo split
        int i0 = ((bx - 1280) * 256 + tid) * 2;
        #pragma unroll
        for (int j = 0; j < 2; j++) {
            int i = i0 + j;
            float4 v = ((const float4*)Wfc)[i];
            float vv[4] = {v.x, v.y, v.z, v.w};
            __half h[4], l[4];
            #pragma unroll
            for (int t = 0; t < 4; t++) {
                h[t] = __float2half_rn(vv[t]);
                l[t] = __float2half_rn(vv[t] - __half2float(h[t]));
            }
            ((__half2*)wfh)[2*i]     = __halves2half2(h[0], h[1]);
            ((__half2*)wfh)[2*i + 1] = __halves2half2(h[2], h[3]);
            ((__half2*)wfl)[2*i]     = __halves2half2(l[0], l[1]);
            ((__half2*)wfl)[2*i + 1] = __halves2half2(l[2], l[3]);
        }
    } else if (bx < 5376) {                // Wproj single cvt
        int i0 = ((bx - 3328) * 256 + tid) * 2;
        #pragma unroll
        for (int j = 0; j < 2; j++) {
            int i = i0 + j;
            float4 v = ((const float4*)Wproj)[i];
            ((__half2*)wp)[2*i]     = __floats2half2_rn(v.x, v.y);
            ((__half2*)wp)[2*i + 1] = __floats2half2_rn(v.z, v.w);
        }
    } else if (bx < 9472) {                // prefix copy: out[b, t<CS] = x
        int i4 = (bx - 5376) * 256 + tid;
        int row = i4 >> 8, col = i4 & 255;
        int b = row >> 11, t = row & 2047;
        size_t g = ((size_t)(b * TT + t) << 8) + col;
        ((float4*)out)[g] = ((const float4*)x)[g];
    } else {                               // rms_norm(x) -> fp16
        const int row = bx - 9472;
        const float4* xr = (const float4*)x + (size_t)row * (DD / 4);
        float4 v = xr[tid];
        float ss = v.x * v.x + v.y * v.y + v.z * v.z + v.w * v.w;
        #pragma unroll
        for (int o = 16; o; o >>= 1) ss += __shfl_xor_sync(0xffffffffu, ss, o);
        if ((tid & 31) == 0) red[tid >> 5] = ss;
        __syncthreads();
        float tot = red[0] + red[1] + red[2] + red[3] + red[4] + red[5] + red[6] + red[7];
        float s = rsqrtf(tot * (1.0f / DD) + 1e-6f);
        size_t base = (size_t)row * (DD / 2) + 2 * tid;
        ((__half2*)xnf)[base]     = __floats2half2_rn(v.x * s, v.y * s);
        ((__half2*)xnf)[base + 1] = __floats2half2_rn(v.z * s, v.w * s);
    }
}

// ============================================================
// RMSNorm fp32 -> fp16 (x_new)
// ============================================================
__global__ __launch_bounds__(256) void rms_k(const float* __restrict__ x,
                                             __half* __restrict__ y)
{
    const int row = blockIdx.x;
    const float4* xr = (const float4*)x + (size_t)row * (DD / 4);
    float4 v = xr[threadIdx.x];
    float ss = v.x * v.x + v.y * v.y + v.z * v.z + v.w * v.w;
    #pragma unroll
    for (int o = 16; o; o >>= 1) ss += __shfl_xor_sync(0xffffffffu, ss, o);
    __shared__ float red[8];
    if ((threadIdx.x & 31) == 0) red[threadIdx.x >> 5] = ss;
    __syncthreads();
    float tot = red[0] + red[1] + red[2] + red[3] + red[4] + red[5] + red[6] + red[7];
    float s = rsqrtf(tot * (1.0f / DD) + 1e-6f);
    size_t base = (size_t)row * (DD / 2) + 2 * threadIdx.x;
    ((__half2*)y)[base]     = __floats2half2_rn(v.x * s, v.y * s);
    ((__half2*)y)[base + 1] = __floats2half2_rn(v.z * s, v.w * s);
}

// ============================================================
// fp16 HMMA GEMM: C[M,N] = A[M,K] * W[N,K]^T, tile 128x128, Kchunk 64.
// PASSES: 1 = A*W; 2 = A*(Wh+Wl)  (hi/lo W split).
// kvsplit (PASSES=1 only): blockIdx.y >= kvsplit uses Wl/HM2/epi5.
// A rows remapped: arow = (r/asl)*ast + aso + r%asl
// epi: 1 softcap + R(gathered) -> fp32 C dense     (Wo)
//      2 relu^2 -> fp16 Ch dense                   (Wfc)
//      3 +R dense -> fp32 C rows gathered          (Wproj -> out)
//      4 l2norm*sc -> fp16 HM head-major           (Q, K)
//      5 fp16 HM head-major                        (V)
// ============================================================
template<int PASSES>
__global__ __launch_bounds__(256, 2)
void gemm_tc(const __half* __restrict__ Ah,
             const __half* __restrict__ Wh, const __half* __restrict__ Wl,
             float* __restrict__ C, __half* __restrict__ Ch,
             __half* __restrict__ HM, __half* __restrict__ HM2,
             const float* __restrict__ R,
             int Nglob, int K,
             int asl, int ast, int aso,
             int rsl, int rst, int rso,
             int SEQ, float sc, int epi, int kvsplit)
{
    extern __shared__ char smem[];
    const uint32_t sb = smem_u32(smem);
    const int tid = threadIdx.x;
    const int wid = tid >> 5;
    const int lane = tid & 31;
    const int bm = blockIdx.x * 128;
    const int nchunks = K >> 6;
    constexpr uint32_t SS = (PASSES == 1) ? 32768u : 49152u;

    const __half* Wuse = Wh;
    __half* HMuse = HM;
    int epiu = epi;
    int bn = blockIdx.y * 128;
    if (PASSES == 1 && kvsplit && (int)blockIdx.y >= kvsplit) {
        Wuse = Wl; HMuse = HM2; epiu = 5;
        bn = (blockIdx.y - kvsplit) * 128;
    }

    auto load_chunk = [&](int p, int c) {
        const int kc = c << 6;
        uint32_t bufb = sb + 1024 + p * SS;
        #pragma unroll
        for (int i = tid; i < 1024; i += 256) {
            int r = i >> 3, seg = i & 7;
            int row = bm + r;
            size_t ar = (size_t)(row / asl) * ast + aso + (row % asl);
            uint32_t off = (r << 7) + (seg << 4);
            uint32_t sw = off ^ ((off >> 3) & 0x70);
            CP_ASYNC16(bufb + sw, Ah + ar * K + kc + seg * 8);
        }
        #pragma unroll
        for (int i = tid; i < 1024; i += 256) {
            int r = i >> 3, seg = i & 7;
            uint32_t off = (r << 7) + (seg << 4);
            uint32_t sw = off ^ ((off >> 3) & 0x70);
            CP_ASYNC16(bufb + 16384 + sw, Wuse + (size_t)(bn + r) * K + kc + seg * 8);
            if (PASSES == 2)
                CP_ASYNC16(bufb + 32768 + sw, Wl + (size_t)(bn + r) * K + kc + seg * 8);
        }
        CP_COMMIT();
    };

    const int warp_m = wid >> 1;
    const int warp_n = wid & 1;

    float acc[2][8][4];
    #pragma unroll
    for (int mf = 0; mf < 2; mf++)
        #pragma unroll
        for (int nf = 0; nf < 8; nf++)
            #pragma unroll
            for (int j = 0; j < 4; j++) acc[mf][nf][j] = 0.f;

    load_chunk(0, 0);

    const int a_row = warp_m * 32 + (lane & 15);
    const uint32_t a_koff = (lane >> 4) << 4;
    const int b_row = warp_n * 64 + ((lane >> 4) << 3) + (lane & 7);
    const uint32_t b_koff = ((lane >> 3) & 1) << 4;

    for (int c = 0; c < nchunks; c++) {
        const int p = c & 1;
        if (c + 1 < nchunks) { load_chunk(1 - p, c + 1); CP_WAIT(1); }
        else                 { CP_WAIT(0); }
        __syncthreads();

        const uint32_t bA  = sb + 1024 + p * SS;
        const uint32_t bW  = bA + 16384;
        const uint32_t bWl = bA + 32768;

        #pragma unroll
        for (int ks = 0; ks < 4; ks++) {
            const uint32_t kb = ks * 32;
            uint32_t ah[2][4];
            #pragma unroll
            for (int mf = 0; mf < 2; mf++) {
                uint32_t off = ((uint32_t)(a_row + mf * 16) << 7) + kb + a_koff;
                off ^= (off >> 3) & 0x70;
                ldsm4(ah[mf][0], ah[mf][1], ah[mf][2], ah[mf][3], bA + off);
            }
            #pragma unroll
            for (int nf2 = 0; nf2 < 4; nf2++) {
                uint32_t off = ((uint32_t)(b_row + nf2 * 16) << 7) + kb + b_koff;
                off ^= (off >> 3) & 0x70;
                uint32_t w0, w1, w2, w3;
                ldsm4(w0, w1, w2, w3, bW + off);
                {
                    uint32_t bb0[2] = {w0, w1}, bb1[2] = {w2, w3};
                    mma_f16(acc[0][2*nf2],   ah[0], bb0);
                    mma_f16(acc[0][2*nf2+1], ah[0], bb1);
                    mma_f16(acc[1][2*nf2],   ah[1], bb0);
                    mma_f16(acc[1][2*nf2+1], ah[1], bb1);
                }
                if (PASSES == 2) {
                    ldsm4(w0, w1, w2, w3, bWl + off);
                    uint32_t bb0[2] = {w0, w1}, bb1[2] = {w2, w3};
                    mma_f16(acc[0][2*nf2],   ah[0], bb0);
                    mma_f16(acc[0][2*nf2+1], ah[0], bb1);
                    mma_f16(acc[1][2*nf2],   ah[1], bb0);
                    mma_f16(acc[1][2*nf2+1], ah[1], bb1);
                }
            }
        }
        __syncthreads();
    }

    // ---- epilogue ----
    const int rq = lane >> 2, cq = (lane & 3) << 1;
    if (epiu >= 4) {
        const int headw = (bn + warp_n * 64) >> 6;
        const int heads = Nglob >> 6;
        #pragma unroll
        for (int mf = 0; mf < 2; mf++) {
            #pragma unroll
            for (int h2 = 0; h2 < 2; h2++) {
                const int rowg = bm + warp_m * 32 + mf * 16 + rq + h2 * 8;
                float s = 1.0f;
                if (epiu == 4) {
                    float ss = 0.f;
                    #pragma unroll
                    for (int nf = 0; nf < 8; nf++) {
                        float x0 = acc[mf][nf][2*h2], x1 = acc[mf][nf][2*h2+1];
                        ss += x0 * x0 + x1 * x1;
                    }
                    ss += __shfl_xor_sync(0xffffffffu, ss, 1);
                    ss += __shfl_xor_sync(0xffffffffu, ss, 2);
                    s = sc / fmaxf(sqrtf(ss), 1e-12f);
                }
                int b = rowg / SEQ, t = rowg - b * SEQ;
                __half* dst = HMuse + (((size_t)(b * heads + headw)) * SEQ + t) * 64;
                #pragma unroll
                for (int nf = 0; nf < 8; nf++) {
                    float x0 = acc[mf][nf][2*h2] * s, x1 = acc[mf][nf][2*h2+1] * s;
                    *(__half2*)(dst + nf * 8 + cq) = __floats2half2_rn(x0, x1);
                }
            }
        }
    } else {
        #pragma unroll
        for (int mf = 0; mf < 2; mf++) {
            #pragma unroll
            for (int h2 = 0; h2 < 2; h2++) {
                const int rowg = bm + warp_m * 32 + mf * 16 + rq + h2 * 8;
                #pragma unroll
                for (int nf = 0; nf < 8; nf++) {
                    float x0 = acc[mf][nf][2*h2], x1 = acc[mf][nf][2*h2+1];
                    const int colg = bn + warp_n * 64 + nf * 8 + cq;
                    if (epiu == 1) {
                        size_t rr = (size_t)(rowg / rsl) * rst + rso + (rowg % rsl);
                        const float* rp = R + rr * Nglob + colg;
                        float2 o;
                        o.x = rp[0] + 15.0f * tanhfast(x0 * (1.0f/15.0f));
                        o.y = rp[1] + 15.0f * tanhfast(x1 * (1.0f/15.0f));
                        *(float2*)(C + (size_t)rowg * Nglob + colg) = o;
                    } else if (epiu == 2) {
                        float a = fmaxf(x0, 0.f); a *= a;
                        float b = fmaxf(x1, 0.f); b *= b;
                        *(__half2*)(Ch + (size_t)rowg * Nglob + colg) = __floats2half2_rn(a, b);
                    } else { // epiu == 3: +R dense, C rows gathered
                        const float* rp = R + (size_t)rowg * Nglob + colg;
                        size_t cr = (size_t)(rowg / rsl) * rst + rso + (rowg % rsl);
                        *(float2*)(C + cr * Nglob + colg) =
                            make_float2(rp[0] + x0, rp[1] + x1);
                    }
                }
            }
        }
    }
}

// ============================================================
// Flash attention via mma.sync fp16 (causal, GQA rep=4).
// 64 q-rows per block, 4 warps x 16 rows. No-max softmax (|s|<=0.125).
// ============================================================
__global__ __launch_bounds__(128) void attn_mma(
    const __half* __restrict__ qbf,
    const __half* __restrict__ kbf,
    const __half* __restrict__ vbf,
    __half* __restrict__ o)
{
    extern __shared__ char sm[];
    const uint32_t sb = smem_u32(sm);
    const int tid = threadIdx.x;
    const int w = tid >> 5, l = tid & 31;
    const int qt = blockIdx.x;
    const int bh = blockIdx.y;
    const int b = bh >> 4, h = bh & 15;
    const int q0 = qt * 64;

    const __half* qg = qbf + ((size_t)bh * NU + q0) * 64;
    const __half* kg = kbf + ((size_t)(b * KVH + (h >> 2)) * TT) * 64;
    const __half* vg = vbf + ((size_t)(b * KVH + (h >> 2)) * TT) * 64;

    for (int i = tid; i < 512; i += 128) {
        int r = i >> 3, seg = i & 7;
        uint32_t off = (r << 7) + (seg << 4);
        uint32_t swo = off ^ ((off >> 3) & 0x70);
        CP_ASYNC16(sb + swo, qg + r * 64 + seg * 8);
    }
    const int n_kt = (CS >> 6) + qt + 1;
    auto load_kv = [&](int p, int c) {
        uint32_t base = sb + 8192 + p * 16384;
        const __half* ks = kg + (size_t)(c << 6) * 64;
        const __half* vs = vg + (size_t)(c << 6) * 64;
        for (int i = tid; i < 512; i += 128) {
            int r = i >> 3, seg = i & 7;
            uint32_t off = (r << 7) + (seg << 4);
            uint32_t swo = off ^ ((off >> 3) & 0x70);
            CP_ASYNC16(base + swo, ks + r * 64 + seg * 8);
            CP_ASYNC16(base + 8192 + swo, vs + r * 64 + seg * 8);
        }
        CP_COMMIT();
    };
    load_kv(0, 0);

    float o_acc[8][4];
    #pragma unroll
    for (int j = 0; j < 8; j++)
        #pragma unroll
        for (int i = 0; i < 4; i++) o_acc[j][i] = 0.f;
    float rsum0 = 0.f, rsum1 = 0.f;

    const int lrow = l & 15;
    const int lhi = l >> 4;
    const int qpos = CS + q0 + w * 16 + (l >> 2);

    for (int c = 0; c < n_kt; c++) {
        const int p = c & 1;
        if (c + 1 < n_kt) { load_kv(1 - p, c + 1); CP_WAIT(1); }
        else              { CP_WAIT(0); }
        __syncthreads();
        const uint32_t kbase = sb + 8192 + p * 16384;
        const uint32_t vbase = kbase + 8192;

        float s[8][4];
        #pragma unroll
        for (int j = 0; j < 8; j++)
            #pragma unroll
            for (int i = 0; i < 4; i++) s[j][i] = 0.f;
        #pragma unroll
        for (int ks = 0; ks < 4; ks++) {
            uint32_t a[4];
            {
                uint32_t off = ((uint32_t)(w * 16 + lrow) << 7) + ks * 32 + (lhi << 4);
                off ^= (off >> 3) & 0x70;
                ldsm4(a[0], a[1], a[2], a[3], sb + off);
            }
            #pragma unroll
            for (int j = 0; j < 8; j += 2) {
                uint32_t off = ((uint32_t)((j + lhi) * 8 + (l & 7)) << 7)
                             + ks * 32 + (((l >> 3) & 1) << 4);
                off ^= (off >> 3) & 0x70;
                uint32_t b0, b1, b2, b3;
                ldsm4(b0, b1, b2, b3, kbase + off);
                uint32_t bb0[2] = {b0, b1}, bb1[2] = {b2, b3};
                mma_f16(s[j],     a, bb0);
                mma_f16(s[j + 1], a, bb1);
            }
        }

        if (c == n_kt - 1) {
            const int k0 = c * 64;
            #pragma unroll
            for (int j = 0; j < 8; j++) {
                int kc = k0 + j * 8 + ((l & 3) << 1);
                if (kc     > qpos)     s[j][0] = -1e30f;
                if (kc + 1 > qpos)     s[j][1] = -1e30f;
                if (kc     > qpos + 8) s[j][2] = -1e30f;
                if (kc + 1 > qpos + 8) s[j][3] = -1e30f;
            }
        }

        #pragma unroll
        for (int j = 0; j < 8; j++) {
            s[j][0] = __expf(s[j][0]);
            s[j][1] = __expf(s[j][1]);
            s[j][2] = __expf(s[j][2]);
            s[j][3] = __expf(s[j][3]);
            rsum0 += s[j][0] + s[j][1];
            rsum1 += s[j][2] + s[j][3];
        }

        #pragma unroll
        for (int ks = 0; ks < 4; ks++) {
            uint32_t a[4];
            a[0] = packh2(s[2*ks][0],   s[2*ks][1]);
            a[1] = packh2(s[2*ks][2],   s[2*ks][3]);
            a[2] = packh2(s[2*ks+1][0], s[2*ks+1][1]);
            a[3] = packh2(s[2*ks+1][2], s[2*ks+1][3]);
            #pragma unroll
            for (int j = 0; j < 8; j += 2) {
                uint32_t off = ((uint32_t)(ks * 16 + lrow) << 7) + ((j + lhi) << 4);
                off ^= (off >> 3) & 0x70;
                uint32_t b0, b1, b2, b3;
                ldsm4t(b0, b1, b2, b3, vbase + off);
                uint32_t bb0[2] = {b0, b1}, bb1[2] = {b2, b3};
                mma_f16(o_acc[j],     a, bb0);
                mma_f16(o_acc[j + 1], a, bb1);
            }
        }
        __syncthreads();
    }

    rsum0 += __shfl_xor_sync(0xffffffffu, rsum0, 1);
    rsum0 += __shfl_xor_sync(0xffffffffu, rsum0, 2);
    rsum1 += __shfl_xor_sync(0xffffffffu, rsum1, 1);
    rsum1 += __shfl_xor_sync(0xffffffffu, rsum1, 2);
    const float inv0 = 1.0f / rsum0, inv1 = 1.0f / rsum1;

    const size_t gr0 = (size_t)(b * NU + q0 + w * 16 + (l >> 2));
    const size_t gr1 = gr0 + 8;
    const int colb = h * 64 + ((l & 3) << 1);
    #pragma unroll
    for (int j = 0; j < 8; j++) {
        const int col = colb + j * 8;
        *(__half2*)(o + gr0 * DD + col) =
            __floats2half2_rn(o_acc[j][0] * inv0, o_acc[j][1] * inv0);
        *(__half2*)(o + gr1 * DD + col) =
            __floats2half2_rn(o_acc[j][2] * inv1, o_acc[j][3] * inv1);
    }
}

// ============================================================
extern "C" void kernel_launch(void* const* d_in, const int* in_sizes, int n_in,
                              void* d_out, int out_size)
{
    const float* x     = (const float*)d_in[0];
    const float* Wq    = (const float*)d_in[1];
    const float* Wk    = (const float*)d_in[2];
    const float* Wv    = (const float*)d_in[3];
    const float* Wo    = (const float*)d_in[4];
    const float* Wfc   = (const float*)d_in[5];
    const float* Wproj = (const float*)d_in[6];
    float* out = (float*)d_out;

    __half *xnf, *qbf, *kbf, *vbf, *af, *x2f, *hf;
    __half *wq, *wk, *wv, *wo, *wfh, *wfl, *wp;
    float *xnew;
    cudaGetSymbolAddress((void**)&xnf, g_xnf);
    cudaGetSymbolAddress((void**)&qbf, g_qbf);
    cudaGetSymbolAddress((void**)&kbf, g_kbf);
    cudaGetSymbolAddress((void**)&vbf, g_vbf);
    cudaGetSymbolAddress((void**)&af,  g_af);
    cudaGetSymbolAddress((void**)&xnew, g_xnew);
    cudaGetSymbolAddress((void**)&x2f, g_x2f);
    cudaGetSymbolAddress((void**)&hf,  g_hf);
    cudaGetSymbolAddress((void**)&wq,  g_wq);
    cudaGetSymbolAddress((void**)&wk,  g_wk);
    cudaGetSymbolAddress((void**)&wv,  g_wv);
    cudaGetSymbolAddress((void**)&wo,  g_wo);
    cudaGetSymbolAddress((void**)&wfh, g_wfh);
    cudaGetSymbolAddress((void**)&wfl, g_wfl);
    cudaGetSymbolAddress((void**)&wp,  g_wp);

    const int SM1 = 1024 + 2 * 32768;   // 66560
    const int SM2 = 1024 + 2 * 49152;   // 99328
    cudaFuncSetAttribute(gemm_tc<1>, cudaFuncAttributeMaxDynamicSharedMemorySize, SM1);
    cudaFuncSetAttribute(gemm_tc<2>, cudaFuncAttributeMaxDynamicSharedMemorySize, SM2);
    cudaFuncSetAttribute(attn_mma, cudaFuncAttributeMaxDynamicSharedMemorySize, 40960);

    // 1. fused prologue: weight cvts + rms(x) + output prefix copy
    prep_k<<<17792, 256>>>(x, Wq, Wk, Wv, Wo, Wfc, Wproj,
                           out, xnf, wq, wk, wv, wo, wfh, wfl, wp);

    // 2. K+V projection (merged launch; y<2 -> K with l2norm, y>=2 -> V)
    gemm_tc<1><<<dim3(MX / 128, 4), 256, SM1>>>(xnf, wk, wv,
        nullptr, nullptr, kbf, vbf, nullptr,
        KVD, DD, MX, MX, 0, 0, 0, 0, TT, 1.0f, 4, 2);
    // 3. Q projection (l2norm * 1/sqrt(HD))
    gemm_tc<1><<<dim3(MQ / 128, DD / 128), 256, SM1>>>(xnf, wq, nullptr,
        nullptr, nullptr, qbf, nullptr, nullptr,
        DD, DD, NU, TT, CS, 0, 0, 0, NU, 0.125f, 4, 0);

    // 4. flash attention
    attn_mma<<<dim3(NU / 64, BB * HH), 128, 40960>>>(qbf, kbf, vbf, af);

    // 5. x_new = x_upd + softcap(attn @ Wo^T)
    gemm_tc<1><<<dim3(MQ / 128, DD / 128), 256, SM1>>>(af, wo, nullptr,
        xnew, nullptr, nullptr, nullptr, x,
        DD, DD, MQ, MQ, 0, NU, TT, CS, 0, 0.f, 1, 0);

    // 6. FFN
    rms_k<<<MQ, 256>>>(xnew, x2f);
    gemm_tc<2><<<dim3(MQ / 128, DFF / 128), 256, SM2>>>(x2f, wfh, wfl,
        nullptr, hf, nullptr, nullptr, nullptr,
        DFF, DD, MQ, MQ, 0, 0, 0, 0, 0, 0.f, 2, 0);
    gemm_tc<1><<<dim3(MQ / 128, DD / 128), 256, SM1>>>(hf, wp, nullptr,
        out, nullptr, nullptr, nullptr, xnew,
        DD, DFF, MQ, MQ, 0, NU, TT, CS, 0, 0.f, 3, 0);
}

// round 8
// speedup vs baseline: 8.8533x; 1.1508x over previous
#include <cuda_runtime.h>
#include <cuda_fp16.h>
#include <stdint.h>
#include <math.h>

// ---- fixed problem shape (HBlock_18597208391748) ----
#define BB   2
#define TT   4160
#define DD   1024
#define HH   16
#define KVH  4
#define HD   64
#define CS   2048
#define NU   (TT - CS)        // 2112
#define KVD  (KVH * HD)       // 256
#define DFF  (4 * DD)         // 4096
#define MQ   (BB * NU)        // 4224
#define MX   (BB * TT)        // 8320

// ---- scratch (device globals; no allocation allowed) ----
__device__ __half g_xnf[(size_t)MX * DD];          // rms_norm(x) fp16
__device__ __half g_qbf[(size_t)MQ * DD];          // [b*16+h][NU][64]
__device__ __half g_kbf[(size_t)MX * KVD];         // [b*4+kvh][TT][64]
__device__ __half g_vbf[(size_t)MX * KVD];
__device__ __half g_af [(size_t)MQ * DD];          // attention out fp16
__device__ float  g_xnew[(size_t)MQ * DD];         // x_new fp32
__device__ __half g_x2f[(size_t)MQ * DD];          // rms(x_new) fp16
__device__ __half g_hf [(size_t)MQ * DFF];         // relu^2 out fp16
// weights fp16 (all single-precision fp16)
__device__ __half g_wq[DD * DD];
__device__ __half g_wk[KVD * DD];
__device__ __half g_wv[KVD * DD];
__device__ __half g_wo[DD * DD];
__device__ __half g_wf[DFF * DD];
__device__ __half g_wp[DD * DFF];

// ============================================================
// PTX helpers
// ============================================================
__device__ __forceinline__ uint32_t smem_u32(const void* p) {
    uint32_t a;
    asm("{ .reg .u64 t; cvta.to.shared.u64 t, %1; cvt.u32.u64 %0, t; }" : "=r"(a) : "l"(p));
    return a;
}
#define CP_ASYNC16(dst, src) \
    asm volatile("cp.async.cg.shared.global [%0], [%1], 16;" :: "r"(dst), "l"(src))
#define CP_COMMIT() asm volatile("cp.async.commit_group;" ::: "memory")
#define CP_WAIT(n)  asm volatile("cp.async.wait_group %0;" :: "n"(n) : "memory")

__device__ __forceinline__ void ldsm4(uint32_t& r0, uint32_t& r1, uint32_t& r2, uint32_t& r3,
                                      uint32_t a) {
    asm volatile("ldmatrix.sync.aligned.m8n8.x4.shared.b16 {%0,%1,%2,%3}, [%4];"
                 : "=r"(r0), "=r"(r1), "=r"(r2), "=r"(r3) : "r"(a));
}
__device__ __forceinline__ void ldsm4t(uint32_t& r0, uint32_t& r1, uint32_t& r2, uint32_t& r3,
                                       uint32_t a) {
    asm volatile("ldmatrix.sync.aligned.m8n8.x4.trans.shared.b16 {%0,%1,%2,%3}, [%4];"
                 : "=r"(r0), "=r"(r1), "=r"(r2), "=r"(r3) : "r"(a));
}
__device__ __forceinline__ void mma_f16(float* d, const uint32_t* a, const uint32_t* b) {
    asm volatile("mma.sync.aligned.m16n8k16.row.col.f32.f16.f16.f32 "
                 "{%0,%1,%2,%3}, {%4,%5,%6,%7}, {%8,%9}, {%0,%1,%2,%3};"
                 : "+f"(d[0]), "+f"(d[1]), "+f"(d[2]), "+f"(d[3])
                 : "r"(a[0]), "r"(a[1]), "r"(a[2]), "r"(a[3]), "r"(b[0]), "r"(b[1]));
}
__device__ __forceinline__ uint32_t packh2(float lo, float hi) {
    __half2 h = __floats2half2_rn(lo, hi);
    return *reinterpret_cast<uint32_t*>(&h);
}
__device__ __forceinline__ float tanhfast(float x) {
    float e = __expf(2.0f * x);
    return (e - 1.0f) / (e + 1.0f);
}

// ============================================================
// fused prologue: weight cvts + rms_norm(x) + output prefix copy
// block ranges:
//  [0,512) Wq  [512,640) Wk  [640,768) Wv  [768,1280) Wo
//  [1280,3328) Wfc  [3328,5376) Wproj  [5376,9472) prefix copy
//  [9472,17792) rms rows
// ============================================================
__global__ __launch_bounds__(256) void prep_k(
    const float* __restrict__ x,
    const float* __restrict__ Wq, const float* __restrict__ Wk,
    const float* __restrict__ Wv, const float* __restrict__ Wo,
    const float* __restrict__ Wfc, const float* __restrict__ Wproj,
    float* __restrict__ out, __half* __restrict__ xnf,
    __half* __restrict__ wq, __half* __restrict__ wk,
    __half* __restrict__ wv, __half* __restrict__ wo,
    __half* __restrict__ wf, __half* __restrict__ wp)
{
    const int bx = blockIdx.x;
    const int tid = threadIdx.x;
    __shared__ float red[8];

    if (bx < 5376) {                       // fp16 weight conversions
        const float* src; __half* dst; int base, n4;
        if (bx < 512)       { src = Wq;    dst = wq; base = 0;    n4 = 262144; }
        else if (bx < 640)  { src = Wk;    dst = wk; base = 512;  n4 = 65536; }
        else if (bx < 768)  { src = Wv;    dst = wv; base = 640;  n4 = 65536; }
        else if (bx < 1280) { src = Wo;    dst = wo; base = 768;  n4 = 262144; }
        else if (bx < 3328) { src = Wfc;   dst = wf; base = 1280; n4 = 1048576; }
        else                { src = Wproj; dst = wp; base = 3328; n4 = 1048576; }
        int i0 = ((bx - base) * 256 + tid) * 2;
        #pragma unroll
        for (int j = 0; j < 2; j++) {
            int i = i0 + j;
            if (i < n4) {
                float4 v = ((const float4*)src)[i];
                ((__half2*)dst)[2*i]     = __floats2half2_rn(v.x, v.y);
                ((__half2*)dst)[2*i + 1] = __floats2half2_rn(v.z, v.w);
            }
        }
    } else if (bx < 9472) {                // prefix copy: out[b, t<CS] = x
        int i4 = (bx - 5376) * 256 + tid;
        int row = i4 >> 8, col = i4 & 255;
        int b = row >> 11, t = row & 2047;
        size_t g = ((size_t)(b * TT + t) << 8) + col;
        ((float4*)out)[g] = ((const float4*)x)[g];
    } else {                               // rms_norm(x) -> fp16
        const int row = bx - 9472;
        const float4* xr = (const float4*)x + (size_t)row * (DD / 4);
        float4 v = xr[tid];
        float ss = v.x * v.x + v.y * v.y + v.z * v.z + v.w * v.w;
        #pragma unroll
        for (int o = 16; o; o >>= 1) ss += __shfl_xor_sync(0xffffffffu, ss, o);
        if ((tid & 31) == 0) red[tid >> 5] = ss;
        __syncthreads();
        float tot = red[0] + red[1] + red[2] + red[3] + red[4] + red[5] + red[6] + red[7];
        float s = rsqrtf(tot * (1.0f / DD) + 1e-6f);
        size_t base = (size_t)row * (DD / 2) + 2 * tid;
        ((__half2*)xnf)[base]     = __floats2half2_rn(v.x * s, v.y * s);
        ((__half2*)xnf)[base + 1] = __floats2half2_rn(v.z * s, v.w * s);
    }
}

// ============================================================
// RMSNorm fp32 -> fp16 (x_new)
// ============================================================
__global__ __launch_bounds__(256) void rms_k(const float* __restrict__ x,
                                             __half* __restrict__ y)
{
    const int row = blockIdx.x;
    const float4* xr = (const float4*)x + (size_t)row * (DD / 4);
    float4 v = xr[threadIdx.x];
    float ss = v.x * v.x + v.y * v.y + v.z * v.z + v.w * v.w;
    #pragma unroll
    for (int o = 16; o; o >>= 1) ss += __shfl_xor_sync(0xffffffffu, ss, o);
    __shared__ float red[8];
    if ((threadIdx.x & 31) == 0) red[threadIdx.x >> 5] = ss;
    __syncthreads();
    float tot = red[0] + red[1] + red[2] + red[3] + red[4] + red[5] + red[6] + red[7];
    float s = rsqrtf(tot * (1.0f / DD) + 1e-6f);
    size_t base = (size_t)row * (DD / 2) + 2 * threadIdx.x;
    ((__half2*)y)[base]     = __floats2half2_rn(v.x * s, v.y * s);
    ((__half2*)y)[base + 1] = __floats2half2_rn(v.z * s, v.w * s);
}

// ============================================================
// fp16 HMMA GEMM: C[M,N] = A[M,K] * W[N,K]^T, tile 128x128, Kchunk 64.
// kvsplit: blockIdx.y >= kvsplit uses Wl/HM2/epi5 (merged K+V launch).
// A rows remapped: arow = (r/asl)*ast + aso + r%asl
// epi: 1 softcap + R(gathered) -> fp32 C dense     (Wo)
//      2 relu^2 -> fp16 Ch dense                   (Wfc)
//      3 +R dense -> fp32 C rows gathered          (Wproj -> out)
//      4 l2norm*sc -> fp16 HM head-major           (Q, K)
//      5 fp16 HM head-major                        (V)
// ============================================================
__global__ __launch_bounds__(256, 2)
void gemm_tc(const __half* __restrict__ Ah,
             const __half* __restrict__ Wh, const __half* __restrict__ Wl,
             float* __restrict__ C, __half* __restrict__ Ch,
             __half* __restrict__ HM, __half* __restrict__ HM2,
             const float* __restrict__ R,
             int Nglob, int K,
             int asl, int ast, int aso,
             int rsl, int rst, int rso,
             int SEQ, float sc, int epi, int kvsplit)
{
    extern __shared__ char smem[];
    const uint32_t sb = smem_u32(smem);
    const int tid = threadIdx.x;
    const int wid = tid >> 5;
    const int lane = tid & 31;
    const int bm = blockIdx.x * 128;
    const int nchunks = K >> 6;
    const uint32_t SS = 32768u;

    const __half* Wuse = Wh;
    __half* HMuse = HM;
    int epiu = epi;
    int bn = blockIdx.y * 128;
    if (kvsplit && (int)blockIdx.y >= kvsplit) {
        Wuse = Wl; HMuse = HM2; epiu = 5;
        bn = (blockIdx.y - kvsplit) * 128;
    }

    auto load_chunk = [&](int p, int c) {
        const int kc = c << 6;
        uint32_t bufb = sb + 1024 + p * SS;
        #pragma unroll
        for (int i = tid; i < 1024; i += 256) {
            int r = i >> 3, seg = i & 7;
            int row = bm + r;
            size_t ar = (size_t)(row / asl) * ast + aso + (row % asl);
            uint32_t off = (r << 7) + (seg << 4);
            uint32_t sw = off ^ ((off >> 3) & 0x70);
            CP_ASYNC16(bufb + sw, Ah + ar * K + kc + seg * 8);
        }
        #pragma unroll
        for (int i = tid; i < 1024; i += 256) {
            int r = i >> 3, seg = i & 7;
            uint32_t off = (r << 7) + (seg << 4);
            uint32_t sw = off ^ ((off >> 3) & 0x70);
            CP_ASYNC16(bufb + 16384 + sw, Wuse + (size_t)(bn + r) * K + kc + seg * 8);
        }
        CP_COMMIT();
    };

    const int warp_m = wid >> 1;
    const int warp_n = wid & 1;

    float acc[2][8][4];
    #pragma unroll
    for (int mf = 0; mf < 2; mf++)
        #pragma unroll
        for (int nf = 0; nf < 8; nf++)
            #pragma unroll
            for (int j = 0; j < 4; j++) acc[mf][nf][j] = 0.f;

    load_chunk(0, 0);

    const int a_row = warp_m * 32 + (lane & 15);
    const uint32_t a_koff = (lane >> 4) << 4;
    const int b_row = warp_n * 64 + ((lane >> 4) << 3) + (lane & 7);
    const uint32_t b_koff = ((lane >> 3) & 1) << 4;

    for (int c = 0; c < nchunks; c++) {
        const int p = c & 1;
        if (c + 1 < nchunks) { load_chunk(1 - p, c + 1); CP_WAIT(1); }
        else                 { CP_WAIT(0); }
        __syncthreads();

        const uint32_t bA = sb + 1024 + p * SS;
        const uint32_t bW = bA + 16384;

        #pragma unroll
        for (int ks = 0; ks < 4; ks++) {
            const uint32_t kb = ks * 32;
            uint32_t ah[2][4];
            #pragma unroll
            for (int mf = 0; mf < 2; mf++) {
                uint32_t off = ((uint32_t)(a_row + mf * 16) << 7) + kb + a_koff;
                off ^= (off >> 3) & 0x70;
                ldsm4(ah[mf][0], ah[mf][1], ah[mf][2], ah[mf][3], bA + off);
            }
            #pragma unroll
            for (int nf2 = 0; nf2 < 4; nf2++) {
                uint32_t off = ((uint32_t)(b_row + nf2 * 16) << 7) + kb + b_koff;
                off ^= (off >> 3) & 0x70;
                uint32_t w0, w1, w2, w3;
                ldsm4(w0, w1, w2, w3, bW + off);
                uint32_t bb0[2] = {w0, w1}, bb1[2] = {w2, w3};
                mma_f16(acc[0][2*nf2],   ah[0], bb0);
                mma_f16(acc[0][2*nf2+1], ah[0], bb1);
                mma_f16(acc[1][2*nf2],   ah[1], bb0);
                mma_f16(acc[1][2*nf2+1], ah[1], bb1);
            }
        }
        __syncthreads();
    }

    // ---- epilogue ----
    const int rq = lane >> 2, cq = (lane & 3) << 1;
    if (epiu >= 4) {
        const int headw = (bn + warp_n * 64) >> 6;
        const int heads = Nglob >> 6;
        #pragma unroll
        for (int mf = 0; mf < 2; mf++) {
            #pragma unroll
            for (int h2 = 0; h2 < 2; h2++) {
                const int rowg = bm + warp_m * 32 + mf * 16 + rq + h2 * 8;
                float s = 1.0f;
                if (epiu == 4) {
                    float ss = 0.f;
                    #pragma unroll
                    for (int nf = 0; nf < 8; nf++) {
                        float x0 = acc[mf][nf][2*h2], x1 = acc[mf][nf][2*h2+1];
                        ss += x0 * x0 + x1 * x1;
                    }
                    ss += __shfl_xor_sync(0xffffffffu, ss, 1);
                    ss += __shfl_xor_sync(0xffffffffu, ss, 2);
                    s = sc / fmaxf(sqrtf(ss), 1e-12f);
                }
                int b = rowg / SEQ, t = rowg - b * SEQ;
                __half* dst = HMuse + (((size_t)(b * heads + headw)) * SEQ + t) * 64;
                #pragma unroll
                for (int nf = 0; nf < 8; nf++) {
                    float x0 = acc[mf][nf][2*h2] * s, x1 = acc[mf][nf][2*h2+1] * s;
                    *(__half2*)(dst + nf * 8 + cq) = __floats2half2_rn(x0, x1);
                }
            }
        }
    } else {
        #pragma unroll
        for (int mf = 0; mf < 2; mf++) {
            #pragma unroll
            for (int h2 = 0; h2 < 2; h2++) {
                const int rowg = bm + warp_m * 32 + mf * 16 + rq + h2 * 8;
                #pragma unroll
                for (int nf = 0; nf < 8; nf++) {
                    float x0 = acc[mf][nf][2*h2], x1 = acc[mf][nf][2*h2+1];
                    const int colg = bn + warp_n * 64 + nf * 8 + cq;
                    if (epiu == 1) {
                        size_t rr = (size_t)(rowg / rsl) * rst + rso + (rowg % rsl);
                        const float* rp = R + rr * Nglob + colg;
                        float2 o;
                        o.x = rp[0] + 15.0f * tanhfast(x0 * (1.0f/15.0f));
                        o.y = rp[1] + 15.0f * tanhfast(x1 * (1.0f/15.0f));
                        *(float2*)(C + (size_t)rowg * Nglob + colg) = o;
                    } else if (epiu == 2) {
                        float a = fmaxf(x0, 0.f); a *= a;
                        float b = fmaxf(x1, 0.f); b *= b;
                        *(__half2*)(Ch + (size_t)rowg * Nglob + colg) = __floats2half2_rn(a, b);
                    } else { // epiu == 3: +R dense, C rows gathered
                        const float* rp = R + (size_t)rowg * Nglob + colg;
                        size_t cr = (size_t)(rowg / rsl) * rst + rso + (rowg % rsl);
                        *(float2*)(C + cr * Nglob + colg) =
                            make_float2(rp[0] + x0, rp[1] + x1);
                    }
                }
            }
        }
    }
}

// ============================================================
// Flash attention via mma.sync fp16 (causal, GQA rep=4).
// 64 q-rows per block, 4 warps x 16 rows. No-max softmax (|s|<=0.125).
// q is pre-scaled by 0.125*log2(e) -> P = exp2(S).
// qt is REVERSED (longest blocks first) for wave balance.
// ============================================================
__global__ __launch_bounds__(128) void attn_mma(
    const __half* __restrict__ qbf,
    const __half* __restrict__ kbf,
    const __half* __restrict__ vbf,
    __half* __restrict__ o)
{
    extern __shared__ char sm[];
    const uint32_t sb = smem_u32(sm);
    const int tid = threadIdx.x;
    const int w = tid >> 5, l = tid & 31;
    const int qt = (int)gridDim.x - 1 - (int)blockIdx.x;   // longest first
    const int bh = blockIdx.y;
    const int b = bh >> 4, h = bh & 15;
    const int q0 = qt * 64;

    const __half* qg = qbf + ((size_t)bh * NU + q0) * 64;
    const __half* kg = kbf + ((size_t)(b * KVH + (h >> 2)) * TT) * 64;
    const __half* vg = vbf + ((size_t)(b * KVH + (h >> 2)) * TT) * 64;

    for (int i = tid; i < 512; i += 128) {
        int r = i >> 3, seg = i & 7;
        uint32_t off = (r << 7) + (seg << 4);
        uint32_t swo = off ^ ((off >> 3) & 0x70);
        CP_ASYNC16(sb + swo, qg + r * 64 + seg * 8);
    }
    const int n_kt = (CS >> 6) + qt + 1;
    auto load_kv = [&](int p, int c) {
        uint32_t base = sb + 8192 + p * 16384;
        const __half* ks = kg + (size_t)(c << 6) * 64;
        const __half* vs = vg + (size_t)(c << 6) * 64;
        for (int i = tid; i < 512; i += 128) {
            int r = i >> 3, seg = i & 7;
            uint32_t off = (r << 7) + (seg << 4);
            uint32_t swo = off ^ ((off >> 3) & 0x70);
            CP_ASYNC16(base + swo, ks + r * 64 + seg * 8);
            CP_ASYNC16(base + 8192 + swo, vs + r * 64 + seg * 8);
        }
        CP_COMMIT();
    };
    load_kv(0, 0);

    float o_acc[8][4];
    #pragma unroll
    for (int j = 0; j < 8; j++)
        #pragma unroll
        for (int i = 0; i < 4; i++) o_acc[j][i] = 0.f;
    float rsum0 = 0.f, rsum1 = 0.f;

    const int lrow = l & 15;
    const int lhi = l >> 4;
    const int qpos = CS + q0 + w * 16 + (l >> 2);

    for (int c = 0; c < n_kt; c++) {
        const int p = c & 1;
        if (c + 1 < n_kt) { load_kv(1 - p, c + 1); CP_WAIT(1); }
        else              { CP_WAIT(0); }
        __syncthreads();
        const uint32_t kbase = sb + 8192 + p * 16384;
        const uint32_t vbase = kbase + 8192;

        float s[8][4];
        #pragma unroll
        for (int j = 0; j < 8; j++)
            #pragma unroll
            for (int i = 0; i < 4; i++) s[j][i] = 0.f;
        #pragma unroll
        for (int ks = 0; ks < 4; ks++) {
            uint32_t a[4];
            {
                uint32_t off = ((uint32_t)(w * 16 + lrow) << 7) + ks * 32 + (lhi << 4);
                off ^= (off >> 3) & 0x70;
                ldsm4(a[0], a[1], a[2], a[3], sb + off);
            }
            #pragma unroll
            for (int j = 0; j < 8; j += 2) {
                uint32_t off = ((uint32_t)((j + lhi) * 8 + (l & 7)) << 7)
                             + ks * 32 + (((l >> 3) & 1) << 4);
                off ^= (off >> 3) & 0x70;
                uint32_t b0, b1, b2, b3;
                ldsm4(b0, b1, b2, b3, kbase + off);
                uint32_t bb0[2] = {b0, b1}, bb1[2] = {b2, b3};
                mma_f16(s[j],     a, bb0);
                mma_f16(s[j + 1], a, bb1);
            }
        }

        if (c == n_kt - 1) {
            const int k0 = c * 64;
            #pragma unroll
            for (int j = 0; j < 8; j++) {
                int kc = k0 + j * 8 + ((l & 3) << 1);
                if (kc     > qpos)     s[j][0] = -1e30f;
                if (kc + 1 > qpos)     s[j][1] = -1e30f;
                if (kc     > qpos + 8) s[j][2] = -1e30f;
                if (kc + 1 > qpos + 8) s[j][3] = -1e30f;
            }
        }

        // P = exp2(S)  (log2(e) folded into q scale; |S| <= 0.18)
        #pragma unroll
        for (int j = 0; j < 8; j++) {
            s[j][0] = exp2f(s[j][0]);
            s[j][1] = exp2f(s[j][1]);
            s[j][2] = exp2f(s[j][2]);
            s[j][3] = exp2f(s[j][3]);
            rsum0 += s[j][0] + s[j][1];
            rsum1 += s[j][2] + s[j][3];
        }

        #pragma unroll
        for (int ks = 0; ks < 4; ks++) {
            uint32_t a[4];
            a[0] = packh2(s[2*ks][0],   s[2*ks][1]);
            a[1] = packh2(s[2*ks][2],   s[2*ks][3]);
            a[2] = packh2(s[2*ks+1][0], s[2*ks+1][1]);
            a[3] = packh2(s[2*ks+1][2], s[2*ks+1][3]);
            #pragma unroll
            for (int j = 0; j < 8; j += 2) {
                uint32_t off = ((uint32_t)(ks * 16 + lrow) << 7) + ((j + lhi) << 4);
                off ^= (off >> 3) & 0x70;
                uint32_t b0, b1, b2, b3;
                ldsm4t(b0, b1, b2, b3, vbase + off);
                uint32_t bb0[2] = {b0, b1}, bb1[2] = {b2, b3};
                mma_f16(o_acc[j],     a, bb0);
                mma_f16(o_acc[j + 1], a, bb1);
            }
        }
        __syncthreads();
    }

    rsum0 += __shfl_xor_sync(0xffffffffu, rsum0, 1);
    rsum0 += __shfl_xor_sync(0xffffffffu, rsum0, 2);
    rsum1 += __shfl_xor_sync(0xffffffffu, rsum1, 1);
    rsum1 += __shfl_xor_sync(0xffffffffu, rsum1, 2);
    const float inv0 = 1.0f / rsum0, inv1 = 1.0f / rsum1;

    const size_t gr0 = (size_t)(b * NU + q0 + w * 16 + (l >> 2));
    const size_t gr1 = gr0 + 8;
    const int colb = h * 64 + ((l & 3) << 1);
    #pragma unroll
    for (int j = 0; j < 8; j++) {
        const int col = colb + j * 8;
        *(__half2*)(o + gr0 * DD + col) =
            __floats2half2_rn(o_acc[j][0] * inv0, o_acc[j][1] * inv0);
        *(__half2*)(o + gr1 * DD + col) =
            __floats2half2_rn(o_acc[j][2] * inv1, o_acc[j][3] * inv1);
    }
}

// ============================================================
extern "C" void kernel_launch(void* const* d_in, const int* in_sizes, int n_in,
                              void* d_out, int out_size)
{
    const float* x     = (const float*)d_in[0];
    const float* Wq    = (const float*)d_in[1];
    const float* Wk    = (const float*)d_in[2];
    const float* Wv    = (const float*)d_in[3];
    const float* Wo    = (const float*)d_in[4];
    const float* Wfc   = (const float*)d_in[5];
    const float* Wproj = (const float*)d_in[6];
    float* out = (float*)d_out;

    __half *xnf, *qbf, *kbf, *vbf, *af, *x2f, *hf;
    __half *wq, *wk, *wv, *wo, *wf, *wp;
    float *xnew;
    cudaGetSymbolAddress((void**)&xnf, g_xnf);
    cudaGetSymbolAddress((void**)&qbf, g_qbf);
    cudaGetSymbolAddress((void**)&kbf, g_kbf);
    cudaGetSymbolAddress((void**)&vbf, g_vbf);
    cudaGetSymbolAddress((void**)&af,  g_af);
    cudaGetSymbolAddress((void**)&xnew, g_xnew);
    cudaGetSymbolAddress((void**)&x2f, g_x2f);
    cudaGetSymbolAddress((void**)&hf,  g_hf);
    cudaGetSymbolAddress((void**)&wq,  g_wq);
    cudaGetSymbolAddress((void**)&wk,  g_wk);
    cudaGetSymbolAddress((void**)&wv,  g_wv);
    cudaGetSymbolAddress((void**)&wo,  g_wo);
    cudaGetSymbolAddress((void**)&wf,  g_wf);
    cudaGetSymbolAddress((void**)&wp,  g_wp);

    const int SM1 = 1024 + 2 * 32768;   // 66560
    cudaFuncSetAttribute(gemm_tc, cudaFuncAttributeMaxDynamicSharedMemorySize, SM1);
    cudaFuncSetAttribute(attn_mma, cudaFuncAttributeMaxDynamicSharedMemorySize, 40960);

    // 1. fused prologue: weight cvts + rms(x) + output prefix copy
    prep_k<<<17792, 256>>>(x, Wq, Wk, Wv, Wo, Wfc, Wproj,
                           out, xnf, wq, wk, wv, wo, wf, wp);

    // 2. K+V projection (merged; y<2 -> K with l2norm, y>=2 -> V)
    gemm_tc<<<dim3(MX / 128, 4), 256, SM1>>>(xnf, wk, wv,
        nullptr, nullptr, kbf, vbf, nullptr,
        KVD, DD, MX, MX, 0, 0, 0, 0, TT, 1.0f, 4, 2);
    // 3. Q projection (l2norm * 0.125 * log2(e) for exp2 softmax)
    gemm_tc<<<dim3(MQ / 128, DD / 128), 256, SM1>>>(xnf, wq, nullptr,
        nullptr, nullptr, qbf, nullptr, nullptr,
        DD, DD, NU, TT, CS, 0, 0, 0, NU, 0.125f * 1.44269504f, 4, 0);

    // 4. flash attention
    attn_mma<<<dim3(NU / 64, BB * HH), 128, 40960>>>(qbf, kbf, vbf, af);

    // 5. x_new = x_upd + softcap(attn @ Wo^T)
    gemm_tc<<<dim3(MQ / 128, DD / 128), 256, SM1>>>(af, wo, nullptr,
        xnew, nullptr, nullptr, nullptr, x,
        DD, DD, MQ, MQ, 0, NU, TT, CS, 0, 0.f, 1, 0);

    // 6. FFN
    rms_k<<<MQ, 256>>>(xnew, x2f);
    gemm_tc<<<dim3(MQ / 128, DFF / 128), 256, SM1>>>(x2f, wf, nullptr,
        nullptr, hf, nullptr, nullptr, nullptr,
        DFF, DD, MQ, MQ, 0, 0, 0, 0, 0, 0.f, 2, 0);
    gemm_tc<<<dim3(MQ / 128, DD / 128), 256, SM1>>>(hf, wp, nullptr,
        out, nullptr, nullptr, nullptr, xnew,
        DD, DFF, MQ, MQ, 0, NU, TT, CS, 0, 0.f, 3, 0);
}

// round 9
// speedup vs baseline: 8.9592x; 1.0120x over previous
#include <cuda_runtime.h>
#include <cuda_fp16.h>
#include <stdint.h>
#include <math.h>

// ---- fixed problem shape (HBlock_18597208391748) ----
#define BB   2
#define TT   4160
#define DD   1024
#define HH   16
#define KVH  4
#define HD   64
#define CS   2048
#define NU   (TT - CS)        // 2112
#define KVD  (KVH * HD)       // 256
#define DFF  (4 * DD)         // 4096
#define MQ   (BB * NU)        // 4224
#define MX   (BB * TT)        // 8320

// ---- scratch (device globals; no allocation allowed) ----
__device__ __half g_xnf[(size_t)MX * DD];          // rms_norm(x) fp16
__device__ __half g_qbf[(size_t)MQ * DD];          // [b*16+h][NU][64]
__device__ __half g_kbf[(size_t)MX * KVD];         // [b*4+kvh][TT][64]
__device__ __half g_vbf[(size_t)MX * KVD];
__device__ __half g_af [(size_t)MQ * DD];          // attention out fp16
__device__ float  g_xnew[(size_t)MQ * DD];         // x_new fp32
__device__ __half g_x2f[(size_t)MQ * DD];          // rms(x_new) fp16
__device__ __half g_hf [(size_t)MQ * DFF];         // relu^2 out fp16
__device__ __half g_wq[DD * DD];
__device__ __half g_wk[KVD * DD];
__device__ __half g_wv[KVD * DD];
__device__ __half g_wo[DD * DD];
__device__ __half g_wf[DFF * DD];
__device__ __half g_wp[DD * DFF];

// ============================================================
// PTX helpers
// ============================================================
__device__ __forceinline__ uint32_t smem_u32(const void* p) {
    uint32_t a;
    asm("{ .reg .u64 t; cvta.to.shared.u64 t, %1; cvt.u32.u64 %0, t; }" : "=r"(a) : "l"(p));
    return a;
}
#define CP_ASYNC16(dst, src) \
    asm volatile("cp.async.cg.shared.global [%0], [%1], 16;" :: "r"(dst), "l"(src))
#define CP_COMMIT() asm volatile("cp.async.commit_group;" ::: "memory")
#define CP_WAIT(n)  asm volatile("cp.async.wait_group %0;" :: "n"(n) : "memory")

__device__ __forceinline__ void ldsm4(uint32_t& r0, uint32_t& r1, uint32_t& r2, uint32_t& r3,
                                      uint32_t a) {
    asm volatile("ldmatrix.sync.aligned.m8n8.x4.shared.b16 {%0,%1,%2,%3}, [%4];"
                 : "=r"(r0), "=r"(r1), "=r"(r2), "=r"(r3) : "r"(a));
}
__device__ __forceinline__ void ldsm4t(uint32_t& r0, uint32_t& r1, uint32_t& r2, uint32_t& r3,
                                       uint32_t a) {
    asm volatile("ldmatrix.sync.aligned.m8n8.x4.trans.shared.b16 {%0,%1,%2,%3}, [%4];"
                 : "=r"(r0), "=r"(r1), "=r"(r2), "=r"(r3) : "r"(a));
}
__device__ __forceinline__ void mma_f16(float* d, const uint32_t* a, const uint32_t* b) {
    asm volatile("mma.sync.aligned.m16n8k16.row.col.f32.f16.f16.f32 "
                 "{%0,%1,%2,%3}, {%4,%5,%6,%7}, {%8,%9}, {%0,%1,%2,%3};"
                 : "+f"(d[0]), "+f"(d[1]), "+f"(d[2]), "+f"(d[3])
                 : "r"(a[0]), "r"(a[1]), "r"(a[2]), "r"(a[3]), "r"(b[0]), "r"(b[1]));
}
// fp16-accumulator HMMA (2x rate)
__device__ __forceinline__ void mma_f16h(uint32_t* d, const uint32_t* a, const uint32_t* b) {
    asm volatile("mma.sync.aligned.m16n8k16.row.col.f16.f16.f16.f16 "
                 "{%0,%1}, {%2,%3,%4,%5}, {%6,%7}, {%0,%1};"
                 : "+r"(d[0]), "+r"(d[1])
                 : "r"(a[0]), "r"(a[1]), "r"(a[2]), "r"(a[3]), "r"(b[0]), "r"(b[1]));
}
__device__ __forceinline__ uint32_t packh2(float lo, float hi) {
    __half2 h = __floats2half2_rn(lo, hi);
    return *reinterpret_cast<uint32_t*>(&h);
}
__device__ __forceinline__ __half2 u2h(uint32_t u) {
    return *reinterpret_cast<__half2*>(&u);
}
__device__ __forceinline__ uint32_t h2u(__half2 h) {
    return *reinterpret_cast<uint32_t*>(&h);
}
__device__ __forceinline__ float tanhfast(float x) {
    float e = __expf(2.0f * x);
    return (e - 1.0f) / (e + 1.0f);
}

// ============================================================
// fused prologue: weight cvts + rms_norm(x) + output prefix copy
// ============================================================
__global__ __launch_bounds__(256) void prep_k(
    const float* __restrict__ x,
    const float* __restrict__ Wq, const float* __restrict__ Wk,
    const float* __restrict__ Wv, const float* __restrict__ Wo,
    const float* __restrict__ Wfc, const float* __restrict__ Wproj,
    float* __restrict__ out, __half* __restrict__ xnf,
    __half* __restrict__ wq, __half* __restrict__ wk,
    __half* __restrict__ wv, __half* __restrict__ wo,
    __half* __restrict__ wf, __half* __restrict__ wp)
{
    const int bx = blockIdx.x;
    const int tid = threadIdx.x;
    __shared__ float red[8];

    if (bx < 5376) {                       // fp16 weight conversions
        const float* src; __half* dst; int base, n4;
        if (bx < 512)       { src = Wq;    dst = wq; base = 0;    n4 = 262144; }
        else if (bx < 640)  { src = Wk;    dst = wk; base = 512;  n4 = 65536; }
        else if (bx < 768)  { src = Wv;    dst = wv; base = 640;  n4 = 65536; }
        else if (bx < 1280) { src = Wo;    dst = wo; base = 768;  n4 = 262144; }
        else if (bx < 3328) { src = Wfc;   dst = wf; base = 1280; n4 = 1048576; }
        else                { src = Wproj; dst = wp; base = 3328; n4 = 1048576; }
        int i0 = ((bx - base) * 256 + tid) * 2;
        #pragma unroll
        for (int j = 0; j < 2; j++) {
            int i = i0 + j;
            if (i < n4) {
                float4 v = ((const float4*)src)[i];
                ((__half2*)dst)[2*i]     = __floats2half2_rn(v.x, v.y);
                ((__half2*)dst)[2*i + 1] = __floats2half2_rn(v.z, v.w);
            }
        }
    } else if (bx < 9472) {                // prefix copy: out[b, t<CS] = x
        int i4 = (bx - 5376) * 256 + tid;
        int row = i4 >> 8, col = i4 & 255;
        int b = row >> 11, t = row & 2047;
        size_t g = ((size_t)(b * TT + t) << 8) + col;
        ((float4*)out)[g] = ((const float4*)x)[g];
    } else {                               // rms_norm(x) -> fp16
        const int row = bx - 9472;
        const float4* xr = (const float4*)x + (size_t)row * (DD / 4);
        float4 v = xr[tid];
        float ss = v.x * v.x + v.y * v.y + v.z * v.z + v.w * v.w;
        #pragma unroll
        for (int o = 16; o; o >>= 1) ss += __shfl_xor_sync(0xffffffffu, ss, o);
        if ((tid & 31) == 0) red[tid >> 5] = ss;
        __syncthreads();
        float tot = red[0] + red[1] + red[2] + red[3] + red[4] + red[5] + red[6] + red[7];
        float s = rsqrtf(tot * (1.0f / DD) + 1e-6f);
        size_t base = (size_t)row * (DD / 2) + 2 * tid;
        ((__half2*)xnf)[base]     = __floats2half2_rn(v.x * s, v.y * s);
        ((__half2*)xnf)[base + 1] = __floats2half2_rn(v.z * s, v.w * s);
    }
}

// ============================================================
// RMSNorm fp32 -> fp16 (x_new)
// ============================================================
__global__ __launch_bounds__(256) void rms_k(const float* __restrict__ x,
                                             __half* __restrict__ y)
{
    const int row = blockIdx.x;
    const float4* xr = (const float4*)x + (size_t)row * (DD / 4);
    float4 v = xr[threadIdx.x];
    float ss = v.x * v.x + v.y * v.y + v.z * v.z + v.w * v.w;
    #pragma unroll
    for (int o = 16; o; o >>= 1) ss += __shfl_xor_sync(0xffffffffu, ss, o);
    __shared__ float red[8];
    if ((threadIdx.x & 31) == 0) red[threadIdx.x >> 5] = ss;
    __syncthreads();
    float tot = red[0] + red[1] + red[2] + red[3] + red[4] + red[5] + red[6] + red[7];
    float s = rsqrtf(tot * (1.0f / DD) + 1e-6f);
    size_t base = (size_t)row * (DD / 2) + 2 * threadIdx.x;
    ((__half2*)y)[base]     = __floats2half2_rn(v.x * s, v.y * s);
    ((__half2*)y)[base + 1] = __floats2half2_rn(v.z * s, v.w * s);
}

// ============================================================
// fp16 HMMA GEMM: C[M,N] = A[M,K] * W[N,K]^T, tile 128x128, Kchunk 64.
// FACC: fp16 accumulators (2x mma rate; QKV/Wo only).
// kvsplit: blockIdx.y >= kvsplit uses Wl/HM2/epi5 (merged K+V launch).
// epi: 1 softcap+R(gathered)->fp32; 2 relu^2->fp16; 3 +R->gathered fp32;
//      4 l2norm*sc->fp16 head-major; 5 fp16 head-major
// ============================================================
template<bool FACC>
__global__ __launch_bounds__(256, 2)
void gemm_tc(const __half* __restrict__ Ah,
             const __half* __restrict__ Wh, const __half* __restrict__ Wl,
             float* __restrict__ C, __half* __restrict__ Ch,
             __half* __restrict__ HM, __half* __restrict__ HM2,
             const float* __restrict__ R,
             int Nglob, int K,
             int asl, int ast, int aso,
             int rsl, int rst, int rso,
             int SEQ, float sc, int epi, int kvsplit)
{
    extern __shared__ char smem[];
    const uint32_t sb = smem_u32(smem);
    const int tid = threadIdx.x;
    const int wid = tid >> 5;
    const int lane = tid & 31;
    const int bm = blockIdx.x * 128;
    const int nchunks = K >> 6;
    const uint32_t SS = 32768u;

    const __half* Wuse = Wh;
    __half* HMuse = HM;
    int epiu = epi;
    int bn = blockIdx.y * 128;
    if (kvsplit && (int)blockIdx.y >= kvsplit) {
        Wuse = Wl; HMuse = HM2; epiu = 5;
        bn = (blockIdx.y - kvsplit) * 128;
    }

    auto load_chunk = [&](int p, int c) {
        const int kc = c << 6;
        uint32_t bufb = sb + 1024 + p * SS;
        #pragma unroll
        for (int i = tid; i < 1024; i += 256) {
            int r = i >> 3, seg = i & 7;
            int row = bm + r;
            size_t ar = (size_t)(row / asl) * ast + aso + (row % asl);
            uint32_t off = (r << 7) + (seg << 4);
            uint32_t sw = off ^ ((off >> 3) & 0x70);
            CP_ASYNC16(bufb + sw, Ah + ar * K + kc + seg * 8);
        }
        #pragma unroll
        for (int i = tid; i < 1024; i += 256) {
            int r = i >> 3, seg = i & 7;
            uint32_t off = (r << 7) + (seg << 4);
            uint32_t sw = off ^ ((off >> 3) & 0x70);
            CP_ASYNC16(bufb + 16384 + sw, Wuse + (size_t)(bn + r) * K + kc + seg * 8);
        }
        CP_COMMIT();
    };

    const int warp_m = wid >> 1;
    const int warp_n = wid & 1;

    float acc[2][8][4];
    uint32_t acch[2][8][2];
    #pragma unroll
    for (int mf = 0; mf < 2; mf++)
        #pragma unroll
        for (int nf = 0; nf < 8; nf++) {
            if (FACC) { acch[mf][nf][0] = 0u; acch[mf][nf][1] = 0u; }
            else {
                #pragma unroll
                for (int j = 0; j < 4; j++) acc[mf][nf][j] = 0.f;
            }
        }

    load_chunk(0, 0);

    const int a_row = warp_m * 32 + (lane & 15);
    const uint32_t a_koff = (lane >> 4) << 4;
    const int b_row = warp_n * 64 + ((lane >> 4) << 3) + (lane & 7);
    const uint32_t b_koff = ((lane >> 3) & 1) << 4;

    for (int c = 0; c < nchunks; c++) {
        const int p = c & 1;
        if (c + 1 < nchunks) { load_chunk(1 - p, c + 1); CP_WAIT(1); }
        else                 { CP_WAIT(0); }
        __syncthreads();

        const uint32_t bA = sb + 1024 + p * SS;
        const uint32_t bW = bA + 16384;

        #pragma unroll
        for (int ks = 0; ks < 4; ks++) {
            const uint32_t kb = ks * 32;
            uint32_t ah[2][4];
            #pragma unroll
            for (int mf = 0; mf < 2; mf++) {
                uint32_t off = ((uint32_t)(a_row + mf * 16) << 7) + kb + a_koff;
                off ^= (off >> 3) & 0x70;
                ldsm4(ah[mf][0], ah[mf][1], ah[mf][2], ah[mf][3], bA + off);
            }
            #pragma unroll
            for (int nf2 = 0; nf2 < 4; nf2++) {
                uint32_t off = ((uint32_t)(b_row + nf2 * 16) << 7) + kb + b_koff;
                off ^= (off >> 3) & 0x70;
                uint32_t w0, w1, w2, w3;
                ldsm4(w0, w1, w2, w3, bW + off);
                uint32_t bb0[2] = {w0, w1}, bb1[2] = {w2, w3};
                if (FACC) {
                    mma_f16h(acch[0][2*nf2],   ah[0], bb0);
                    mma_f16h(acch[0][2*nf2+1], ah[0], bb1);
                    mma_f16h(acch[1][2*nf2],   ah[1], bb0);
                    mma_f16h(acch[1][2*nf2+1], ah[1], bb1);
                } else {
                    mma_f16(acc[0][2*nf2],   ah[0], bb0);
                    mma_f16(acc[0][2*nf2+1], ah[0], bb1);
                    mma_f16(acc[1][2*nf2],   ah[1], bb0);
                    mma_f16(acc[1][2*nf2+1], ah[1], bb1);
                }
            }
        }
        __syncthreads();
    }

    if (FACC) {
        #pragma unroll
        for (int mf = 0; mf < 2; mf++)
            #pragma unroll
            for (int nf = 0; nf < 8; nf++) {
                float2 lo = __half22float2(u2h(acch[mf][nf][0]));
                float2 hi = __half22float2(u2h(acch[mf][nf][1]));
                acc[mf][nf][0] = lo.x; acc[mf][nf][1] = lo.y;
                acc[mf][nf][2] = hi.x; acc[mf][nf][3] = hi.y;
            }
    }

    // ---- epilogue ----
    const int rq = lane >> 2, cq = (lane & 3) << 1;
    if (epiu >= 4) {
        const int headw = (bn + warp_n * 64) >> 6;
        const int heads = Nglob >> 6;
        #pragma unroll
        for (int mf = 0; mf < 2; mf++) {
            #pragma unroll
            for (int h2 = 0; h2 < 2; h2++) {
                const int rowg = bm + warp_m * 32 + mf * 16 + rq + h2 * 8;
                float s = 1.0f;
                if (epiu == 4) {
                    float ss = 0.f;
                    #pragma unroll
                    for (int nf = 0; nf < 8; nf++) {
                        float x0 = acc[mf][nf][2*h2], x1 = acc[mf][nf][2*h2+1];
                        ss += x0 * x0 + x1 * x1;
                    }
                    ss += __shfl_xor_sync(0xffffffffu, ss, 1);
                    ss += __shfl_xor_sync(0xffffffffu, ss, 2);
                    s = sc / fmaxf(sqrtf(ss), 1e-12f);
                }
                int b = rowg / SEQ, t = rowg - b * SEQ;
                __half* dst = HMuse + (((size_t)(b * heads + headw)) * SEQ + t) * 64;
                #pragma unroll
                for (int nf = 0; nf < 8; nf++) {
                    float x0 = acc[mf][nf][2*h2] * s, x1 = acc[mf][nf][2*h2+1] * s;
                    *(__half2*)(dst + nf * 8 + cq) = __floats2half2_rn(x0, x1);
                }
            }
        }
    } else {
        #pragma unroll
        for (int mf = 0; mf < 2; mf++) {
            #pragma unroll
            for (int h2 = 0; h2 < 2; h2++) {
                const int rowg = bm + warp_m * 32 + mf * 16 + rq + h2 * 8;
                #pragma unroll
                for (int nf = 0; nf < 8; nf++) {
                    float x0 = acc[mf][nf][2*h2], x1 = acc[mf][nf][2*h2+1];
                    const int colg = bn + warp_n * 64 + nf * 8 + cq;
                    if (epiu == 1) {
                        size_t rr = (size_t)(rowg / rsl) * rst + rso + (rowg % rsl);
                        const float* rp = R + rr * Nglob + colg;
                        float2 o;
                        o.x = rp[0] + 15.0f * tanhfast(x0 * (1.0f/15.0f));
                        o.y = rp[1] + 15.0f * tanhfast(x1 * (1.0f/15.0f));
                        *(float2*)(C + (size_t)rowg * Nglob + colg) = o;
                    } else if (epiu == 2) {
                        float a = fmaxf(x0, 0.f); a *= a;
                        float b = fmaxf(x1, 0.f); b *= b;
                        *(__half2*)(Ch + (size_t)rowg * Nglob + colg) = __floats2half2_rn(a, b);
                    } else { // epiu == 3
                        const float* rp = R + (size_t)rowg * Nglob + colg;
                        size_t cr = (size_t)(rowg / rsl) * rst + rso + (rowg % rsl);
                        *(float2*)(C + cr * Nglob + colg) =
                            make_float2(rp[0] + x0, rp[1] + x1);
                    }
                }
            }
        }
    }
}

// ============================================================
// Flash attention, 2 heads per CTA (shared kv-head), 256 thr / 8 warps.
// warps 0-3 -> head h0, warps 4-7 -> head h1; each warp 16 q-rows.
// S via fp16-acc mma; P = cubic poly exp on half2 (|s|<=0.125);
// zero-mask after exp on the diagonal tile. PV f32-acc mma.
// smem: Q 2x8KB @0; stage p: K @16384+p*16384, V @+8192. Total 49152.
// ============================================================
__global__ __launch_bounds__(256) void attn_mma(
    const __half* __restrict__ qbf,
    const __half* __restrict__ kbf,
    const __half* __restrict__ vbf,
    __half* __restrict__ o)
{
    extern __shared__ char sm[];
    const uint32_t sb = smem_u32(sm);
    const int tid = threadIdx.x;
    const int w = tid >> 5, l = tid & 31;
    const int wp = w >> 2;            // head within pair
    const int wr = w & 3;             // 16-row group
    const int qt = (int)gridDim.x - 1 - (int)blockIdx.x;   // longest first
    const int y = blockIdx.y;
    const int b = y >> 3, hp = y & 7;
    const int head = hp * 2 + wp;
    const int kvh = hp >> 1;
    const int q0 = qt * 64;

    const __half* kg = kbf + ((size_t)(b * KVH + kvh) * TT) * 64;
    const __half* vg = vbf + ((size_t)(b * KVH + kvh) * TT) * 64;

    // Q load: two head tiles
    for (int i = tid; i < 1024; i += 256) {
        int hpi = i >> 9;
        int rem = i & 511;
        int r = rem >> 3, seg = rem & 7;
        const __half* src = qbf + (((size_t)(b * 16 + hp * 2 + hpi)) * NU + q0 + r) * 64 + seg * 8;
        uint32_t off = (r << 7) + (seg << 4);
        uint32_t swo = off ^ ((off >> 3) & 0x70);
        CP_ASYNC16(sb + hpi * 8192 + swo, src);
    }
    const int n_kt = (CS >> 6) + qt + 1;
    auto load_kv = [&](int p, int c) {
        uint32_t base = sb + 16384 + p * 16384;
        const __half* ks = kg + (size_t)(c << 6) * 64;
        const __half* vs = vg + (size_t)(c << 6) * 64;
        for (int i = tid; i < 1024; i += 256) {
            int half = i >> 9;
            int rem = i & 511;
            int r = rem >> 3, seg = rem & 7;
            uint32_t off = (r << 7) + (seg << 4);
            uint32_t swo = off ^ ((off >> 3) & 0x70);
            const __half* src = (half ? vs : ks) + r * 64 + seg * 8;
            CP_ASYNC16(base + half * 8192 + swo, src);
        }
        CP_COMMIT();
    };
    load_kv(0, 0);

    float o_acc[8][4];
    #pragma unroll
    for (int j = 0; j < 8; j++)
        #pragma unroll
        for (int i = 0; i < 4; i++) o_acc[j][i] = 0.f;
    float rsum0 = 0.f, rsum1 = 0.f;

    const int lrow = l & 15;
    const int lhi = l >> 4;
    const int cq = (l & 3) << 1;
    const int qpos = CS + q0 + wr * 16 + (l >> 2);
    const uint32_t qbase = sb + wp * 8192;

    const __half2 C6 = __float2half2_rn(0.16666667f);
    const __half2 C5 = __float2half2_rn(0.5f);
    const __half2 C1 = __float2half2_rn(1.0f);

    for (int c = 0; c < n_kt; c++) {
        const int p = c & 1;
        if (c + 1 < n_kt) { load_kv(1 - p, c + 1); CP_WAIT(1); }
        else              { CP_WAIT(0); }
        __syncthreads();
        const uint32_t kbase = sb + 16384 + p * 16384;
        const uint32_t vbase = kbase + 8192;

        // ---- S = Q K^T (fp16 accumulators, 2x rate) ----
        uint32_t sh[8][2];
        #pragma unroll
        for (int j = 0; j < 8; j++) { sh[j][0] = 0u; sh[j][1] = 0u; }
        #pragma unroll
        for (int ks = 0; ks < 4; ks++) {
            uint32_t a[4];
            {
                uint32_t off = ((uint32_t)(wr * 16 + lrow) << 7) + ks * 32 + (lhi << 4);
                off ^= (off >> 3) & 0x70;
                ldsm4(a[0], a[1], a[2], a[3], qbase + off);
            }
            #pragma unroll
            for (int j = 0; j < 8; j += 2) {
                uint32_t off = ((uint32_t)((j + lhi) * 8 + (l & 7)) << 7)
                             + ks * 32 + (((l >> 3) & 1) << 4);
                off ^= (off >> 3) & 0x70;
                uint32_t b0, b1, b2, b3;
                ldsm4(b0, b1, b2, b3, kbase + off);
                uint32_t bb0[2] = {b0, b1}, bb1[2] = {b2, b3};
                mma_f16h(sh[j],     a, bb0);
                mma_f16h(sh[j + 1], a, bb1);
            }
        }

        // ---- P = exp(S) via cubic poly on half2 ----
        #pragma unroll
        for (int j = 0; j < 8; j++) {
            #pragma unroll
            for (int r = 0; r < 2; r++) {
                __half2 yv = u2h(sh[j][r]);
                __half2 t = __hfma2(yv, C6, C5);
                t = __hfma2(yv, t, C1);
                sh[j][r] = h2u(__hfma2(yv, t, C1));
            }
        }

        // ---- causal zero-mask on the diagonal tile ----
        if (c == n_kt - 1) {
            const int k0c = c * 64;
            #pragma unroll
            for (int j = 0; j < 8; j++) {
                int col0 = k0c + j * 8 + cq;
                float2 f0 = __half22float2(u2h(sh[j][0]));
                if (col0     > qpos) f0.x = 0.f;
                if (col0 + 1 > qpos) f0.y = 0.f;
                sh[j][0] = packh2(f0.x, f0.y);
                float2 f1 = __half22float2(u2h(sh[j][1]));
                if (col0     > qpos + 8) f1.x = 0.f;
                if (col0 + 1 > qpos + 8) f1.y = 0.f;
                sh[j][1] = packh2(f1.x, f1.y);
            }
        }

        // ---- row sums (half2 tree -> f32) ----
        {
            __half2 t0 = u2h(sh[0][0]), t1 = u2h(sh[0][1]);
            #pragma unroll
            for (int j = 1; j < 8; j++) {
                t0 = __hadd2(t0, u2h(sh[j][0]));
                t1 = __hadd2(t1, u2h(sh[j][1]));
            }
            float2 f0 = __half22float2(t0);
            float2 f1 = __half22float2(t1);
            rsum0 += f0.x + f0.y;
            rsum1 += f1.x + f1.y;
        }

        // ---- O += P V (f32 accumulators) ----
        #pragma unroll
        for (int ks = 0; ks < 4; ks++) {
            uint32_t a[4] = {sh[2*ks][0], sh[2*ks][1], sh[2*ks+1][0], sh[2*ks+1][1]};
            #pragma unroll
            for (int j = 0; j < 8; j += 2) {
                uint32_t off = ((uint32_t)(ks * 16 + lrow) << 7) + ((j + lhi) << 4);
                off ^= (off >> 3) & 0x70;
                uint32_t b0, b1, b2, b3;
                ldsm4t(b0, b1, b2, b3, vbase + off);
                uint32_t bb0[2] = {b0, b1}, bb1[2] = {b2, b3};
                mma_f16(o_acc[j],     a, bb0);
                mma_f16(o_acc[j + 1], a, bb1);
            }
        }
        __syncthreads();
    }

    rsum0 += __shfl_xor_sync(0xffffffffu, rsum0, 1);
    rsum0 += __shfl_xor_sync(0xffffffffu, rsum0, 2);
    rsum1 += __shfl_xor_sync(0xffffffffu, rsum1, 1);
    rsum1 += __shfl_xor_sync(0xffffffffu, rsum1, 2);
    const float inv0 = 1.0f / rsum0, inv1 = 1.0f / rsum1;

    const size_t gr0 = (size_t)(b * NU + q0 + wr * 16 + (l >> 2));
    const size_t gr1 = gr0 + 8;
    const int colb = head * 64 + cq;
    #pragma unroll
    for (int j = 0; j < 8; j++) {
        const int col = colb + j * 8;
        *(__half2*)(o + gr0 * DD + col) =
            __floats2half2_rn(o_acc[j][0] * inv0, o_acc[j][1] * inv0);
        *(__half2*)(o + gr1 * DD + col) =
            __floats2half2_rn(o_acc[j][2] * inv1, o_acc[j][3] * inv1);
    }
}

// ============================================================
extern "C" void kernel_launch(void* const* d_in, const int* in_sizes, int n_in,
                              void* d_out, int out_size)
{
    const float* x     = (const float*)d_in[0];
    const float* Wq    = (const float*)d_in[1];
    const float* Wk    = (const float*)d_in[2];
    const float* Wv    = (const float*)d_in[3];
    const float* Wo    = (const float*)d_in[4];
    const float* Wfc   = (const float*)d_in[5];
    const float* Wproj = (const float*)d_in[6];
    float* out = (float*)d_out;

    __half *xnf, *qbf, *kbf, *vbf, *af, *x2f, *hf;
    __half *wq, *wk, *wv, *wo, *wf, *wp;
    float *xnew;
    cudaGetSymbolAddress((void**)&xnf, g_xnf);
    cudaGetSymbolAddress((void**)&qbf, g_qbf);
    cudaGetSymbolAddress((void**)&kbf, g_kbf);
    cudaGetSymbolAddress((void**)&vbf, g_vbf);
    cudaGetSymbolAddress((void**)&af,  g_af);
    cudaGetSymbolAddress((void**)&xnew, g_xnew);
    cudaGetSymbolAddress((void**)&x2f, g_x2f);
    cudaGetSymbolAddress((void**)&hf,  g_hf);
    cudaGetSymbolAddress((void**)&wq,  g_wq);
    cudaGetSymbolAddress((void**)&wk,  g_wk);
    cudaGetSymbolAddress((void**)&wv,  g_wv);
    cudaGetSymbolAddress((void**)&wo,  g_wo);
    cudaGetSymbolAddress((void**)&wf,  g_wf);
    cudaGetSymbolAddress((void**)&wp,  g_wp);

    const int SM1 = 1024 + 2 * 32768;   // 66560
    cudaFuncSetAttribute(gemm_tc<true>,  cudaFuncAttributeMaxDynamicSharedMemorySize, SM1);
    cudaFuncSetAttribute(gemm_tc<false>, cudaFuncAttributeMaxDynamicSharedMemorySize, SM1);
    cudaFuncSetAttribute(attn_mma, cudaFuncAttributeMaxDynamicSharedMemorySize, 49152);

    // 1. fused prologue
    prep_k<<<17792, 256>>>(x, Wq, Wk, Wv, Wo, Wfc, Wproj,
                           out, xnf, wq, wk, wv, wo, wf, wp);

    // 2. K+V projection (merged; y<2 -> K with l2norm, y>=2 -> V), fp16 acc
    gemm_tc<true><<<dim3(MX / 128, 4), 256, SM1>>>(xnf, wk, wv,
        nullptr, nullptr, kbf, vbf, nullptr,
        KVD, DD, MX, MX, 0, 0, 0, 0, TT, 1.0f, 4, 2);
    // 3. Q projection (l2norm * 0.125), fp16 acc
    gemm_tc<true><<<dim3(MQ / 128, DD / 128), 256, SM1>>>(xnf, wq, nullptr,
        nullptr, nullptr, qbf, nullptr, nullptr,
        DD, DD, NU, TT, CS, 0, 0, 0, NU, 0.125f, 4, 0);

    // 4. flash attention (2 heads per CTA)
    attn_mma<<<dim3(NU / 64, BB * 8), 256, 49152>>>(qbf, kbf, vbf, af);

    // 5. x_new = x_upd + softcap(attn @ Wo^T), fp16 acc
    gemm_tc<true><<<dim3(MQ / 128, DD / 128), 256, SM1>>>(af, wo, nullptr,
        xnew, nullptr, nullptr, nullptr, x,
        DD, DD, MQ, MQ, 0, NU, TT, CS, 0, 0.f, 1, 0);

    // 6. FFN (f32 acc for accuracy)
    rms_k<<<MQ, 256>>>(xnew, x2f);
    gemm_tc<false><<<dim3(MQ / 128, DFF / 128), 256, SM1>>>(x2f, wf, nullptr,
        nullptr, hf, nullptr, nullptr, nullptr,
        DFF, DD, MQ, MQ, 0, 0, 0, 0, 0, 0.f, 2, 0);
    gemm_tc<false><<<dim3(MQ / 128, DD / 128), 256, SM1>>>(hf, wp, nullptr,
        out, nullptr, nullptr, nullptr, xnew,
        DD, DFF, MQ, MQ, 0, NU, TT, CS, 0, 0.f, 3, 0);
}